// round 1
// baseline (speedup 1.0000x reference)
#include <cuda_runtime.h>
#include <math.h>

#define NTOK 1024
#define BATCH 2
#define HEADS 8
#define DH 64
#define BHN (BATCH*HEADS)   /* 16 */
#define DIMM 512
#define MROWS (BATCH*NTOK)  /* 2048 */
#define SCALE 0.125f

// ---- scratch (device globals; allocation-free per harness rules) ----
__device__ float g_qu[BHN*NTOK*DH];
__device__ float g_ku[BHN*NTOK*DH];
__device__ float g_vu[BHN*NTOK*DH];
__device__ float g_qc[BHN*NTOK*DH];
__device__ float g_kc[BHN*NTOK*DH];
__device__ float g_vc[BHN*NTOK*DH];
__device__ float g_t1[(size_t)BHN*NTOK*NTOK];   // term1 (lower blocks only)
__device__ float g_sg[(size_t)BHN*NTOK*NTOK];   // sig   (upper blocks only)
__device__ float g_su[(size_t)BHN*NTOK*NTOK];   // S_u -> scores -> probs (in place)
__device__ float g_oh[BHN*NTOK*DH];             // attn @ v_c, per-head

// =====================================================================
// K1: 6 input projections. X[2048,512] @ W[512,512] -> [bh][tok][d]
// =====================================================================
__global__ __launch_bounds__(256) void k_proj(
    const float* __restrict__ X,
    const float* __restrict__ w0, const float* __restrict__ w1,
    const float* __restrict__ w2, const float* __restrict__ w3,
    const float* __restrict__ w4, const float* __restrict__ w5)
{
    const float* W; float* O;
    switch (blockIdx.z) {
        case 0: W = w0; O = g_qu; break;
        case 1: W = w1; O = g_ku; break;
        case 2: W = w2; O = g_vu; break;
        case 3: W = w3; O = g_qc; break;
        case 4: W = w4; O = g_kc; break;
        default: W = w5; O = g_vc; break;
    }
    __shared__ float As[16][65];
    __shared__ float Bs[16][65];
    int tx = threadIdx.x, ty = threadIdx.y;
    int tid = ty*16 + tx;
    int m0 = blockIdx.y*64, n0 = blockIdx.x*64;
    float acc[4][4] = {};
    for (int k0 = 0; k0 < DIMM; k0 += 16) {
        #pragma unroll
        for (int l = 0; l < 4; l++) {
            int e = tid + l*256;
            int r = e >> 4, c = e & 15;
            As[c][r] = X[(m0+r)*DIMM + k0 + c];
        }
        #pragma unroll
        for (int l = 0; l < 4; l++) {
            int e = tid + l*256;
            int r = e >> 6, c = e & 63;
            Bs[r][c] = W[(k0+r)*DIMM + n0 + c];
        }
        __syncthreads();
        #pragma unroll
        for (int kk = 0; kk < 16; kk++) {
            float a[4], b[4];
            #pragma unroll
            for (int u = 0; u < 4; u++) a[u] = As[kk][ty*4+u];
            #pragma unroll
            for (int u = 0; u < 4; u++) b[u] = Bs[kk][tx*4+u];
            #pragma unroll
            for (int i = 0; i < 4; i++)
                #pragma unroll
                for (int j = 0; j < 4; j++) acc[i][j] += a[i]*b[j];
        }
        __syncthreads();
    }
    #pragma unroll
    for (int i = 0; i < 4; i++) {
        int m = m0 + ty*4 + i;
        int b = m >> 10, tok = m & 1023;
        #pragma unroll
        for (int j = 0; j < 4; j++) {
            int nn = n0 + tx*4 + j;
            int h = nn >> 6, dd = nn & 63;
            O[((b*HEADS + h)*NTOK + tok)*DH + dd] = acc[i][j];
        }
    }
}

// =====================================================================
// K2: term1 (which=0, lower blocks) / sig (which=1, upper blocks)
// NT GEMM [1024 x 1024 x 64], masked + activated epilogue
// =====================================================================
__global__ __launch_bounds__(256) void k_t1sig()
{
    int which = blockIdx.z >> 4;
    int bh    = blockIdx.z & 15;
    int bx = blockIdx.x, by = blockIdx.y;
    if (which == 0) { if (bx > by) return; }   // term1: j-tile <= i-tile
    else            { if (bx < by) return; }   // sig:   j-tile >= i-tile
    const float* A  = (which == 0 ? g_qc : g_qu) + (size_t)bh*NTOK*DH;
    const float* Bm = (which == 0 ? g_vu : g_ku) + (size_t)bh*NTOK*DH;
    float* O = (which == 0 ? g_t1 : g_sg) + (size_t)bh*NTOK*NTOK;
    __shared__ float As[16][65];
    __shared__ float Bs[16][65];
    int tx = threadIdx.x, ty = threadIdx.y;
    int tid = ty*16 + tx;
    int i0 = by*64, j0 = bx*64;
    float acc[4][4] = {};
    for (int k0 = 0; k0 < DH; k0 += 16) {
        #pragma unroll
        for (int l = 0; l < 4; l++) {
            int e = tid + l*256;
            int r = e >> 4, c = e & 15;
            As[c][r] = A [(i0+r)*DH + k0 + c];
            Bs[c][r] = Bm[(j0+r)*DH + k0 + c];
        }
        __syncthreads();
        #pragma unroll
        for (int kk = 0; kk < 16; kk++) {
            float a[4], b[4];
            #pragma unroll
            for (int u = 0; u < 4; u++) a[u] = As[kk][ty*4+u];
            #pragma unroll
            for (int u = 0; u < 4; u++) b[u] = Bs[kk][tx*4+u];
            #pragma unroll
            for (int i = 0; i < 4; i++)
                #pragma unroll
                for (int j = 0; j < 4; j++) acc[i][j] += a[i]*b[j];
        }
        __syncthreads();
    }
    #pragma unroll
    for (int u = 0; u < 4; u++) {
        int i = i0 + ty*4 + u;
        #pragma unroll
        for (int v = 0; v < 4; v++) {
            int j = j0 + tx*4 + v;
            float s = acc[u][v]*SCALE;
            float o;
            if (which == 0) o = (j <= i) ? s : 0.f;
            else            o = (j >  i) ? 1.f/(1.f + __expf(-s)) : 0.f;
            O[(size_t)i*NTOK + j] = o;
        }
    }
}

// =====================================================================
// K3: S_u[i,k] = sum_j term1[i,j]*sig[k,j]; block-triangular:
// only bk<=bi blocks, j-tiles restricted to [bk*64, (bi+1)*64)
// =====================================================================
__global__ __launch_bounds__(256) void k_su()
{
    int bx = blockIdx.x, by = blockIdx.y, bh = blockIdx.z;
    if (bx > by) return;
    const float* A  = g_t1 + (size_t)bh*NTOK*NTOK;   // rows i
    const float* Bm = g_sg + (size_t)bh*NTOK*NTOK;   // rows k
    float* O = g_su + (size_t)bh*NTOK*NTOK;
    __shared__ float As[16][65];
    __shared__ float Bs[16][65];
    int tx = threadIdx.x, ty = threadIdx.y;
    int tid = ty*16 + tx;
    int i0 = by*64, kr0 = bx*64;
    float acc[4][4] = {};
    int jbeg = bx*64, jend = (by+1)*64;
    for (int j0 = jbeg; j0 < jend; j0 += 16) {
        #pragma unroll
        for (int l = 0; l < 4; l++) {
            int e = tid + l*256;
            int r = e >> 4, c = e & 15;
            As[c][r] = A [(size_t)(i0 +r)*NTOK + j0 + c];
            Bs[c][r] = Bm[(size_t)(kr0+r)*NTOK + j0 + c];
        }
        __syncthreads();
        #pragma unroll
        for (int kk = 0; kk < 16; kk++) {
            float a[4], b[4];
            #pragma unroll
            for (int u = 0; u < 4; u++) a[u] = As[kk][ty*4+u];
            #pragma unroll
            for (int u = 0; u < 4; u++) b[u] = Bs[kk][tx*4+u];
            #pragma unroll
            for (int i = 0; i < 4; i++)
                #pragma unroll
                for (int j = 0; j < 4; j++) acc[i][j] += a[i]*b[j];
        }
        __syncthreads();
    }
    #pragma unroll
    for (int u = 0; u < 4; u++) {
        int i = i0 + ty*4 + u;
        #pragma unroll
        for (int v = 0; v < 4; v++) {
            int k = kr0 + tx*4 + v;
            O[(size_t)i*NTOK + k] = acc[u][v];
        }
    }
}

// =====================================================================
// K4a: scores = S_c - silu(S_u), in place over g_su (lower blocks)
// S_c computed on the fly: q_c . k_c (NT, K=64)
// =====================================================================
__global__ __launch_bounds__(256) void k_scores()
{
    int bx = blockIdx.x, by = blockIdx.y, bh = blockIdx.z;
    if (bx > by) return;
    const float* A  = g_qc + (size_t)bh*NTOK*DH;
    const float* Bm = g_kc + (size_t)bh*NTOK*DH;
    float* S = g_su + (size_t)bh*NTOK*NTOK;
    __shared__ float As[16][65];
    __shared__ float Bs[16][65];
    int tx = threadIdx.x, ty = threadIdx.y;
    int tid = ty*16 + tx;
    int i0 = by*64, k0r = bx*64;
    float acc[4][4] = {};
    for (int k0 = 0; k0 < DH; k0 += 16) {
        #pragma unroll
        for (int l = 0; l < 4; l++) {
            int e = tid + l*256;
            int r = e >> 4, c = e & 15;
            As[c][r] = A [(i0 +r)*DH + k0 + c];
            Bs[c][r] = Bm[(k0r+r)*DH + k0 + c];
        }
        __syncthreads();
        #pragma unroll
        for (int kk = 0; kk < 16; kk++) {
            float a[4], b[4];
            #pragma unroll
            for (int u = 0; u < 4; u++) a[u] = As[kk][ty*4+u];
            #pragma unroll
            for (int u = 0; u < 4; u++) b[u] = Bs[kk][tx*4+u];
            #pragma unroll
            for (int i = 0; i < 4; i++)
                #pragma unroll
                for (int j = 0; j < 4; j++) acc[i][j] += a[i]*b[j];
        }
        __syncthreads();
    }
    #pragma unroll
    for (int u = 0; u < 4; u++) {
        int i = i0 + ty*4 + u;
        #pragma unroll
        for (int v = 0; v < 4; v++) {
            int k = k0r + tx*4 + v;
            size_t idx = (size_t)i*NTOK + k;
            float sc = acc[u][v]*SCALE;
            float su = S[idx];
            float sil = su / (1.f + __expf(-su));
            S[idx] = (k <= i) ? (sc - sil) : -1e30f;
        }
    }
}

// =====================================================================
// K4b: row softmax over k<=i; writes probs up to end of diagonal tile
// (zeros for i<k<tile_end), in place.
// =====================================================================
__global__ __launch_bounds__(256) void k_softmax()
{
    int i  = blockIdx.x;
    int bh = blockIdx.y;
    float* S = g_su + (size_t)bh*NTOK*NTOK + (size_t)i*NTOK;
    int L = i + 1;
    int wlen = ((i >> 6) + 1) << 6;
    int tid = threadIdx.x;
    __shared__ float red[256];
    float x[4];
    float mx = -1e30f;
    #pragma unroll
    for (int l = 0; l < 4; l++) {
        int k = tid + l*256;
        x[l] = (k < L) ? S[k] : -1e30f;
        mx = fmaxf(mx, x[l]);
    }
    red[tid] = mx; __syncthreads();
    for (int s = 128; s > 0; s >>= 1) {
        if (tid < s) red[tid] = fmaxf(red[tid], red[tid+s]);
        __syncthreads();
    }
    mx = red[0]; __syncthreads();
    float sum = 0.f;
    #pragma unroll
    for (int l = 0; l < 4; l++) {
        int k = tid + l*256;
        x[l] = (k < L) ? __expf(x[l] - mx) : 0.f;
        sum += x[l];
    }
    red[tid] = sum; __syncthreads();
    for (int s = 128; s > 0; s >>= 1) {
        if (tid < s) red[tid] += red[tid+s];
        __syncthreads();
    }
    float inv = 1.f / red[0];
    #pragma unroll
    for (int l = 0; l < 4; l++) {
        int k = tid + l*256;
        if (k < wlen) S[k] = x[l]*inv;
    }
}

// =====================================================================
// K5: out_heads = P @ v_c  (NN, M=1024, N=64, K restricted to <= diag tile)
// =====================================================================
__global__ __launch_bounds__(256) void k_av()
{
    int by = blockIdx.y, bh = blockIdx.z;
    const float* P = g_su + (size_t)bh*NTOK*NTOK;
    const float* V = g_vc + (size_t)bh*NTOK*DH;
    float* O = g_oh + (size_t)bh*NTOK*DH;
    __shared__ float As[16][65];
    __shared__ float Bs[16][65];
    int tx = threadIdx.x, ty = threadIdx.y;
    int tid = ty*16 + tx;
    int i0 = by*64;
    float acc[4][4] = {};
    int kend = (by+1)*64;
    for (int k0 = 0; k0 < kend; k0 += 16) {
        #pragma unroll
        for (int l = 0; l < 4; l++) {
            int e = tid + l*256;
            int r = e >> 4, c = e & 15;
            As[c][r] = P[(size_t)(i0+r)*NTOK + k0 + c];
        }
        #pragma unroll
        for (int l = 0; l < 4; l++) {
            int e = tid + l*256;
            int r = e >> 6, c = e & 63;
            Bs[r][c] = V[(k0+r)*DH + c];
        }
        __syncthreads();
        #pragma unroll
        for (int kk = 0; kk < 16; kk++) {
            float a[4], b[4];
            #pragma unroll
            for (int u = 0; u < 4; u++) a[u] = As[kk][ty*4+u];
            #pragma unroll
            for (int u = 0; u < 4; u++) b[u] = Bs[kk][tx*4+u];
            #pragma unroll
            for (int i = 0; i < 4; i++)
                #pragma unroll
                for (int j = 0; j < 4; j++) acc[i][j] += a[i]*b[j];
        }
        __syncthreads();
    }
    #pragma unroll
    for (int u = 0; u < 4; u++) {
        int i = i0 + ty*4 + u;
        #pragma unroll
        for (int v = 0; v < 4; v++) {
            int d = tx*4 + v;
            O[i*DH + d] = acc[u][v];
        }
    }
}

// =====================================================================
// K6: output projection. A gathered from g_oh as [2048, 512] @ w_out
// =====================================================================
__global__ __launch_bounds__(256) void k_outproj(
    const float* __restrict__ Wo, float* __restrict__ Out)
{
    __shared__ float As[16][65];
    __shared__ float Bs[16][65];
    int tx = threadIdx.x, ty = threadIdx.y;
    int tid = ty*16 + tx;
    int m0 = blockIdx.y*64, n0 = blockIdx.x*64;
    float acc[4][4] = {};
    for (int k0 = 0; k0 < DIMM; k0 += 16) {
        #pragma unroll
        for (int l = 0; l < 4; l++) {
            int e = tid + l*256;
            int r = e >> 4, c = e & 15;
            int m = m0 + r, k = k0 + c;
            int b = m >> 10, tok = m & 1023;
            int h = k >> 6, dd = k & 63;
            As[c][r] = g_oh[((b*HEADS + h)*NTOK + tok)*DH + dd];
        }
        #pragma unroll
        for (int l = 0; l < 4; l++) {
            int e = tid + l*256;
            int r = e >> 6, c = e & 63;
            Bs[r][c] = Wo[(k0+r)*DIMM + n0 + c];
        }
        __syncthreads();
        #pragma unroll
        for (int kk = 0; kk < 16; kk++) {
            float a[4], b[4];
            #pragma unroll
            for (int u = 0; u < 4; u++) a[u] = As[kk][ty*4+u];
            #pragma unroll
            for (int u = 0; u < 4; u++) b[u] = Bs[kk][tx*4+u];
            #pragma unroll
            for (int i = 0; i < 4; i++)
                #pragma unroll
                for (int j = 0; j < 4; j++) acc[i][j] += a[i]*b[j];
        }
        __syncthreads();
    }
    #pragma unroll
    for (int u = 0; u < 4; u++) {
        int m = m0 + ty*4 + u;
        #pragma unroll
        for (int v = 0; v < 4; v++) {
            int nn = n0 + tx*4 + v;
            Out[m*DIMM + nn] = acc[u][v];
        }
    }
}

extern "C" void kernel_launch(void* const* d_in, const int* in_sizes, int n_in,
                              void* d_out, int out_size)
{
    const float* x   = (const float*)d_in[0];
    const float* wqu = (const float*)d_in[1];
    const float* wku = (const float*)d_in[2];
    const float* wvu = (const float*)d_in[3];
    const float* wqc = (const float*)d_in[4];
    const float* wkc = (const float*)d_in[5];
    const float* wvc = (const float*)d_in[6];
    const float* wout= (const float*)d_in[7];
    float* out = (float*)d_out;

    dim3 t(16,16);
    k_proj   <<<dim3(8, 32, 6),  t>>>(x, wqu, wku, wvu, wqc, wkc, wvc);
    k_t1sig  <<<dim3(16,16,32),  t>>>();
    k_su     <<<dim3(16,16,16),  t>>>();
    k_scores <<<dim3(16,16,16),  t>>>();
    k_softmax<<<dim3(1024,16),   256>>>();
    k_av     <<<dim3(1, 16, 16), t>>>();
    k_outproj<<<dim3(8, 32),     t>>>(wout, out);
}

// round 2
// speedup vs baseline: 1.0494x; 1.0494x over previous
#include <cuda_runtime.h>
#include <math.h>

#define NTOK 1024
#define BATCH 2
#define HEADS 8
#define DH 64
#define BHN (BATCH*HEADS)   /* 16 */
#define DIMM 512
#define SCALE 0.125f

// ---- scratch (device globals; allocation-free per harness rules) ----
__device__ float g_qu[BHN*NTOK*DH];
__device__ float g_ku[BHN*NTOK*DH];
__device__ float g_vu[BHN*NTOK*DH];
__device__ float g_qc[BHN*NTOK*DH];
__device__ float g_kc[BHN*NTOK*DH];
__device__ float g_vc[BHN*NTOK*DH];
__device__ float g_t1[(size_t)BHN*NTOK*NTOK];   // term1 (lower blocks only)
__device__ float g_sg[(size_t)BHN*NTOK*NTOK];   // sig   (upper blocks only)
__device__ float g_su[(size_t)BHN*NTOK*NTOK];   // scores -> probs (in place)
__device__ float g_oh[BHN*NTOK*DH];             // attn @ v_c, per-head

// ---------------------------------------------------------------------
// Shared inner-product core: 128x128 tile, 16x16 threads, 8x8 microtile
// As/Bs are [16][132]: As[k][m], Bs[k][n]
// ---------------------------------------------------------------------
#define MMA_STEP(As, Bs, acc, tx, ty)                                   \
    do {                                                                \
        _Pragma("unroll")                                               \
        for (int kk = 0; kk < 16; kk++) {                               \
            float a[8], b[8];                                           \
            *(float4*)&a[0] = *(const float4*)&As[kk][(ty)*8];          \
            *(float4*)&a[4] = *(const float4*)&As[kk][(ty)*8+4];        \
            *(float4*)&b[0] = *(const float4*)&Bs[kk][(tx)*8];          \
            *(float4*)&b[4] = *(const float4*)&Bs[kk][(tx)*8+4];        \
            _Pragma("unroll")                                           \
            for (int i = 0; i < 8; i++)                                 \
                _Pragma("unroll")                                       \
                for (int j = 0; j < 8; j++)                             \
                    acc[i][j] += a[i]*b[j];                             \
        }                                                               \
    } while (0)

// load a 128-row x 16-col tile of row-major A (ld=lda) transposed into As[k][m]
#define LOAD_T(As, A, row0, k0, lda)                                    \
    do {                                                                \
        _Pragma("unroll")                                               \
        for (int l = 0; l < 2; l++) {                                   \
            int idx = tid + l*256;                                      \
            int r = idx >> 2, c4 = idx & 3;                             \
            float4 v = *(const float4*)&(A)[(size_t)((row0)+r)*(lda) + (k0) + c4*4]; \
            As[c4*4+0][r] = v.x; As[c4*4+1][r] = v.y;                   \
            As[c4*4+2][r] = v.z; As[c4*4+3][r] = v.w;                   \
        }                                                               \
    } while (0)

// load a 16-row x 128-col tile of row-major B (ld=ldb) directly into Bs[k][n]
#define LOAD_N(Bs, B, k0, col0, ldb)                                    \
    do {                                                                \
        _Pragma("unroll")                                               \
        for (int l = 0; l < 2; l++) {                                   \
            int idx = tid + l*256;                                      \
            int r = idx >> 5, c4 = idx & 31;                            \
            *(float4*)&Bs[r][c4*4] =                                    \
                *(const float4*)&(B)[(size_t)((k0)+r)*(ldb) + (col0) + c4*4]; \
        }                                                               \
    } while (0)

// =====================================================================
// K1: 6 input projections. X[2048,512] @ W[512,512] -> [bh][tok][d]
// =====================================================================
__global__ __launch_bounds__(256,2) void k_proj(
    const float* __restrict__ X,
    const float* __restrict__ w0, const float* __restrict__ w1,
    const float* __restrict__ w2, const float* __restrict__ w3,
    const float* __restrict__ w4, const float* __restrict__ w5)
{
    const float* W; float* O;
    switch (blockIdx.z) {
        case 0: W = w0; O = g_qu; break;
        case 1: W = w1; O = g_ku; break;
        case 2: W = w2; O = g_vu; break;
        case 3: W = w3; O = g_qc; break;
        case 4: W = w4; O = g_kc; break;
        default: W = w5; O = g_vc; break;
    }
    __shared__ float As[16][132];
    __shared__ float Bs[16][132];
    int tid = threadIdx.x;
    int tx = tid & 15, ty = tid >> 4;
    int m0 = blockIdx.y*128, n0 = blockIdx.x*128;
    float acc[8][8] = {};
    for (int k0 = 0; k0 < DIMM; k0 += 16) {
        LOAD_T(As, X, m0, k0, DIMM);
        LOAD_N(Bs, W, k0, n0, DIMM);
        __syncthreads();
        MMA_STEP(As, Bs, acc, tx, ty);
        __syncthreads();
    }
    #pragma unroll
    for (int u = 0; u < 8; u++) {
        int m = m0 + ty*8 + u;
        int b = m >> 10, tok = m & 1023;
        #pragma unroll
        for (int v = 0; v < 8; v++) {
            int nn = n0 + tx*8 + v;
            int h = nn >> 6, dd = nn & 63;
            O[((b*HEADS + h)*NTOK + tok)*DH + dd] = acc[u][v];
        }
    }
}

// =====================================================================
// K2: term1 (which=0, lower blocks) / sig (which=1, upper blocks)
// NT GEMM [1024 x 1024 x 64], masked + activated epilogue
// =====================================================================
__global__ __launch_bounds__(256,2) void k_t1sig()
{
    int which = blockIdx.z >> 4;
    int bh    = blockIdx.z & 15;
    int bx = blockIdx.x, by = blockIdx.y;
    if (which == 0) { if (bx > by) return; }   // term1: j-tile <= i-tile
    else            { if (bx < by) return; }   // sig:   j-tile >= i-tile
    const float* A  = (which == 0 ? g_qc : g_qu) + (size_t)bh*NTOK*DH;
    const float* Bm = (which == 0 ? g_vu : g_ku) + (size_t)bh*NTOK*DH;
    float* O = (which == 0 ? g_t1 : g_sg) + (size_t)bh*NTOK*NTOK;
    __shared__ float As[16][132];
    __shared__ float Bs[16][132];
    int tid = threadIdx.x;
    int tx = tid & 15, ty = tid >> 4;
    int i0 = by*128, j0 = bx*128;
    float acc[8][8] = {};
    for (int k0 = 0; k0 < DH; k0 += 16) {
        LOAD_T(As, A,  i0, k0, DH);
        LOAD_T(Bs, Bm, j0, k0, DH);
        __syncthreads();
        MMA_STEP(As, Bs, acc, tx, ty);
        __syncthreads();
    }
    #pragma unroll
    for (int u = 0; u < 8; u++) {
        int i = i0 + ty*8 + u;
        #pragma unroll
        for (int v = 0; v < 8; v++) {
            int j = j0 + tx*8 + v;
            float s = acc[u][v]*SCALE;
            float o;
            if (which == 0) o = (j <= i) ? s : 0.f;
            else            o = (j >  i) ? 1.f/(1.f + __expf(-s)) : 0.f;
            O[(size_t)i*NTOK + j] = o;
        }
    }
}

// =====================================================================
// K3 (fused): S_u = term1 @ sig^T (block-triangular j range), then
// acc = -silu(acc), then acc += SCALE * q_c @ k_c^T, masked write.
// Produces final pre-softmax scores directly into g_su.
// =====================================================================
__global__ __launch_bounds__(256,2) void k_su()
{
    int bx = blockIdx.x, by = blockIdx.y, bh = blockIdx.z;
    if (bx > by) return;
    const float* A  = g_t1 + (size_t)bh*NTOK*NTOK;   // rows i
    const float* Bm = g_sg + (size_t)bh*NTOK*NTOK;   // rows k
    const float* Qc = g_qc + (size_t)bh*NTOK*DH;
    const float* Kc = g_kc + (size_t)bh*NTOK*DH;
    float* S = g_su + (size_t)bh*NTOK*NTOK;
    __shared__ float As[16][132];
    __shared__ float Bs[16][132];
    int tid = threadIdx.x;
    int tx = tid & 15, ty = tid >> 4;
    int i0 = by*128, kx0 = bx*128;
    float acc[8][8] = {};
    // ---- phase 1: S_u over j in [bx*128, (by+1)*128) ----
    int jend = (by+1)*128;
    for (int j0 = bx*128; j0 < jend; j0 += 16) {
        LOAD_T(As, A,  i0,  j0, NTOK);
        LOAD_T(Bs, Bm, kx0, j0, NTOK);
        __syncthreads();
        MMA_STEP(As, Bs, acc, tx, ty);
        __syncthreads();
    }
    // ---- transform: acc = -silu(acc) ----
    #pragma unroll
    for (int u = 0; u < 8; u++)
        #pragma unroll
        for (int v = 0; v < 8; v++) {
            float su = acc[u][v];
            acc[u][v] = -su / (1.f + __expf(-su));
        }
    // ---- phase 2: acc += SCALE * q_c @ k_c^T (SCALE folded into As) ----
    for (int k0 = 0; k0 < DH; k0 += 16) {
        {   // scaled transpose load of q_c
            #pragma unroll
            for (int l = 0; l < 2; l++) {
                int idx = tid + l*256;
                int r = idx >> 2, c4 = idx & 3;
                float4 v = *(const float4*)&Qc[(size_t)(i0+r)*DH + k0 + c4*4];
                As[c4*4+0][r] = v.x*SCALE; As[c4*4+1][r] = v.y*SCALE;
                As[c4*4+2][r] = v.z*SCALE; As[c4*4+3][r] = v.w*SCALE;
            }
        }
        LOAD_T(Bs, Kc, kx0, k0, DH);
        __syncthreads();
        MMA_STEP(As, Bs, acc, tx, ty);
        __syncthreads();
    }
    #pragma unroll
    for (int u = 0; u < 8; u++) {
        int i = i0 + ty*8 + u;
        #pragma unroll
        for (int v = 0; v < 8; v++) {
            int k = kx0 + tx*8 + v;
            S[(size_t)i*NTOK + k] = (k <= i) ? acc[u][v] : -1e30f;
        }
    }
}

// =====================================================================
// K4: row softmax over k<=i; zero-fill to the end of the 128-block
// =====================================================================
__global__ __launch_bounds__(256) void k_softmax()
{
    int i  = blockIdx.x;
    int bh = blockIdx.y;
    float* S = g_su + (size_t)bh*NTOK*NTOK + (size_t)i*NTOK;
    int L = i + 1;
    int wlen = ((i >> 7) + 1) << 7;   // 128-granular for k_av tiles
    int tid = threadIdx.x;
    __shared__ float red[256];
    float x[4];
    float mx = -1e30f;
    #pragma unroll
    for (int l = 0; l < 4; l++) {
        int k = tid + l*256;
        x[l] = (k < L) ? S[k] : -1e30f;
        mx = fmaxf(mx, x[l]);
    }
    red[tid] = mx; __syncthreads();
    for (int s = 128; s > 0; s >>= 1) {
        if (tid < s) red[tid] = fmaxf(red[tid], red[tid+s]);
        __syncthreads();
    }
    mx = red[0]; __syncthreads();
    float sum = 0.f;
    #pragma unroll
    for (int l = 0; l < 4; l++) {
        int k = tid + l*256;
        x[l] = (k < L) ? __expf(x[l] - mx) : 0.f;
        sum += x[l];
    }
    red[tid] = sum; __syncthreads();
    for (int s = 128; s > 0; s >>= 1) {
        if (tid < s) red[tid] += red[tid+s];
        __syncthreads();
    }
    float inv = 1.f / red[0];
    #pragma unroll
    for (int l = 0; l < 4; l++) {
        int k = tid + l*256;
        if (k < wlen) S[k] = x[l]*inv;
    }
}

// =====================================================================
// K5: out_heads = P @ v_c  (NN, M=1024, N=64, K up to end of diag block)
// tile 128x64, microtile 8x4
// =====================================================================
__global__ __launch_bounds__(256,2) void k_av()
{
    int by = blockIdx.y, bh = blockIdx.z;
    const float* P = g_su + (size_t)bh*NTOK*NTOK;
    const float* V = g_vc + (size_t)bh*NTOK*DH;
    float* O = g_oh + (size_t)bh*NTOK*DH;
    __shared__ float As[16][132];
    __shared__ float Bs[16][68];
    int tid = threadIdx.x;
    int tx = tid & 15, ty = tid >> 4;
    int i0 = by*128;
    float acc[8][4] = {};
    int kend = (by+1)*128;
    for (int k0 = 0; k0 < kend; k0 += 16) {
        LOAD_T(As, P, i0, k0, NTOK);
        {   // B: 16x64 direct
            int r = tid >> 4, c4 = tid & 15;
            *(float4*)&Bs[r][c4*4] = *(const float4*)&V[(size_t)(k0+r)*DH + c4*4];
        }
        __syncthreads();
        #pragma unroll
        for (int kk = 0; kk < 16; kk++) {
            float a[8], b[4];
            *(float4*)&a[0] = *(const float4*)&As[kk][ty*8];
            *(float4*)&a[4] = *(const float4*)&As[kk][ty*8+4];
            *(float4*)&b[0] = *(const float4*)&Bs[kk][tx*4];
            #pragma unroll
            for (int i = 0; i < 8; i++)
                #pragma unroll
                for (int j = 0; j < 4; j++)
                    acc[i][j] += a[i]*b[j];
        }
        __syncthreads();
    }
    #pragma unroll
    for (int u = 0; u < 8; u++) {
        int i = i0 + ty*8 + u;
        #pragma unroll
        for (int v = 0; v < 4; v++) {
            int d = tx*4 + v;
            O[i*DH + d] = acc[u][v];
        }
    }
}

// =====================================================================
// K6: output projection. A gathered from g_oh as [2048, 512] @ w_out
// =====================================================================
__global__ __launch_bounds__(256,2) void k_outproj(
    const float* __restrict__ Wo, float* __restrict__ Out)
{
    __shared__ float As[16][132];
    __shared__ float Bs[16][132];
    int tid = threadIdx.x;
    int tx = tid & 15, ty = tid >> 4;
    int m0 = blockIdx.y*128, n0 = blockIdx.x*128;
    float acc[8][8] = {};
    for (int k0 = 0; k0 < DIMM; k0 += 16) {
        {   // gather-transpose load of A from g_oh
            #pragma unroll
            for (int l = 0; l < 2; l++) {
                int idx = tid + l*256;
                int r = idx >> 2, c4 = idx & 3;
                int m = m0 + r, k = k0 + c4*4;
                int b = m >> 10, tok = m & 1023;
                int h = k >> 6, dd = k & 63;
                float4 v = *(const float4*)&g_oh[((b*HEADS + h)*NTOK + tok)*DH + dd];
                As[c4*4+0][r] = v.x; As[c4*4+1][r] = v.y;
                As[c4*4+2][r] = v.z; As[c4*4+3][r] = v.w;
            }
        }
        LOAD_N(Bs, Wo, k0, n0, DIMM);
        __syncthreads();
        MMA_STEP(As, Bs, acc, tx, ty);
        __syncthreads();
    }
    #pragma unroll
    for (int u = 0; u < 8; u++) {
        int m = m0 + ty*8 + u;
        #pragma unroll
        for (int v = 0; v < 8; v++) {
            int nn = n0 + tx*8 + v;
            Out[(size_t)m*DIMM + nn] = acc[u][v];
        }
    }
}

extern "C" void kernel_launch(void* const* d_in, const int* in_sizes, int n_in,
                              void* d_out, int out_size)
{
    const float* x   = (const float*)d_in[0];
    const float* wqu = (const float*)d_in[1];
    const float* wku = (const float*)d_in[2];
    const float* wvu = (const float*)d_in[3];
    const float* wqc = (const float*)d_in[4];
    const float* wkc = (const float*)d_in[5];
    const float* wvc = (const float*)d_in[6];
    const float* wout= (const float*)d_in[7];
    float* out = (float*)d_out;

    k_proj   <<<dim3(4, 16, 6),  256>>>(x, wqu, wku, wvu, wqc, wkc, wvc);
    k_t1sig  <<<dim3(8, 8, 32),  256>>>();
    k_su     <<<dim3(8, 8, 16),  256>>>();
    k_softmax<<<dim3(1024,16),   256>>>();
    k_av     <<<dim3(1, 8, 16),  256>>>();
    k_outproj<<<dim3(4, 16),     256>>>(wout, out);
}

// round 5
// speedup vs baseline: 1.3358x; 1.2729x over previous
#include <cuda_runtime.h>
#include <cuda_bf16.h>
#include <math.h>
#include <stdint.h>

#define NTOK 1024
#define BATCH 2
#define HEADS 8
#define DH 64
#define BHN (BATCH*HEADS)   /* 16 */
#define DIMM 512
#define SCALE 0.125f
#define ST 40               /* smem row stride in bf16 elems (pad vs conflicts) */

// ---- scratch (device globals; allocation-free per harness rules) ----
__device__ float g_qu[BHN*NTOK*DH];
__device__ float g_ku[BHN*NTOK*DH];
__device__ float g_vu[BHN*NTOK*DH];
__device__ float g_qc[BHN*NTOK*DH];
__device__ float g_kc[BHN*NTOK*DH];
__device__ float g_vc[BHN*NTOK*DH];
__device__ float g_su[(size_t)BHN*NTOK*NTOK];   // scores -> probs (in place)
__device__ float g_oh[BHN*NTOK*DH];             // attn @ v_c, per-head

// bf16 hi/lo split operands
__device__ __nv_bfloat16 g_xh[2048*DIMM];
__device__ __nv_bfloat16 g_xl[2048*DIMM];
__device__ __nv_bfloat16 g_wth[6*DIMM*DIMM];   // transposed weights [z][n][k]
__device__ __nv_bfloat16 g_wtl[6*DIMM*DIMM];
__device__ __nv_bfloat16 g_t1h[(size_t)BHN*NTOK*NTOK];
__device__ __nv_bfloat16 g_t1l[(size_t)BHN*NTOK*NTOK];
__device__ __nv_bfloat16 g_sgh[(size_t)BHN*NTOK*NTOK];
__device__ __nv_bfloat16 g_sgl[(size_t)BHN*NTOK*NTOK];
__device__ __nv_bfloat16 g_qch[BHN*NTOK*DH];   // SCALE * q_c split
__device__ __nv_bfloat16 g_qcl[BHN*NTOK*DH];
__device__ __nv_bfloat16 g_kch[BHN*NTOK*DH];
__device__ __nv_bfloat16 g_kcl[BHN*NTOK*DH];

// =====================================================================
// mma.sync bf16 split helpers
// =====================================================================
#define MMA_BF16(c, a0,a1,a2,a3, b0,b1)                                  \
    asm volatile("mma.sync.aligned.m16n8k16.row.col.f32.bf16.bf16.f32 "  \
        "{%0,%1,%2,%3}, {%4,%5,%6,%7}, {%8,%9}, {%0,%1,%2,%3};"          \
        : "+f"((c)[0]), "+f"((c)[1]), "+f"((c)[2]), "+f"((c)[3])         \
        : "r"(a0), "r"(a1), "r"(a2), "r"(a3), "r"(b0), "r"(b1))

// load 128 rows x 32 k bf16 tile into smem (row-major, stride ST)
__device__ __forceinline__ void ld_tile(uint16_t* sm, const __nv_bfloat16* g,
                                        int row0, int k0, int ldg)
{
    int r = threadIdx.x >> 1, h = threadIdx.x & 1;
    const int4* src = (const int4*)(g + (size_t)(row0 + r)*ldg + k0 + h*16);
    int4 v0 = src[0], v1 = src[1];
    int4* dst = (int4*)(sm + r*ST + h*16);
    dst[0] = v0; dst[1] = v1;
}

// one 32-k chunk of the 128x128 3-product split GEMM
__device__ __forceinline__ void mma_chunk(
    const uint32_t* Ah, const uint32_t* Al,
    const uint32_t* Bh, const uint32_t* Bl,
    float acc[4][4][4], int wm, int wn, int lane)
{
    int g = lane >> 2, q = lane & 3;
    #pragma unroll
    for (int ks = 0; ks < 2; ks++) {
        int kq = ks*16 + q*2;
        uint32_t bh[4][2], bl[4][2];
        #pragma unroll
        for (int ni = 0; ni < 4; ni++) {
            int nr = wn*32 + ni*8 + g;
            int base = (nr*ST + kq) >> 1;
            bh[ni][0] = Bh[base]; bh[ni][1] = Bh[base + 4];
            bl[ni][0] = Bl[base]; bl[ni][1] = Bl[base + 4];
        }
        #pragma unroll
        for (int mi = 0; mi < 4; mi++) {
            int r0 = wm*64 + mi*16 + g;
            int ba  = (r0*ST + kq) >> 1;
            int ba8 = ((r0+8)*ST + kq) >> 1;
            uint32_t ah0 = Ah[ba], ah1 = Ah[ba8], ah2 = Ah[ba+4], ah3 = Ah[ba8+4];
            uint32_t al0 = Al[ba], al1 = Al[ba8], al2 = Al[ba+4], al3 = Al[ba8+4];
            #pragma unroll
            for (int ni = 0; ni < 4; ni++) {
                MMA_BF16(acc[mi][ni], ah0,ah1,ah2,ah3, bh[ni][0], bh[ni][1]);
                MMA_BF16(acc[mi][ni], ah0,ah1,ah2,ah3, bl[ni][0], bl[ni][1]);
                MMA_BF16(acc[mi][ni], al0,al1,al2,al3, bh[ni][0], bh[ni][1]);
            }
        }
    }
}

// =====================================================================
// prep kernels: split X; transpose + split weights
// =====================================================================
__global__ __launch_bounds__(256) void k_prep_x(const float* __restrict__ X)
{
    int idx = (blockIdx.x*256 + threadIdx.x)*4;
    float4 v = *(const float4*)&X[idx];
    float vv[4] = {v.x, v.y, v.z, v.w};
    #pragma unroll
    for (int i = 0; i < 4; i++) {
        __nv_bfloat16 h = __float2bfloat16(vv[i]);
        g_xh[idx+i] = h;
        g_xl[idx+i] = __float2bfloat16(vv[i] - __bfloat162float(h));
    }
}

__global__ void k_prep_w(
    const float* __restrict__ w0, const float* __restrict__ w1,
    const float* __restrict__ w2, const float* __restrict__ w3,
    const float* __restrict__ w4, const float* __restrict__ w5)
{
    const float* W;
    switch (blockIdx.z) {
        case 0: W = w0; break; case 1: W = w1; break; case 2: W = w2; break;
        case 3: W = w3; break; case 4: W = w4; break; default: W = w5; break;
    }
    __shared__ float t[32][33];
    int tx = threadIdx.x, ty = threadIdx.y;   // (32, 8)
    int k0 = blockIdx.y*32, n0 = blockIdx.x*32;
    #pragma unroll
    for (int i = 0; i < 4; i++)
        t[ty + i*8][tx] = W[(size_t)(k0 + ty + i*8)*DIMM + n0 + tx];
    __syncthreads();
    size_t zoff = (size_t)blockIdx.z * DIMM * DIMM;
    #pragma unroll
    for (int i = 0; i < 4; i++) {
        float v = t[tx][ty + i*8];
        __nv_bfloat16 h = __float2bfloat16(v);
        size_t o = zoff + (size_t)(n0 + ty + i*8)*DIMM + k0 + tx;
        g_wth[o] = h;
        g_wtl[o] = __float2bfloat16(v - __bfloat162float(h));
    }
}

// =====================================================================
// k_proj_mma: 6 projections via split bf16 mma. Also emits q_c/k_c splits.
// =====================================================================
__global__ __launch_bounds__(256) void k_proj_mma()
{
    int z = blockIdx.z;
    float* O;
    switch (z) {
        case 0: O = g_qu; break; case 1: O = g_ku; break; case 2: O = g_vu; break;
        case 3: O = g_qc; break; case 4: O = g_kc; break; default: O = g_vc; break;
    }
    const __nv_bfloat16* Wth = g_wth + (size_t)z*DIMM*DIMM;
    const __nv_bfloat16* Wtl = g_wtl + (size_t)z*DIMM*DIMM;
    __shared__ __align__(16) uint16_t sAh[128*ST], sAl[128*ST], sBh[128*ST], sBl[128*ST];
    int tid = threadIdx.x, lane = tid & 31, wid = tid >> 5;
    int wm = wid >> 2, wn = wid & 3;
    int m0 = blockIdx.y*128, n0 = blockIdx.x*128;
    float acc[4][4][4] = {};
    for (int k0 = 0; k0 < DIMM; k0 += 32) {
        ld_tile(sAh, g_xh, m0, k0, DIMM);
        ld_tile(sAl, g_xl, m0, k0, DIMM);
        ld_tile(sBh, Wth,  n0, k0, DIMM);
        ld_tile(sBl, Wtl,  n0, k0, DIMM);
        __syncthreads();
        mma_chunk((const uint32_t*)sAh, (const uint32_t*)sAl,
                  (const uint32_t*)sBh, (const uint32_t*)sBl, acc, wm, wn, lane);
        __syncthreads();
    }
    int g = lane >> 2, q = lane & 3;
    #pragma unroll
    for (int mi = 0; mi < 4; mi++) {
        #pragma unroll
        for (int ni = 0; ni < 4; ni++) {
            int col = n0 + wn*32 + ni*8 + q*2;
            int h = col >> 6, dd = col & 63;
            #pragma unroll
            for (int rr = 0; rr < 2; rr++) {
                int m = m0 + wm*64 + mi*16 + g + rr*8;
                int b = m >> 10, tok = m & 1023;
                float v0 = acc[mi][ni][rr*2+0], v1 = acc[mi][ni][rr*2+1];
                size_t oidx = ((size_t)(b*HEADS + h)*NTOK + tok)*DH + dd;
                *(float2*)&O[oidx] = make_float2(v0, v1);
                if (z == 3) {   // q_c: scaled splits
                    float s0 = v0*SCALE, s1 = v1*SCALE;
                    __nv_bfloat16 h0 = __float2bfloat16(s0), h1 = __float2bfloat16(s1);
                    g_qch[oidx] = h0; g_qch[oidx+1] = h1;
                    g_qcl[oidx]   = __float2bfloat16(s0 - __bfloat162float(h0));
                    g_qcl[oidx+1] = __float2bfloat16(s1 - __bfloat162float(h1));
                } else if (z == 4) {
                    __nv_bfloat16 h0 = __float2bfloat16(v0), h1 = __float2bfloat16(v1);
                    g_kch[oidx] = h0; g_kch[oidx+1] = h1;
                    g_kcl[oidx]   = __float2bfloat16(v0 - __bfloat162float(h0));
                    g_kcl[oidx+1] = __float2bfloat16(v1 - __bfloat162float(h1));
                }
            }
        }
    }
}

// =====================================================================
// k_t1sig (FFMA): term1/sig, writes bf16 hi/lo splits directly
// =====================================================================
#define MMA_STEP(As, Bs, acc, tx, ty)                                   \
    do {                                                                \
        _Pragma("unroll")                                               \
        for (int kk = 0; kk < 16; kk++) {                               \
            float a[8], b[8];                                           \
            *(float4*)&a[0] = *(const float4*)&As[kk][(ty)*8];          \
            *(float4*)&a[4] = *(const float4*)&As[kk][(ty)*8+4];        \
            *(float4*)&b[0] = *(const float4*)&Bs[kk][(tx)*8];          \
            *(float4*)&b[4] = *(const float4*)&Bs[kk][(tx)*8+4];        \
            _Pragma("unroll")                                           \
            for (int i = 0; i < 8; i++)                                 \
                _Pragma("unroll")                                       \
                for (int j = 0; j < 8; j++)                             \
                    acc[i][j] += a[i]*b[j];                             \
        }                                                               \
    } while (0)

#define LOAD_T(As, A, row0, k0, lda)                                    \
    do {                                                                \
        _Pragma("unroll")                                               \
        for (int l = 0; l < 2; l++) {                                   \
            int idx = tid + l*256;                                      \
            int r = idx >> 2, c4 = idx & 3;                             \
            float4 v = *(const float4*)&(A)[(size_t)((row0)+r)*(lda) + (k0) + c4*4]; \
            As[c4*4+0][r] = v.x; As[c4*4+1][r] = v.y;                   \
            As[c4*4+2][r] = v.z; As[c4*4+3][r] = v.w;                   \
        }                                                               \
    } while (0)

__global__ __launch_bounds__(256,2) void k_t1sig()
{
    int which = blockIdx.z >> 4;
    int bh    = blockIdx.z & 15;
    int bx = blockIdx.x, by = blockIdx.y;
    if (which == 0) { if (bx > by) return; }
    else            { if (bx < by) return; }
    const float* A  = (which == 0 ? g_qc : g_qu) + (size_t)bh*NTOK*DH;
    const float* Bm = (which == 0 ? g_vu : g_ku) + (size_t)bh*NTOK*DH;
    __nv_bfloat16* Oh = (which == 0 ? g_t1h : g_sgh) + (size_t)bh*NTOK*NTOK;
    __nv_bfloat16* Ol = (which == 0 ? g_t1l : g_sgl) + (size_t)bh*NTOK*NTOK;
    __shared__ float As[16][132];
    __shared__ float Bs[16][132];
    int tid = threadIdx.x;
    int tx = tid & 15, ty = tid >> 4;
    int i0 = by*128, j0 = bx*128;
    float acc[8][8] = {};
    for (int k0 = 0; k0 < DH; k0 += 16) {
        LOAD_T(As, A,  i0, k0, DH);
        LOAD_T(Bs, Bm, j0, k0, DH);
        __syncthreads();
        MMA_STEP(As, Bs, acc, tx, ty);
        __syncthreads();
    }
    #pragma unroll
    for (int u = 0; u < 8; u++) {
        int i = i0 + ty*8 + u;
        #pragma unroll
        for (int v = 0; v < 8; v++) {
            int j = j0 + tx*8 + v;
            float s = acc[u][v]*SCALE;
            float o;
            if (which == 0) o = (j <= i) ? s : 0.f;
            else            o = (j >  i) ? 1.f/(1.f + __expf(-s)) : 0.f;
            size_t idx = (size_t)i*NTOK + j;
            __nv_bfloat16 hh = __float2bfloat16(o);
            Oh[idx] = hh;
            Ol[idx] = __float2bfloat16(o - __bfloat162float(hh));
        }
    }
}

// =====================================================================
// k_su_mma: split-mma fused scores.
// acc = term1 @ sig^T (block-triangular j); acc = -silu(acc);
// acc += (SCALE*q_c) @ k_c^T; masked store to g_su.
// =====================================================================
__global__ __launch_bounds__(256) void k_su_mma()
{
    int bx = blockIdx.x, by = blockIdx.y, bh = blockIdx.z;
    if (bx > by) return;
    const __nv_bfloat16* T1h = g_t1h + (size_t)bh*NTOK*NTOK;
    const __nv_bfloat16* T1l = g_t1l + (size_t)bh*NTOK*NTOK;
    const __nv_bfloat16* SGh = g_sgh + (size_t)bh*NTOK*NTOK;
    const __nv_bfloat16* SGl = g_sgl + (size_t)bh*NTOK*NTOK;
    const __nv_bfloat16* Qh = g_qch + (size_t)bh*NTOK*DH;
    const __nv_bfloat16* Ql = g_qcl + (size_t)bh*NTOK*DH;
    const __nv_bfloat16* Kh = g_kch + (size_t)bh*NTOK*DH;
    const __nv_bfloat16* Kl = g_kcl + (size_t)bh*NTOK*DH;
    float* S = g_su + (size_t)bh*NTOK*NTOK;

    __shared__ __align__(16) uint16_t sAh[128*ST], sAl[128*ST], sBh[128*ST], sBl[128*ST];
    int tid = threadIdx.x, lane = tid & 31, wid = tid >> 5;
    int wm = wid >> 2, wn = wid & 3;
    int i0 = by*128, kx0 = bx*128;
    float acc[4][4][4] = {};

    // phase 1: S_u over j in [bx*128, (by+1)*128)
    int jend = (by+1)*128;
    for (int j0 = bx*128; j0 < jend; j0 += 32) {
        ld_tile(sAh, T1h, i0,  j0, NTOK);
        ld_tile(sAl, T1l, i0,  j0, NTOK);
        ld_tile(sBh, SGh, kx0, j0, NTOK);
        ld_tile(sBl, SGl, kx0, j0, NTOK);
        __syncthreads();
        mma_chunk((const uint32_t*)sAh, (const uint32_t*)sAl,
                  (const uint32_t*)sBh, (const uint32_t*)sBl, acc, wm, wn, lane);
        __syncthreads();
    }
    // acc = -silu(acc)
    #pragma unroll
    for (int mi = 0; mi < 4; mi++)
        #pragma unroll
        for (int ni = 0; ni < 4; ni++)
            #pragma unroll
            for (int e = 0; e < 4; e++) {
                float su = acc[mi][ni][e];
                acc[mi][ni][e] = -su / (1.f + __expf(-su));
            }
    // phase 2: += (SCALE*q_c) @ k_c^T
    for (int k0 = 0; k0 < DH; k0 += 32) {
        ld_tile(sAh, Qh, i0,  k0, DH);
        ld_tile(sAl, Ql, i0,  k0, DH);
        ld_tile(sBh, Kh, kx0, k0, DH);
        ld_tile(sBl, Kl, kx0, k0, DH);
        __syncthreads();
        mma_chunk((const uint32_t*)sAh, (const uint32_t*)sAl,
                  (const uint32_t*)sBh, (const uint32_t*)sBl, acc, wm, wn, lane);
        __syncthreads();
    }
    // epilogue: causal mask + store
    int g = lane >> 2, q = lane & 3;
    #pragma unroll
    for (int mi = 0; mi < 4; mi++) {
        #pragma unroll
        for (int ni = 0; ni < 4; ni++) {
            int k = kx0 + wn*32 + ni*8 + q*2;
            #pragma unroll
            for (int rr = 0; rr < 2; rr++) {
                int i = i0 + wm*64 + mi*16 + g + rr*8;
                float v0 = (k   <= i) ? acc[mi][ni][rr*2+0] : -1e30f;
                float v1 = (k+1 <= i) ? acc[mi][ni][rr*2+1] : -1e30f;
                *(float2*)&S[(size_t)i*NTOK + k] = make_float2(v0, v1);
            }
        }
    }
}

// =====================================================================
// k_softmax / k_av / k_outproj (unchanged FFMA)
// =====================================================================
__global__ __launch_bounds__(256) void k_softmax()
{
    int i  = blockIdx.x;
    int bh = blockIdx.y;
    float* S = g_su + (size_t)bh*NTOK*NTOK + (size_t)i*NTOK;
    int L = i + 1;
    int wlen = ((i >> 7) + 1) << 7;
    int tid = threadIdx.x;
    __shared__ float red[256];
    float x[4];
    float mx = -1e30f;
    #pragma unroll
    for (int l = 0; l < 4; l++) {
        int k = tid + l*256;
        x[l] = (k < L) ? S[k] : -1e30f;
        mx = fmaxf(mx, x[l]);
    }
    red[tid] = mx; __syncthreads();
    for (int s = 128; s > 0; s >>= 1) {
        if (tid < s) red[tid] = fmaxf(red[tid], red[tid+s]);
        __syncthreads();
    }
    mx = red[0]; __syncthreads();
    float sum = 0.f;
    #pragma unroll
    for (int l = 0; l < 4; l++) {
        int k = tid + l*256;
        x[l] = (k < L) ? __expf(x[l] - mx) : 0.f;
        sum += x[l];
    }
    red[tid] = sum; __syncthreads();
    for (int s = 128; s > 0; s >>= 1) {
        if (tid < s) red[tid] += red[tid+s];
        __syncthreads();
    }
    float inv = 1.f / red[0];
    #pragma unroll
    for (int l = 0; l < 4; l++) {
        int k = tid + l*256;
        if (k < wlen) S[k] = x[l]*inv;
    }
}

__global__ __launch_bounds__(256,2) void k_av()
{
    int by = blockIdx.y, bh = blockIdx.z;
    const float* P = g_su + (size_t)bh*NTOK*NTOK;
    const float* V = g_vc + (size_t)bh*NTOK*DH;
    float* O = g_oh + (size_t)bh*NTOK*DH;
    __shared__ float As[16][132];
    __shared__ float Bs[16][68];
    int tid = threadIdx.x;
    int tx = tid & 15, ty = tid >> 4;
    int i0 = by*128;
    float acc[8][4] = {};
    int kend = (by+1)*128;
    for (int k0 = 0; k0 < kend; k0 += 16) {
        LOAD_T(As, P, i0, k0, NTOK);
        {
            int r = tid >> 4, c4 = tid & 15;
            *(float4*)&Bs[r][c4*4] = *(const float4*)&V[(size_t)(k0+r)*DH + c4*4];
        }
        __syncthreads();
        #pragma unroll
        for (int kk = 0; kk < 16; kk++) {
            float a[8], b[4];
            *(float4*)&a[0] = *(const float4*)&As[kk][ty*8];
            *(float4*)&a[4] = *(const float4*)&As[kk][ty*8+4];
            *(float4*)&b[0] = *(const float4*)&Bs[kk][tx*4];
            #pragma unroll
            for (int i = 0; i < 8; i++)
                #pragma unroll
                for (int j = 0; j < 4; j++)
                    acc[i][j] += a[i]*b[j];
        }
        __syncthreads();
    }
    #pragma unroll
    for (int u = 0; u < 8; u++) {
        int i = i0 + ty*8 + u;
        #pragma unroll
        for (int v = 0; v < 4; v++) {
            int d = tx*4 + v;
            O[i*DH + d] = acc[u][v];
        }
    }
}

__global__ __launch_bounds__(256,2) void k_outproj(
    const float* __restrict__ Wo, float* __restrict__ Out)
{
    __shared__ float As[16][132];
    __shared__ float Bs[16][132];
    int tid = threadIdx.x;
    int tx = tid & 15, ty = tid >> 4;
    int m0 = blockIdx.y*128, n0 = blockIdx.x*128;
    float acc[8][8] = {};
    for (int k0 = 0; k0 < DIMM; k0 += 16) {
        {
            #pragma unroll
            for (int l = 0; l < 2; l++) {
                int idx = tid + l*256;
                int r = idx >> 2, c4 = idx & 3;
                int m = m0 + r, k = k0 + c4*4;
                int b = m >> 10, tok = m & 1023;
                int h = k >> 6, dd = k & 63;
                float4 v = *(const float4*)&g_oh[((b*HEADS + h)*NTOK + tok)*DH + dd];
                As[c4*4+0][r] = v.x; As[c4*4+1][r] = v.y;
                As[c4*4+2][r] = v.z; As[c4*4+3][r] = v.w;
            }
        }
        {
            #pragma unroll
            for (int l = 0; l < 2; l++) {
                int idx = tid + l*256;
                int r = idx >> 5, c4 = idx & 31;
                *(float4*)&Bs[r][c4*4] =
                    *(const float4*)&Wo[(size_t)(k0+r)*DIMM + n0 + c4*4];
            }
        }
        __syncthreads();
        MMA_STEP(As, Bs, acc, tx, ty);
        __syncthreads();
    }
    #pragma unroll
    for (int u = 0; u < 8; u++) {
        int m = m0 + ty*8 + u;
        #pragma unroll
        for (int v = 0; v < 8; v++) {
            int nn = n0 + tx*8 + v;
            Out[(size_t)m*DIMM + nn] = acc[u][v];
        }
    }
}

extern "C" void kernel_launch(void* const* d_in, const int* in_sizes, int n_in,
                              void* d_out, int out_size)
{
    const float* x   = (const float*)d_in[0];
    const float* wqu = (const float*)d_in[1];
    const float* wku = (const float*)d_in[2];
    const float* wvu = (const float*)d_in[3];
    const float* wqc = (const float*)d_in[4];
    const float* wkc = (const float*)d_in[5];
    const float* wvc = (const float*)d_in[6];
    const float* wout= (const float*)d_in[7];
    float* out = (float*)d_out;

    k_prep_x  <<<1024, 256>>>(x);
    k_prep_w  <<<dim3(16,16,6), dim3(32,8)>>>(wqu, wku, wvu, wqc, wkc, wvc);
    k_proj_mma<<<dim3(4, 16, 6), 256>>>();
    k_t1sig   <<<dim3(8, 8, 32), 256>>>();
    k_su_mma  <<<dim3(8, 8, 16), 256>>>();
    k_softmax <<<dim3(1024,16),  256>>>();
    k_av      <<<dim3(1, 8, 16), 256>>>();
    k_outproj <<<dim3(4, 16),    256>>>(wout, out);
}

// round 6
// speedup vs baseline: 1.6414x; 1.2287x over previous
#include <cuda_runtime.h>
#include <cuda_bf16.h>
#include <math.h>
#include <stdint.h>

#define NTOK 1024
#define BATCH 2
#define HEADS 8
#define DH 64
#define BHN (BATCH*HEADS)   /* 16 */
#define DIMM 512
#define SCALE 0.125f
#define ST 40               /* smem row stride in bf16 elems */

// ---- scratch ----
__device__ float g_vc[BHN*NTOK*DH];             // fp32 v_c for k_av
__device__ float g_su[(size_t)BHN*NTOK*NTOK];   // scores -> probs (in place)

// bf16 hi/lo split operands
__device__ __nv_bfloat16 g_xh[2048*DIMM];
__device__ __nv_bfloat16 g_xl[2048*DIMM];
__device__ __nv_bfloat16 g_wth[7*DIMM*DIMM];   // transposed weights [z][n][k]
__device__ __nv_bfloat16 g_wtl[7*DIMM*DIMM];
__device__ __nv_bfloat16 g_t1h[(size_t)BHN*NTOK*NTOK];
__device__ __nv_bfloat16 g_t1l[(size_t)BHN*NTOK*NTOK];
__device__ __nv_bfloat16 g_sgh[(size_t)BHN*NTOK*NTOK];
__device__ __nv_bfloat16 g_sgl[(size_t)BHN*NTOK*NTOK];
__device__ __nv_bfloat16 g_quh[BHN*NTOK*DH];   // SCALE * q_u
__device__ __nv_bfloat16 g_qul[BHN*NTOK*DH];
__device__ __nv_bfloat16 g_kuh[BHN*NTOK*DH];
__device__ __nv_bfloat16 g_kul[BHN*NTOK*DH];
__device__ __nv_bfloat16 g_vuh[BHN*NTOK*DH];
__device__ __nv_bfloat16 g_vul[BHN*NTOK*DH];
__device__ __nv_bfloat16 g_qch[BHN*NTOK*DH];   // SCALE * q_c
__device__ __nv_bfloat16 g_qcl[BHN*NTOK*DH];
__device__ __nv_bfloat16 g_kch[BHN*NTOK*DH];
__device__ __nv_bfloat16 g_kcl[BHN*NTOK*DH];
__device__ __nv_bfloat16 g_ohh[2048*DIMM];     // attn@v_c, [m][h*64+d] split
__device__ __nv_bfloat16 g_ohl[2048*DIMM];

// =====================================================================
// mma.sync bf16 split helpers
// =====================================================================
#define MMA_BF16(c, a0,a1,a2,a3, b0,b1)                                  \
    asm volatile("mma.sync.aligned.m16n8k16.row.col.f32.bf16.bf16.f32 "  \
        "{%0,%1,%2,%3}, {%4,%5,%6,%7}, {%8,%9}, {%0,%1,%2,%3};"          \
        : "+f"((c)[0]), "+f"((c)[1]), "+f"((c)[2]), "+f"((c)[3])         \
        : "r"(a0), "r"(a1), "r"(a2), "r"(a3), "r"(b0), "r"(b1))

__device__ __forceinline__ void ld_tile(uint16_t* sm, const __nv_bfloat16* g,
                                        int row0, int k0, int ldg)
{
    int r = threadIdx.x >> 1, h = threadIdx.x & 1;
    const int4* src = (const int4*)(g + (size_t)(row0 + r)*ldg + k0 + h*16);
    int4 v0 = src[0], v1 = src[1];
    int4* dst = (int4*)(sm + r*ST + h*16);
    dst[0] = v0; dst[1] = v1;
}

__device__ __forceinline__ void mma_chunk(
    const uint32_t* Ah, const uint32_t* Al,
    const uint32_t* Bh, const uint32_t* Bl,
    float acc[4][4][4], int wm, int wn, int lane)
{
    int g = lane >> 2, q = lane & 3;
    #pragma unroll
    for (int ks = 0; ks < 2; ks++) {
        int kq = ks*16 + q*2;
        uint32_t bh[4][2], bl[4][2];
        #pragma unroll
        for (int ni = 0; ni < 4; ni++) {
            int nr = wn*32 + ni*8 + g;
            int base = (nr*ST + kq) >> 1;
            bh[ni][0] = Bh[base]; bh[ni][1] = Bh[base + 4];
            bl[ni][0] = Bl[base]; bl[ni][1] = Bl[base + 4];
        }
        #pragma unroll
        for (int mi = 0; mi < 4; mi++) {
            int r0 = wm*64 + mi*16 + g;
            int ba  = (r0*ST + kq) >> 1;
            int ba8 = ((r0+8)*ST + kq) >> 1;
            uint32_t ah0 = Ah[ba], ah1 = Ah[ba8], ah2 = Ah[ba+4], ah3 = Ah[ba8+4];
            uint32_t al0 = Al[ba], al1 = Al[ba8], al2 = Al[ba+4], al3 = Al[ba8+4];
            #pragma unroll
            for (int ni = 0; ni < 4; ni++) {
                MMA_BF16(acc[mi][ni], ah0,ah1,ah2,ah3, bh[ni][0], bh[ni][1]);
                MMA_BF16(acc[mi][ni], ah0,ah1,ah2,ah3, bl[ni][0], bl[ni][1]);
                MMA_BF16(acc[mi][ni], al0,al1,al2,al3, bh[ni][0], bh[ni][1]);
            }
        }
    }
}

__device__ __forceinline__ void split_bf16(float v, __nv_bfloat16& h, __nv_bfloat16& l)
{
    h = __float2bfloat16(v);
    l = __float2bfloat16(v - __bfloat162float(h));
}

// =====================================================================
// prep kernels
// =====================================================================
__global__ __launch_bounds__(256) void k_prep_x(const float* __restrict__ X)
{
    int idx = (blockIdx.x*256 + threadIdx.x)*4;
    float4 v = *(const float4*)&X[idx];
    float vv[4] = {v.x, v.y, v.z, v.w};
    #pragma unroll
    for (int i = 0; i < 4; i++) {
        __nv_bfloat16 h, l; split_bf16(vv[i], h, l);
        g_xh[idx+i] = h; g_xl[idx+i] = l;
    }
}

__global__ void k_prep_w(
    const float* __restrict__ w0, const float* __restrict__ w1,
    const float* __restrict__ w2, const float* __restrict__ w3,
    const float* __restrict__ w4, const float* __restrict__ w5,
    const float* __restrict__ w6)
{
    const float* W;
    switch (blockIdx.z) {
        case 0: W = w0; break; case 1: W = w1; break; case 2: W = w2; break;
        case 3: W = w3; break; case 4: W = w4; break; case 5: W = w5; break;
        default: W = w6; break;
    }
    __shared__ float t[32][33];
    int tx = threadIdx.x, ty = threadIdx.y;   // (32, 8)
    int k0 = blockIdx.y*32, n0 = blockIdx.x*32;
    #pragma unroll
    for (int i = 0; i < 4; i++)
        t[ty + i*8][tx] = W[(size_t)(k0 + ty + i*8)*DIMM + n0 + tx];
    __syncthreads();
    size_t zoff = (size_t)blockIdx.z * DIMM * DIMM;
    #pragma unroll
    for (int i = 0; i < 4; i++) {
        float v = t[tx][ty + i*8];
        __nv_bfloat16 h, l; split_bf16(v, h, l);
        size_t o = zoff + (size_t)(n0 + ty + i*8)*DIMM + k0 + tx;
        g_wth[o] = h; g_wtl[o] = l;
    }
}

// =====================================================================
// k_proj_mma: 6 projections. Emits bf16 splits (scaled for q_u/q_c);
// fp32 only for v_c.
// =====================================================================
__global__ __launch_bounds__(256) void k_proj_mma()
{
    int z = blockIdx.z;
    __nv_bfloat16 *Oh = 0, *Ol = 0;
    float sc = 1.f;
    switch (z) {
        case 0: Oh = g_quh; Ol = g_qul; sc = SCALE; break;
        case 1: Oh = g_kuh; Ol = g_kul; break;
        case 2: Oh = g_vuh; Ol = g_vul; break;
        case 3: Oh = g_qch; Ol = g_qcl; sc = SCALE; break;
        case 4: Oh = g_kch; Ol = g_kcl; break;
        default: break;  // z==5 -> fp32 g_vc
    }
    const __nv_bfloat16* Wth = g_wth + (size_t)z*DIMM*DIMM;
    const __nv_bfloat16* Wtl = g_wtl + (size_t)z*DIMM*DIMM;
    __shared__ __align__(16) uint16_t sAh[128*ST], sAl[128*ST], sBh[128*ST], sBl[128*ST];
    int tid = threadIdx.x, lane = tid & 31, wid = tid >> 5;
    int wm = wid >> 2, wn = wid & 3;
    int m0 = blockIdx.y*128, n0 = blockIdx.x*128;
    float acc[4][4][4] = {};
    for (int k0 = 0; k0 < DIMM; k0 += 32) {
        ld_tile(sAh, g_xh, m0, k0, DIMM);
        ld_tile(sAl, g_xl, m0, k0, DIMM);
        ld_tile(sBh, Wth,  n0, k0, DIMM);
        ld_tile(sBl, Wtl,  n0, k0, DIMM);
        __syncthreads();
        mma_chunk((const uint32_t*)sAh, (const uint32_t*)sAl,
                  (const uint32_t*)sBh, (const uint32_t*)sBl, acc, wm, wn, lane);
        __syncthreads();
    }
    int g = lane >> 2, q = lane & 3;
    #pragma unroll
    for (int mi = 0; mi < 4; mi++) {
        #pragma unroll
        for (int ni = 0; ni < 4; ni++) {
            int col = n0 + wn*32 + ni*8 + q*2;
            int h = col >> 6, dd = col & 63;
            #pragma unroll
            for (int rr = 0; rr < 2; rr++) {
                int m = m0 + wm*64 + mi*16 + g + rr*8;
                int b = m >> 10, tok = m & 1023;
                float v0 = acc[mi][ni][rr*2+0], v1 = acc[mi][ni][rr*2+1];
                size_t oidx = ((size_t)(b*HEADS + h)*NTOK + tok)*DH + dd;
                if (z == 5) {
                    *(float2*)&g_vc[oidx] = make_float2(v0, v1);
                } else {
                    float s0 = v0*sc, s1 = v1*sc;
                    __nv_bfloat16 h0, l0, h1, l1;
                    split_bf16(s0, h0, l0); split_bf16(s1, h1, l1);
                    __nv_bfloat162 hp; hp.x = h0; hp.y = h1;
                    __nv_bfloat162 lp; lp.x = l0; lp.y = l1;
                    *(__nv_bfloat162*)&Oh[oidx] = hp;
                    *(__nv_bfloat162*)&Ol[oidx] = lp;
                }
            }
        }
    }
}

// =====================================================================
// k_t1sig_mma: term1 (which=0, lower blocks) / sig (which=1, upper blocks)
// via split mma, K=64. Writes bf16 splits.
// =====================================================================
__global__ __launch_bounds__(256) void k_t1sig_mma()
{
    int which = blockIdx.z >> 4;
    int bh    = blockIdx.z & 15;
    int bx = blockIdx.x, by = blockIdx.y;
    if (which == 0) { if (bx > by) return; }
    else            { if (bx < by) return; }
    size_t voff = (size_t)bh*NTOK*DH;
    const __nv_bfloat16* Ah_g = (which == 0 ? g_qch : g_quh) + voff;
    const __nv_bfloat16* Al_g = (which == 0 ? g_qcl : g_qul) + voff;
    const __nv_bfloat16* Bh_g = (which == 0 ? g_vuh : g_kuh) + voff;
    const __nv_bfloat16* Bl_g = (which == 0 ? g_vul : g_kul) + voff;
    __nv_bfloat16* Oh = (which == 0 ? g_t1h : g_sgh) + (size_t)bh*NTOK*NTOK;
    __nv_bfloat16* Ol = (which == 0 ? g_t1l : g_sgl) + (size_t)bh*NTOK*NTOK;

    __shared__ __align__(16) uint16_t sAh[128*ST], sAl[128*ST], sBh[128*ST], sBl[128*ST];
    int tid = threadIdx.x, lane = tid & 31, wid = tid >> 5;
    int wm = wid >> 2, wn = wid & 3;
    int i0 = by*128, j0b = bx*128;
    float acc[4][4][4] = {};
    for (int k0 = 0; k0 < DH; k0 += 32) {
        ld_tile(sAh, Ah_g, i0,  k0, DH);
        ld_tile(sAl, Al_g, i0,  k0, DH);
        ld_tile(sBh, Bh_g, j0b, k0, DH);
        ld_tile(sBl, Bl_g, j0b, k0, DH);
        __syncthreads();
        mma_chunk((const uint32_t*)sAh, (const uint32_t*)sAl,
                  (const uint32_t*)sBh, (const uint32_t*)sBl, acc, wm, wn, lane);
        __syncthreads();
    }
    int g = lane >> 2, q = lane & 3;
    #pragma unroll
    for (int mi = 0; mi < 4; mi++) {
        #pragma unroll
        for (int ni = 0; ni < 4; ni++) {
            int j = j0b + wn*32 + ni*8 + q*2;
            #pragma unroll
            for (int rr = 0; rr < 2; rr++) {
                int i = i0 + wm*64 + mi*16 + g + rr*8;
                float s0 = acc[mi][ni][rr*2+0], s1 = acc[mi][ni][rr*2+1];
                float o0, o1;
                if (which == 0) {
                    o0 = (j   <= i) ? s0 : 0.f;
                    o1 = (j+1 <= i) ? s1 : 0.f;
                } else {
                    o0 = (j   > i) ? 1.f/(1.f + __expf(-s0)) : 0.f;
                    o1 = (j+1 > i) ? 1.f/(1.f + __expf(-s1)) : 0.f;
                }
                __nv_bfloat16 h0, l0, h1, l1;
                split_bf16(o0, h0, l0); split_bf16(o1, h1, l1);
                __nv_bfloat162 hp; hp.x = h0; hp.y = h1;
                __nv_bfloat162 lp; lp.x = l0; lp.y = l1;
                size_t idx = (size_t)i*NTOK + j;
                *(__nv_bfloat162*)&Oh[idx] = hp;
                *(__nv_bfloat162*)&Ol[idx] = lp;
            }
        }
    }
}

// =====================================================================
// k_su_mma: fused scores (unchanged from R5)
// =====================================================================
__global__ __launch_bounds__(256) void k_su_mma()
{
    int bx = blockIdx.x, by = blockIdx.y, bh = blockIdx.z;
    if (bx > by) return;
    const __nv_bfloat16* T1h = g_t1h + (size_t)bh*NTOK*NTOK;
    const __nv_bfloat16* T1l = g_t1l + (size_t)bh*NTOK*NTOK;
    const __nv_bfloat16* SGh = g_sgh + (size_t)bh*NTOK*NTOK;
    const __nv_bfloat16* SGl = g_sgl + (size_t)bh*NTOK*NTOK;
    const __nv_bfloat16* Qh = g_qch + (size_t)bh*NTOK*DH;
    const __nv_bfloat16* Ql = g_qcl + (size_t)bh*NTOK*DH;
    const __nv_bfloat16* Kh = g_kch + (size_t)bh*NTOK*DH;
    const __nv_bfloat16* Kl = g_kcl + (size_t)bh*NTOK*DH;
    float* S = g_su + (size_t)bh*NTOK*NTOK;

    __shared__ __align__(16) uint16_t sAh[128*ST], sAl[128*ST], sBh[128*ST], sBl[128*ST];
    int tid = threadIdx.x, lane = tid & 31, wid = tid >> 5;
    int wm = wid >> 2, wn = wid & 3;
    int i0 = by*128, kx0 = bx*128;
    float acc[4][4][4] = {};

    int jend = (by+1)*128;
    for (int j0 = bx*128; j0 < jend; j0 += 32) {
        ld_tile(sAh, T1h, i0,  j0, NTOK);
        ld_tile(sAl, T1l, i0,  j0, NTOK);
        ld_tile(sBh, SGh, kx0, j0, NTOK);
        ld_tile(sBl, SGl, kx0, j0, NTOK);
        __syncthreads();
        mma_chunk((const uint32_t*)sAh, (const uint32_t*)sAl,
                  (const uint32_t*)sBh, (const uint32_t*)sBl, acc, wm, wn, lane);
        __syncthreads();
    }
    #pragma unroll
    for (int mi = 0; mi < 4; mi++)
        #pragma unroll
        for (int ni = 0; ni < 4; ni++)
            #pragma unroll
            for (int e = 0; e < 4; e++) {
                float su = acc[mi][ni][e];
                acc[mi][ni][e] = -su / (1.f + __expf(-su));
            }
    for (int k0 = 0; k0 < DH; k0 += 32) {
        ld_tile(sAh, Qh, i0,  k0, DH);
        ld_tile(sAl, Ql, i0,  k0, DH);
        ld_tile(sBh, Kh, kx0, k0, DH);
        ld_tile(sBl, Kl, kx0, k0, DH);
        __syncthreads();
        mma_chunk((const uint32_t*)sAh, (const uint32_t*)sAl,
                  (const uint32_t*)sBh, (const uint32_t*)sBl, acc, wm, wn, lane);
        __syncthreads();
    }
    int g = lane >> 2, q = lane & 3;
    #pragma unroll
    for (int mi = 0; mi < 4; mi++) {
        #pragma unroll
        for (int ni = 0; ni < 4; ni++) {
            int k = kx0 + wn*32 + ni*8 + q*2;
            #pragma unroll
            for (int rr = 0; rr < 2; rr++) {
                int i = i0 + wm*64 + mi*16 + g + rr*8;
                float v0 = (k   <= i) ? acc[mi][ni][rr*2+0] : -1e30f;
                float v1 = (k+1 <= i) ? acc[mi][ni][rr*2+1] : -1e30f;
                *(float2*)&S[(size_t)i*NTOK + k] = make_float2(v0, v1);
            }
        }
    }
}

// =====================================================================
// k_softmax (unchanged)
// =====================================================================
__global__ __launch_bounds__(256) void k_softmax()
{
    int i  = blockIdx.x;
    int bh = blockIdx.y;
    float* S = g_su + (size_t)bh*NTOK*NTOK + (size_t)i*NTOK;
    int L = i + 1;
    int wlen = ((i >> 7) + 1) << 7;
    int tid = threadIdx.x;
    __shared__ float red[256];
    float x[4];
    float mx = -1e30f;
    #pragma unroll
    for (int l = 0; l < 4; l++) {
        int k = tid + l*256;
        x[l] = (k < L) ? S[k] : -1e30f;
        mx = fmaxf(mx, x[l]);
    }
    red[tid] = mx; __syncthreads();
    for (int s = 128; s > 0; s >>= 1) {
        if (tid < s) red[tid] = fmaxf(red[tid], red[tid+s]);
        __syncthreads();
    }
    mx = red[0]; __syncthreads();
    float sum = 0.f;
    #pragma unroll
    for (int l = 0; l < 4; l++) {
        int k = tid + l*256;
        x[l] = (k < L) ? __expf(x[l] - mx) : 0.f;
        sum += x[l];
    }
    red[tid] = sum; __syncthreads();
    for (int s = 128; s > 0; s >>= 1) {
        if (tid < s) red[tid] += red[tid+s];
        __syncthreads();
    }
    float inv = 1.f / red[0];
    #pragma unroll
    for (int l = 0; l < 4; l++) {
        int k = tid + l*256;
        if (k < wlen) S[k] = x[l]*inv;
    }
}

// =====================================================================
// k_av: P @ v_c (FFMA), epilogue writes bf16 splits into [m][h*64+d]
// =====================================================================
#define LOAD_TF(As, A, row0, k0, lda)                                   \
    do {                                                                \
        _Pragma("unroll")                                               \
        for (int l = 0; l < 2; l++) {                                   \
            int idx = tid + l*256;                                      \
            int r = idx >> 2, c4 = idx & 3;                             \
            float4 v = *(const float4*)&(A)[(size_t)((row0)+r)*(lda) + (k0) + c4*4]; \
            As[c4*4+0][r] = v.x; As[c4*4+1][r] = v.y;                   \
            As[c4*4+2][r] = v.z; As[c4*4+3][r] = v.w;                   \
        }                                                               \
    } while (0)

__global__ __launch_bounds__(256,2) void k_av()
{
    int by = blockIdx.y, bh = blockIdx.z;
    int b = bh >> 3, h = bh & 7;
    const float* P = g_su + (size_t)bh*NTOK*NTOK;
    const float* V = g_vc + (size_t)bh*NTOK*DH;
    __shared__ float As[16][132];
    __shared__ float Bs[16][68];
    int tid = threadIdx.x;
    int tx = tid & 15, ty = tid >> 4;
    int i0 = by*128;
    float acc[8][4] = {};
    int kend = (by+1)*128;
    for (int k0 = 0; k0 < kend; k0 += 16) {
        LOAD_TF(As, P, i0, k0, NTOK);
        {
            int r = tid >> 4, c4 = tid & 15;
            *(float4*)&Bs[r][c4*4] = *(const float4*)&V[(size_t)(k0+r)*DH + c4*4];
        }
        __syncthreads();
        #pragma unroll
        for (int kk = 0; kk < 16; kk++) {
            float a[8], bb[4];
            *(float4*)&a[0] = *(const float4*)&As[kk][ty*8];
            *(float4*)&a[4] = *(const float4*)&As[kk][ty*8+4];
            *(float4*)&bb[0] = *(const float4*)&Bs[kk][tx*4];
            #pragma unroll
            for (int i = 0; i < 8; i++)
                #pragma unroll
                for (int j = 0; j < 4; j++)
                    acc[i][j] += a[i]*bb[j];
        }
        __syncthreads();
    }
    #pragma unroll
    for (int u = 0; u < 8; u++) {
        int i = i0 + ty*8 + u;
        size_t row = (size_t)(b*NTOK + i)*DIMM + h*DH;
        #pragma unroll
        for (int v = 0; v < 4; v += 2) {
            int d = tx*4 + v;
            __nv_bfloat16 h0, l0, h1, l1;
            split_bf16(acc[u][v],   h0, l0);
            split_bf16(acc[u][v+1], h1, l1);
            __nv_bfloat162 hp; hp.x = h0; hp.y = h1;
            __nv_bfloat162 lp; lp.x = l0; lp.y = l1;
            *(__nv_bfloat162*)&g_ohh[row + d] = hp;
            *(__nv_bfloat162*)&g_ohl[row + d] = lp;
        }
    }
}

// =====================================================================
// k_outproj_mma: [2048,512] @ w_out via split mma
// =====================================================================
__global__ __launch_bounds__(256) void k_outproj_mma(float* __restrict__ Out)
{
    const __nv_bfloat16* Wth = g_wth + (size_t)6*DIMM*DIMM;
    const __nv_bfloat16* Wtl = g_wtl + (size_t)6*DIMM*DIMM;
    __shared__ __align__(16) uint16_t sAh[128*ST], sAl[128*ST], sBh[128*ST], sBl[128*ST];
    int tid = threadIdx.x, lane = tid & 31, wid = tid >> 5;
    int wm = wid >> 2, wn = wid & 3;
    int m0 = blockIdx.y*128, n0 = blockIdx.x*128;
    float acc[4][4][4] = {};
    for (int k0 = 0; k0 < DIMM; k0 += 32) {
        ld_tile(sAh, g_ohh, m0, k0, DIMM);
        ld_tile(sAl, g_ohl, m0, k0, DIMM);
        ld_tile(sBh, Wth,  n0, k0, DIMM);
        ld_tile(sBl, Wtl,  n0, k0, DIMM);
        __syncthreads();
        mma_chunk((const uint32_t*)sAh, (const uint32_t*)sAl,
                  (const uint32_t*)sBh, (const uint32_t*)sBl, acc, wm, wn, lane);
        __syncthreads();
    }
    int g = lane >> 2, q = lane & 3;
    #pragma unroll
    for (int mi = 0; mi < 4; mi++) {
        #pragma unroll
        for (int ni = 0; ni < 4; ni++) {
            int nn = n0 + wn*32 + ni*8 + q*2;
            #pragma unroll
            for (int rr = 0; rr < 2; rr++) {
                int m = m0 + wm*64 + mi*16 + g + rr*8;
                *(float2*)&Out[(size_t)m*DIMM + nn] =
                    make_float2(acc[mi][ni][rr*2+0], acc[mi][ni][rr*2+1]);
            }
        }
    }
}

extern "C" void kernel_launch(void* const* d_in, const int* in_sizes, int n_in,
                              void* d_out, int out_size)
{
    const float* x   = (const float*)d_in[0];
    const float* wqu = (const float*)d_in[1];
    const float* wku = (const float*)d_in[2];
    const float* wvu = (const float*)d_in[3];
    const float* wqc = (const float*)d_in[4];
    const float* wkc = (const float*)d_in[5];
    const float* wvc = (const float*)d_in[6];
    const float* wout= (const float*)d_in[7];
    float* out = (float*)d_out;

    k_prep_x    <<<1024, 256>>>(x);
    k_prep_w    <<<dim3(16,16,7), dim3(32,8)>>>(wqu, wku, wvu, wqc, wkc, wvc, wout);
    k_proj_mma  <<<dim3(4, 16, 6), 256>>>();
    k_t1sig_mma <<<dim3(8, 8, 32), 256>>>();
    k_su_mma    <<<dim3(8, 8, 16), 256>>>();
    k_softmax   <<<dim3(1024,16),  256>>>();
    k_av        <<<dim3(1, 8, 16), 256>>>();
    k_outproj_mma<<<dim3(4, 16),   256>>>(out);
}

// round 7
// speedup vs baseline: 1.8021x; 1.0979x over previous
#include <cuda_runtime.h>
#include <cuda_bf16.h>
#include <math.h>
#include <stdint.h>

#define NTOK 1024
#define BATCH 2
#define HEADS 8
#define DH 64
#define BHN (BATCH*HEADS)   /* 16 */
#define DIMM 512
#define SCALE 0.125f
#define ST 40               /* smem row stride in bf16 elems */

// ---- scratch ----
__device__ float g_su[(size_t)BHN*NTOK*NTOK];   // pre-softmax scores

// bf16 hi/lo split operands
__device__ __nv_bfloat16 g_xh[2048*DIMM];
__device__ __nv_bfloat16 g_xl[2048*DIMM];
__device__ __nv_bfloat16 g_wth[7*DIMM*DIMM];   // transposed weights [z][n][k]
__device__ __nv_bfloat16 g_wtl[7*DIMM*DIMM];
__device__ __nv_bfloat16 g_t1h[(size_t)BHN*NTOK*NTOK];
__device__ __nv_bfloat16 g_t1l[(size_t)BHN*NTOK*NTOK];
__device__ __nv_bfloat16 g_sgh[(size_t)BHN*NTOK*NTOK];
__device__ __nv_bfloat16 g_sgl[(size_t)BHN*NTOK*NTOK];
__device__ __nv_bfloat16 g_ph[(size_t)BHN*NTOK*NTOK];   // probs split
__device__ __nv_bfloat16 g_pl[(size_t)BHN*NTOK*NTOK];
__device__ __nv_bfloat16 g_quh[BHN*NTOK*DH];   // SCALE * q_u
__device__ __nv_bfloat16 g_qul[BHN*NTOK*DH];
__device__ __nv_bfloat16 g_kuh[BHN*NTOK*DH];
__device__ __nv_bfloat16 g_kul[BHN*NTOK*DH];
__device__ __nv_bfloat16 g_vuh[BHN*NTOK*DH];
__device__ __nv_bfloat16 g_vul[BHN*NTOK*DH];
__device__ __nv_bfloat16 g_qch[BHN*NTOK*DH];   // SCALE * q_c
__device__ __nv_bfloat16 g_qcl[BHN*NTOK*DH];
__device__ __nv_bfloat16 g_kch[BHN*NTOK*DH];
__device__ __nv_bfloat16 g_kcl[BHN*NTOK*DH];
__device__ __nv_bfloat16 g_vch[BHN*DH*NTOK];   // v_c TRANSPOSED [bh][d][tok]
__device__ __nv_bfloat16 g_vcl[BHN*DH*NTOK];
__device__ __nv_bfloat16 g_ohh[2048*DIMM];     // attn@v_c, [m][h*64+d] split
__device__ __nv_bfloat16 g_ohl[2048*DIMM];

// =====================================================================
// mma.sync bf16 split helpers
// =====================================================================
#define MMA_BF16(c, a0,a1,a2,a3, b0,b1)                                  \
    asm volatile("mma.sync.aligned.m16n8k16.row.col.f32.bf16.bf16.f32 "  \
        "{%0,%1,%2,%3}, {%4,%5,%6,%7}, {%8,%9}, {%0,%1,%2,%3};"          \
        : "+f"((c)[0]), "+f"((c)[1]), "+f"((c)[2]), "+f"((c)[3])         \
        : "r"(a0), "r"(a1), "r"(a2), "r"(a3), "r"(b0), "r"(b1))

__device__ __forceinline__ void ld_tile(uint16_t* sm, const __nv_bfloat16* g,
                                        int row0, int k0, int ldg)
{
    int r = threadIdx.x >> 1, h = threadIdx.x & 1;
    const int4* src = (const int4*)(g + (size_t)(row0 + r)*ldg + k0 + h*16);
    int4 v0 = src[0], v1 = src[1];
    int4* dst = (int4*)(sm + r*ST + h*16);
    dst[0] = v0; dst[1] = v1;
}

// 64-row variant (first 128 threads)
__device__ __forceinline__ void ld_tile64(uint16_t* sm, const __nv_bfloat16* g,
                                          int row0, int k0, int ldg)
{
    if (threadIdx.x < 128) {
        int r = threadIdx.x >> 1, h = threadIdx.x & 1;
        const int4* src = (const int4*)(g + (size_t)(row0 + r)*ldg + k0 + h*16);
        int4 v0 = src[0], v1 = src[1];
        int4* dst = (int4*)(sm + r*ST + h*16);
        dst[0] = v0; dst[1] = v1;
    }
}

__device__ __forceinline__ void mma_chunk(
    const uint32_t* Ah, const uint32_t* Al,
    const uint32_t* Bh, const uint32_t* Bl,
    float acc[4][4][4], int wm, int wn, int lane)
{
    int g = lane >> 2, q = lane & 3;
    #pragma unroll
    for (int ks = 0; ks < 2; ks++) {
        int kq = ks*16 + q*2;
        uint32_t bh[4][2], bl[4][2];
        #pragma unroll
        for (int ni = 0; ni < 4; ni++) {
            int nr = wn*32 + ni*8 + g;
            int base = (nr*ST + kq) >> 1;
            bh[ni][0] = Bh[base]; bh[ni][1] = Bh[base + 4];
            bl[ni][0] = Bl[base]; bl[ni][1] = Bl[base + 4];
        }
        #pragma unroll
        for (int mi = 0; mi < 4; mi++) {
            int r0 = wm*64 + mi*16 + g;
            int ba  = (r0*ST + kq) >> 1;
            int ba8 = ((r0+8)*ST + kq) >> 1;
            uint32_t ah0 = Ah[ba], ah1 = Ah[ba8], ah2 = Ah[ba+4], ah3 = Ah[ba8+4];
            uint32_t al0 = Al[ba], al1 = Al[ba8], al2 = Al[ba+4], al3 = Al[ba8+4];
            #pragma unroll
            for (int ni = 0; ni < 4; ni++) {
                MMA_BF16(acc[mi][ni], ah0,ah1,ah2,ah3, bh[ni][0], bh[ni][1]);
                MMA_BF16(acc[mi][ni], ah0,ah1,ah2,ah3, bl[ni][0], bl[ni][1]);
                MMA_BF16(acc[mi][ni], al0,al1,al2,al3, bh[ni][0], bh[ni][1]);
            }
        }
    }
}

__device__ __forceinline__ void split_bf16(float v, __nv_bfloat16& h, __nv_bfloat16& l)
{
    h = __float2bfloat16(v);
    l = __float2bfloat16(v - __bfloat162float(h));
}

// =====================================================================
// prep kernels
// =====================================================================
__global__ __launch_bounds__(256) void k_prep_x(const float* __restrict__ X)
{
    int idx = (blockIdx.x*256 + threadIdx.x)*4;
    float4 v = *(const float4*)&X[idx];
    float vv[4] = {v.x, v.y, v.z, v.w};
    #pragma unroll
    for (int i = 0; i < 4; i++) {
        __nv_bfloat16 h, l; split_bf16(vv[i], h, l);
        g_xh[idx+i] = h; g_xl[idx+i] = l;
    }
}

__global__ void k_prep_w(
    const float* __restrict__ w0, const float* __restrict__ w1,
    const float* __restrict__ w2, const float* __restrict__ w3,
    const float* __restrict__ w4, const float* __restrict__ w5,
    const float* __restrict__ w6)
{
    const float* W;
    switch (blockIdx.z) {
        case 0: W = w0; break; case 1: W = w1; break; case 2: W = w2; break;
        case 3: W = w3; break; case 4: W = w4; break; case 5: W = w5; break;
        default: W = w6; break;
    }
    __shared__ float t[32][33];
    int tx = threadIdx.x, ty = threadIdx.y;   // (32, 8)
    int k0 = blockIdx.y*32, n0 = blockIdx.x*32;
    #pragma unroll
    for (int i = 0; i < 4; i++)
        t[ty + i*8][tx] = W[(size_t)(k0 + ty + i*8)*DIMM + n0 + tx];
    __syncthreads();
    size_t zoff = (size_t)blockIdx.z * DIMM * DIMM;
    #pragma unroll
    for (int i = 0; i < 4; i++) {
        float v = t[tx][ty + i*8];
        __nv_bfloat16 h, l; split_bf16(v, h, l);
        size_t o = zoff + (size_t)(n0 + ty + i*8)*DIMM + k0 + tx;
        g_wth[o] = h; g_wtl[o] = l;
    }
}

// =====================================================================
// k_proj_mma: 6 projections -> bf16 splits (v_c transposed)
// =====================================================================
__global__ __launch_bounds__(256,2) void k_proj_mma()
{
    int z = blockIdx.z;
    __nv_bfloat16 *Oh = 0, *Ol = 0;
    float sc = 1.f;
    switch (z) {
        case 0: Oh = g_quh; Ol = g_qul; sc = SCALE; break;
        case 1: Oh = g_kuh; Ol = g_kul; break;
        case 2: Oh = g_vuh; Ol = g_vul; break;
        case 3: Oh = g_qch; Ol = g_qcl; sc = SCALE; break;
        case 4: Oh = g_kch; Ol = g_kcl; break;
        default: break;  // z==5 -> transposed g_vch/g_vcl
    }
    const __nv_bfloat16* Wth = g_wth + (size_t)z*DIMM*DIMM;
    const __nv_bfloat16* Wtl = g_wtl + (size_t)z*DIMM*DIMM;
    __shared__ __align__(16) uint16_t sAh[128*ST], sAl[128*ST], sBh[128*ST], sBl[128*ST];
    int tid = threadIdx.x, lane = tid & 31, wid = tid >> 5;
    int wm = wid >> 2, wn = wid & 3;
    int m0 = blockIdx.y*128, n0 = blockIdx.x*128;
    float acc[4][4][4] = {};
    for (int k0 = 0; k0 < DIMM; k0 += 32) {
        ld_tile(sAh, g_xh, m0, k0, DIMM);
        ld_tile(sAl, g_xl, m0, k0, DIMM);
        ld_tile(sBh, Wth,  n0, k0, DIMM);
        ld_tile(sBl, Wtl,  n0, k0, DIMM);
        __syncthreads();
        mma_chunk((const uint32_t*)sAh, (const uint32_t*)sAl,
                  (const uint32_t*)sBh, (const uint32_t*)sBl, acc, wm, wn, lane);
        __syncthreads();
    }
    int g = lane >> 2, q = lane & 3;
    #pragma unroll
    for (int mi = 0; mi < 4; mi++) {
        #pragma unroll
        for (int ni = 0; ni < 4; ni++) {
            int col = n0 + wn*32 + ni*8 + q*2;
            int h = col >> 6, dd = col & 63;
            #pragma unroll
            for (int rr = 0; rr < 2; rr++) {
                int m = m0 + wm*64 + mi*16 + g + rr*8;
                int b = m >> 10, tok = m & 1023;
                float v0 = acc[mi][ni][rr*2+0], v1 = acc[mi][ni][rr*2+1];
                if (z == 5) {
                    size_t tb = ((size_t)(b*HEADS + h)*DH + dd)*NTOK + tok;
                    __nv_bfloat16 h0, l0, h1, l1;
                    split_bf16(v0, h0, l0); split_bf16(v1, h1, l1);
                    g_vch[tb] = h0;        g_vcl[tb] = l0;
                    g_vch[tb + NTOK] = h1; g_vcl[tb + NTOK] = l1;
                } else {
                    size_t oidx = ((size_t)(b*HEADS + h)*NTOK + tok)*DH + dd;
                    float s0 = v0*sc, s1 = v1*sc;
                    __nv_bfloat16 h0, l0, h1, l1;
                    split_bf16(s0, h0, l0); split_bf16(s1, h1, l1);
                    __nv_bfloat162 hp; hp.x = h0; hp.y = h1;
                    __nv_bfloat162 lp; lp.x = l0; lp.y = l1;
                    *(__nv_bfloat162*)&Oh[oidx] = hp;
                    *(__nv_bfloat162*)&Ol[oidx] = lp;
                }
            }
        }
    }
}

// =====================================================================
// k_t1sig_mma: term1 / sig via split mma, K=64
// =====================================================================
__global__ __launch_bounds__(256,2) void k_t1sig_mma()
{
    int which = blockIdx.z >> 4;
    int bh    = blockIdx.z & 15;
    int bx = blockIdx.x, by = blockIdx.y;
    if (which == 0) { if (bx > by) return; }
    else            { if (bx < by) return; }
    size_t voff = (size_t)bh*NTOK*DH;
    const __nv_bfloat16* Ah_g = (which == 0 ? g_qch : g_quh) + voff;
    const __nv_bfloat16* Al_g = (which == 0 ? g_qcl : g_qul) + voff;
    const __nv_bfloat16* Bh_g = (which == 0 ? g_vuh : g_kuh) + voff;
    const __nv_bfloat16* Bl_g = (which == 0 ? g_vul : g_kul) + voff;
    __nv_bfloat16* Oh = (which == 0 ? g_t1h : g_sgh) + (size_t)bh*NTOK*NTOK;
    __nv_bfloat16* Ol = (which == 0 ? g_t1l : g_sgl) + (size_t)bh*NTOK*NTOK;

    __shared__ __align__(16) uint16_t sAh[128*ST], sAl[128*ST], sBh[128*ST], sBl[128*ST];
    int tid = threadIdx.x, lane = tid & 31, wid = tid >> 5;
    int wm = wid >> 2, wn = wid & 3;
    int i0 = by*128, j0b = bx*128;
    float acc[4][4][4] = {};
    for (int k0 = 0; k0 < DH; k0 += 32) {
        ld_tile(sAh, Ah_g, i0,  k0, DH);
        ld_tile(sAl, Al_g, i0,  k0, DH);
        ld_tile(sBh, Bh_g, j0b, k0, DH);
        ld_tile(sBl, Bl_g, j0b, k0, DH);
        __syncthreads();
        mma_chunk((const uint32_t*)sAh, (const uint32_t*)sAl,
                  (const uint32_t*)sBh, (const uint32_t*)sBl, acc, wm, wn, lane);
        __syncthreads();
    }
    int g = lane >> 2, q = lane & 3;
    #pragma unroll
    for (int mi = 0; mi < 4; mi++) {
        #pragma unroll
        for (int ni = 0; ni < 4; ni++) {
            int j = j0b + wn*32 + ni*8 + q*2;
            #pragma unroll
            for (int rr = 0; rr < 2; rr++) {
                int i = i0 + wm*64 + mi*16 + g + rr*8;
                float s0 = acc[mi][ni][rr*2+0], s1 = acc[mi][ni][rr*2+1];
                float o0, o1;
                if (which == 0) {
                    o0 = (j   <= i) ? s0 : 0.f;
                    o1 = (j+1 <= i) ? s1 : 0.f;
                } else {
                    o0 = (j   > i) ? 1.f/(1.f + __expf(-s0)) : 0.f;
                    o1 = (j+1 > i) ? 1.f/(1.f + __expf(-s1)) : 0.f;
                }
                __nv_bfloat16 h0, l0, h1, l1;
                split_bf16(o0, h0, l0); split_bf16(o1, h1, l1);
                __nv_bfloat162 hp; hp.x = h0; hp.y = h1;
                __nv_bfloat162 lp; lp.x = l0; lp.y = l1;
                size_t idx = (size_t)i*NTOK + j;
                *(__nv_bfloat162*)&Oh[idx] = hp;
                *(__nv_bfloat162*)&Ol[idx] = lp;
            }
        }
    }
}

// =====================================================================
// k_su_mma: fused scores
// =====================================================================
__global__ __launch_bounds__(256,2) void k_su_mma()
{
    int bx = blockIdx.x, by = blockIdx.y, bh = blockIdx.z;
    if (bx > by) return;
    const __nv_bfloat16* T1h = g_t1h + (size_t)bh*NTOK*NTOK;
    const __nv_bfloat16* T1l = g_t1l + (size_t)bh*NTOK*NTOK;
    const __nv_bfloat16* SGh = g_sgh + (size_t)bh*NTOK*NTOK;
    const __nv_bfloat16* SGl = g_sgl + (size_t)bh*NTOK*NTOK;
    const __nv_bfloat16* Qh = g_qch + (size_t)bh*NTOK*DH;
    const __nv_bfloat16* Ql = g_qcl + (size_t)bh*NTOK*DH;
    const __nv_bfloat16* Kh = g_kch + (size_t)bh*NTOK*DH;
    const __nv_bfloat16* Kl = g_kcl + (size_t)bh*NTOK*DH;
    float* S = g_su + (size_t)bh*NTOK*NTOK;

    __shared__ __align__(16) uint16_t sAh[128*ST], sAl[128*ST], sBh[128*ST], sBl[128*ST];
    int tid = threadIdx.x, lane = tid & 31, wid = tid >> 5;
    int wm = wid >> 2, wn = wid & 3;
    int i0 = by*128, kx0 = bx*128;
    float acc[4][4][4] = {};

    int jend = (by+1)*128;
    for (int j0 = bx*128; j0 < jend; j0 += 32) {
        ld_tile(sAh, T1h, i0,  j0, NTOK);
        ld_tile(sAl, T1l, i0,  j0, NTOK);
        ld_tile(sBh, SGh, kx0, j0, NTOK);
        ld_tile(sBl, SGl, kx0, j0, NTOK);
        __syncthreads();
        mma_chunk((const uint32_t*)sAh, (const uint32_t*)sAl,
                  (const uint32_t*)sBh, (const uint32_t*)sBl, acc, wm, wn, lane);
        __syncthreads();
    }
    #pragma unroll
    for (int mi = 0; mi < 4; mi++)
        #pragma unroll
        for (int ni = 0; ni < 4; ni++)
            #pragma unroll
            for (int e = 0; e < 4; e++) {
                float su = acc[mi][ni][e];
                acc[mi][ni][e] = -su / (1.f + __expf(-su));
            }
    for (int k0 = 0; k0 < DH; k0 += 32) {
        ld_tile(sAh, Qh, i0,  k0, DH);
        ld_tile(sAl, Ql, i0,  k0, DH);
        ld_tile(sBh, Kh, kx0, k0, DH);
        ld_tile(sBl, Kl, kx0, k0, DH);
        __syncthreads();
        mma_chunk((const uint32_t*)sAh, (const uint32_t*)sAl,
                  (const uint32_t*)sBh, (const uint32_t*)sBl, acc, wm, wn, lane);
        __syncthreads();
    }
    int g = lane >> 2, q = lane & 3;
    #pragma unroll
    for (int mi = 0; mi < 4; mi++) {
        #pragma unroll
        for (int ni = 0; ni < 4; ni++) {
            int k = kx0 + wn*32 + ni*8 + q*2;
            #pragma unroll
            for (int rr = 0; rr < 2; rr++) {
                int i = i0 + wm*64 + mi*16 + g + rr*8;
                float v0 = (k   <= i) ? acc[mi][ni][rr*2+0] : -1e30f;
                float v1 = (k+1 <= i) ? acc[mi][ni][rr*2+1] : -1e30f;
                *(float2*)&S[(size_t)i*NTOK + k] = make_float2(v0, v1);
            }
        }
    }
}

// =====================================================================
// k_softmax: reads fp32 scores, writes bf16 split probs
// =====================================================================
__global__ __launch_bounds__(256) void k_softmax()
{
    int i  = blockIdx.x;
    int bh = blockIdx.y;
    size_t roff = (size_t)bh*NTOK*NTOK + (size_t)i*NTOK;
    const float* S = g_su + roff;
    __nv_bfloat16* Ph = g_ph + roff;
    __nv_bfloat16* Pl = g_pl + roff;
    int L = i + 1;
    int wlen = ((i >> 7) + 1) << 7;
    int tid = threadIdx.x;
    __shared__ float red[256];
    float x[4];
    float mx = -1e30f;
    #pragma unroll
    for (int l = 0; l < 4; l++) {
        int k = tid + l*256;
        x[l] = (k < L) ? S[k] : -1e30f;
        mx = fmaxf(mx, x[l]);
    }
    red[tid] = mx; __syncthreads();
    for (int s = 128; s > 0; s >>= 1) {
        if (tid < s) red[tid] = fmaxf(red[tid], red[tid+s]);
        __syncthreads();
    }
    mx = red[0]; __syncthreads();
    float sum = 0.f;
    #pragma unroll
    for (int l = 0; l < 4; l++) {
        int k = tid + l*256;
        x[l] = (k < L) ? __expf(x[l] - mx) : 0.f;
        sum += x[l];
    }
    red[tid] = sum; __syncthreads();
    for (int s = 128; s > 0; s >>= 1) {
        if (tid < s) red[tid] += red[tid+s];
        __syncthreads();
    }
    float inv = 1.f / red[0];
    #pragma unroll
    for (int l = 0; l < 4; l++) {
        int k = tid + l*256;
        if (k < wlen) {
            float p = x[l]*inv;
            __nv_bfloat16 h, lo; split_bf16(p, h, lo);
            Ph[k] = h; Pl[k] = lo;
        }
    }
}

// =====================================================================
// k_av_mma: O = P @ V via split mma. Block 128x64, warps 4x2.
// B = V^T [d][tok] splits. Epilogue -> g_ohh/g_ohl.
// =====================================================================
__global__ __launch_bounds__(256,2) void k_av_mma()
{
    int by = blockIdx.x, bh = blockIdx.y;
    int b = bh >> 3, h = bh & 7;
    const __nv_bfloat16* Ph = g_ph + (size_t)bh*NTOK*NTOK;
    const __nv_bfloat16* Pl = g_pl + (size_t)bh*NTOK*NTOK;
    const __nv_bfloat16* Vh = g_vch + (size_t)bh*DH*NTOK;
    const __nv_bfloat16* Vl = g_vcl + (size_t)bh*DH*NTOK;

    __shared__ __align__(16) uint16_t sAh[128*ST], sAl[128*ST], sBh[64*ST], sBl[64*ST];
    int tid = threadIdx.x, lane = tid & 31, wid = tid >> 5;
    int wm = wid >> 1, wn = wid & 1;   // 4 x 2
    int i0 = by*128;
    float acc[2][4][4] = {};
    int kend = (by+1)*128;
    for (int k0 = 0; k0 < kend; k0 += 32) {
        ld_tile(sAh, Ph, i0, k0, NTOK);
        ld_tile(sAl, Pl, i0, k0, NTOK);
        ld_tile64(sBh, Vh, 0, k0, NTOK);
        ld_tile64(sBl, Vl, 0, k0, NTOK);
        __syncthreads();
        {
            const uint32_t* Ah = (const uint32_t*)sAh;
            const uint32_t* Al = (const uint32_t*)sAl;
            const uint32_t* Bh = (const uint32_t*)sBh;
            const uint32_t* Bl = (const uint32_t*)sBl;
            int g = lane >> 2, q = lane & 3;
            #pragma unroll
            for (int ks = 0; ks < 2; ks++) {
                int kq = ks*16 + q*2;
                uint32_t bhr[4][2], blr[4][2];
                #pragma unroll
                for (int ni = 0; ni < 4; ni++) {
                    int nr = wn*32 + ni*8 + g;
                    int base = (nr*ST + kq) >> 1;
                    bhr[ni][0] = Bh[base]; bhr[ni][1] = Bh[base + 4];
                    blr[ni][0] = Bl[base]; blr[ni][1] = Bl[base + 4];
                }
                #pragma unroll
                for (int mi = 0; mi < 2; mi++) {
                    int r0 = wm*32 + mi*16 + g;
                    int ba  = (r0*ST + kq) >> 1;
                    int ba8 = ((r0+8)*ST + kq) >> 1;
                    uint32_t ah0 = Ah[ba], ah1 = Ah[ba8], ah2 = Ah[ba+4], ah3 = Ah[ba8+4];
                    uint32_t al0 = Al[ba], al1 = Al[ba8], al2 = Al[ba+4], al3 = Al[ba8+4];
                    #pragma unroll
                    for (int ni = 0; ni < 4; ni++) {
                        MMA_BF16(acc[mi][ni], ah0,ah1,ah2,ah3, bhr[ni][0], bhr[ni][1]);
                        MMA_BF16(acc[mi][ni], ah0,ah1,ah2,ah3, blr[ni][0], blr[ni][1]);
                        MMA_BF16(acc[mi][ni], al0,al1,al2,al3, bhr[ni][0], bhr[ni][1]);
                    }
                }
            }
        }
        __syncthreads();
    }
    int g = lane >> 2, q = lane & 3;
    #pragma unroll
    for (int mi = 0; mi < 2; mi++) {
        #pragma unroll
        for (int ni = 0; ni < 4; ni++) {
            int d = wn*32 + ni*8 + q*2;
            #pragma unroll
            for (int rr = 0; rr < 2; rr++) {
                int i = i0 + wm*32 + mi*16 + g + rr*8;
                size_t row = (size_t)(b*NTOK + i)*DIMM + h*DH + d;
                __nv_bfloat16 h0, l0, h1, l1;
                split_bf16(acc[mi][ni][rr*2+0], h0, l0);
                split_bf16(acc[mi][ni][rr*2+1], h1, l1);
                __nv_bfloat162 hp; hp.x = h0; hp.y = h1;
                __nv_bfloat162 lp; lp.x = l0; lp.y = l1;
                *(__nv_bfloat162*)&g_ohh[row] = hp;
                *(__nv_bfloat162*)&g_ohl[row] = lp;
            }
        }
    }
}

// =====================================================================
// k_outproj_mma: [2048,512] @ w_out via split mma
// =====================================================================
__global__ __launch_bounds__(256,2) void k_outproj_mma(float* __restrict__ Out)
{
    const __nv_bfloat16* Wth = g_wth + (size_t)6*DIMM*DIMM;
    const __nv_bfloat16* Wtl = g_wtl + (size_t)6*DIMM*DIMM;
    __shared__ __align__(16) uint16_t sAh[128*ST], sAl[128*ST], sBh[128*ST], sBl[128*ST];
    int tid = threadIdx.x, lane = tid & 31, wid = tid >> 5;
    int wm = wid >> 2, wn = wid & 3;
    int m0 = blockIdx.y*128, n0 = blockIdx.x*128;
    float acc[4][4][4] = {};
    for (int k0 = 0; k0 < DIMM; k0 += 32) {
        ld_tile(sAh, g_ohh, m0, k0, DIMM);
        ld_tile(sAl, g_ohl, m0, k0, DIMM);
        ld_tile(sBh, Wth,  n0, k0, DIMM);
        ld_tile(sBl, Wtl,  n0, k0, DIMM);
        __syncthreads();
        mma_chunk((const uint32_t*)sAh, (const uint32_t*)sAl,
                  (const uint32_t*)sBh, (const uint32_t*)sBl, acc, wm, wn, lane);
        __syncthreads();
    }
    int g = lane >> 2, q = lane & 3;
    #pragma unroll
    for (int mi = 0; mi < 4; mi++) {
        #pragma unroll
        for (int ni = 0; ni < 4; ni++) {
            int nn = n0 + wn*32 + ni*8 + q*2;
            #pragma unroll
            for (int rr = 0; rr < 2; rr++) {
                int m = m0 + wm*64 + mi*16 + g + rr*8;
                *(float2*)&Out[(size_t)m*DIMM + nn] =
                    make_float2(acc[mi][ni][rr*2+0], acc[mi][ni][rr*2+1]);
            }
        }
    }
}

extern "C" void kernel_launch(void* const* d_in, const int* in_sizes, int n_in,
                              void* d_out, int out_size)
{
    const float* x   = (const float*)d_in[0];
    const float* wqu = (const float*)d_in[1];
    const float* wku = (const float*)d_in[2];
    const float* wvu = (const float*)d_in[3];
    const float* wqc = (const float*)d_in[4];
    const float* wkc = (const float*)d_in[5];
    const float* wvc = (const float*)d_in[6];
    const float* wout= (const float*)d_in[7];
    float* out = (float*)d_out;

    k_prep_x    <<<1024, 256>>>(x);
    k_prep_w    <<<dim3(16,16,7), dim3(32,8)>>>(wqu, wku, wvu, wqc, wkc, wvc, wout);
    k_proj_mma  <<<dim3(4, 16, 6), 256>>>();
    k_t1sig_mma <<<dim3(8, 8, 32), 256>>>();
    k_su_mma    <<<dim3(8, 8, 16), 256>>>();
    k_softmax   <<<dim3(1024,16),  256>>>();
    k_av_mma    <<<dim3(8, 16),    256>>>();
    k_outproj_mma<<<dim3(4, 16),   256>>>(out);
}

// round 8
// speedup vs baseline: 2.1311x; 1.1825x over previous
#include <cuda_runtime.h>
#include <cuda_bf16.h>
#include <math.h>
#include <stdint.h>

#define NTOK 1024
#define BATCH 2
#define HEADS 8
#define DH 64
#define BHN (BATCH*HEADS)   /* 16 */
#define DIMM 512
#define SCALE 0.125f
#define ST 40               /* smem row stride in bf16 elems (80B = 16B-aligned, conflict-free) */

// ---- scratch ----
__device__ float g_su[(size_t)BHN*NTOK*NTOK];   // pre-softmax scores

// bf16 hi/lo split operands
__device__ __nv_bfloat16 g_xh[2048*DIMM];
__device__ __nv_bfloat16 g_xl[2048*DIMM];
__device__ __nv_bfloat16 g_wth[7*DIMM*DIMM];   // transposed weights [z][n][k]
__device__ __nv_bfloat16 g_wtl[7*DIMM*DIMM];
__device__ __nv_bfloat16 g_t1h[(size_t)BHN*NTOK*NTOK];
__device__ __nv_bfloat16 g_t1l[(size_t)BHN*NTOK*NTOK];
__device__ __nv_bfloat16 g_sgh[(size_t)BHN*NTOK*NTOK];
__device__ __nv_bfloat16 g_sgl[(size_t)BHN*NTOK*NTOK];
__device__ __nv_bfloat16 g_ph[(size_t)BHN*NTOK*NTOK];   // probs split
__device__ __nv_bfloat16 g_pl[(size_t)BHN*NTOK*NTOK];
__device__ __nv_bfloat16 g_quh[BHN*NTOK*DH];   // SCALE * q_u
__device__ __nv_bfloat16 g_qul[BHN*NTOK*DH];
__device__ __nv_bfloat16 g_kuh[BHN*NTOK*DH];
__device__ __nv_bfloat16 g_kul[BHN*NTOK*DH];
__device__ __nv_bfloat16 g_vuh[BHN*NTOK*DH];
__device__ __nv_bfloat16 g_vul[BHN*NTOK*DH];
__device__ __nv_bfloat16 g_qch[BHN*NTOK*DH];   // SCALE * q_c
__device__ __nv_bfloat16 g_qcl[BHN*NTOK*DH];
__device__ __nv_bfloat16 g_kch[BHN*NTOK*DH];
__device__ __nv_bfloat16 g_kcl[BHN*NTOK*DH];
__device__ __nv_bfloat16 g_vch[BHN*DH*NTOK];   // v_c TRANSPOSED [bh][d][tok]
__device__ __nv_bfloat16 g_vcl[BHN*DH*NTOK];
__device__ __nv_bfloat16 g_ohh[2048*DIMM];     // attn@v_c, [m][h*64+d] split
__device__ __nv_bfloat16 g_ohl[2048*DIMM];

// =====================================================================
// helpers
// =====================================================================
#define MMA_BF16(c, a0,a1,a2,a3, b0,b1)                                  \
    asm volatile("mma.sync.aligned.m16n8k16.row.col.f32.bf16.bf16.f32 "  \
        "{%0,%1,%2,%3}, {%4,%5,%6,%7}, {%8,%9}, {%0,%1,%2,%3};"          \
        : "+f"((c)[0]), "+f"((c)[1]), "+f"((c)[2]), "+f"((c)[3])         \
        : "r"(a0), "r"(a1), "r"(a2), "r"(a3), "r"(b0), "r"(b1))

#define LDMX4(r0,r1,r2,r3, addr)                                         \
    asm volatile("ldmatrix.sync.aligned.m8n8.x4.shared.b16 {%0,%1,%2,%3}, [%4];" \
        : "=r"(r0),"=r"(r1),"=r"(r2),"=r"(r3) : "r"(addr))

__device__ __forceinline__ uint32_t smem_u32(const void* p) {
    uint32_t a;
    asm("{ .reg .u64 t; cvta.to.shared.u64 t, %1; cvt.u32.u64 %0, t; }"
        : "=r"(a) : "l"(p));
    return a;
}

// packed hi/lo split of a pair: hp/lp hold {lo16=v0, hi16=v1}
__device__ __forceinline__ void split2(float v0, float v1, uint32_t& hp, uint32_t& lp)
{
    asm("cvt.rn.bf16x2.f32 %0, %1, %2;" : "=r"(hp) : "f"(v1), "f"(v0));
    float h0 = __uint_as_float(hp << 16);
    float h1 = __uint_as_float(hp & 0xFFFF0000u);
    asm("cvt.rn.bf16x2.f32 %0, %1, %2;" : "=r"(lp) : "f"(v1 - h1), "f"(v0 - h0));
}

__device__ __forceinline__ void split_bf16(float v, __nv_bfloat16& h, __nv_bfloat16& l)
{
    h = __float2bfloat16(v);
    l = __float2bfloat16(v - __bfloat162float(h));
}

// load 128 rows x 32 k bf16 tile into smem (row-major, stride ST)
__device__ __forceinline__ void ld_tile(uint16_t* sm, const __nv_bfloat16* g,
                                        int row0, int k0, int ldg)
{
    int r = threadIdx.x >> 1, h = threadIdx.x & 1;
    const int4* src = (const int4*)(g + (size_t)(row0 + r)*ldg + k0 + h*16);
    int4 v0 = src[0], v1 = src[1];
    int4* dst = (int4*)(sm + r*ST + h*16);
    dst[0] = v0; dst[1] = v1;
}

__device__ __forceinline__ void ld_tile64(uint16_t* sm, const __nv_bfloat16* g,
                                          int row0, int k0, int ldg)
{
    if (threadIdx.x < 128) {
        int r = threadIdx.x >> 1, h = threadIdx.x & 1;
        const int4* src = (const int4*)(g + (size_t)(row0 + r)*ldg + k0 + h*16);
        int4 v0 = src[0], v1 = src[1];
        int4* dst = (int4*)(sm + r*ST + h*16);
        dst[0] = v0; dst[1] = v1;
    }
}

// =====================================================================
// ldmatrix-based 32-k chunk of the split GEMM.
// MI m-tiles of 16 rows per warp; 4 n-tiles of 8 per warp (32 cols).
// =====================================================================
template<int MI>
__device__ __forceinline__ void mma_chunk_ldm(
    uint32_t aAh, uint32_t aAl, uint32_t aBh, uint32_t aBl,
    float (&acc)[MI][4][4], int wm, int wn, int lane)
{
    int lr = lane & 15;
    int lc = (lane >> 4) << 3;         // 0 or 8 (elems)
    int bl_ = lane & 7;
    int bn = ((lane >> 4) & 1) << 3;   // lanes16-31 -> +8 n rows
    int bk = ((lane >> 3) & 1) << 3;   // lanes 8-15,24-31 -> +8 k
    uint32_t aoff = (uint32_t)(((wm*(MI*16) + lr)*ST + lc) * 2);
    uint32_t boff = (uint32_t)(((wn*32 + bn + bl_)*ST + bk) * 2);
    #pragma unroll
    for (int ks = 0; ks < 2; ks++) {
        uint32_t kb = (uint32_t)(ks * 32);   // 16 elems = 32 bytes
        uint32_t bhf[4][2], blf[4][2];
        LDMX4(bhf[0][0], bhf[0][1], bhf[1][0], bhf[1][1], aBh + boff + kb);
        LDMX4(bhf[2][0], bhf[2][1], bhf[3][0], bhf[3][1], aBh + boff + kb + 16*ST*2);
        LDMX4(blf[0][0], blf[0][1], blf[1][0], blf[1][1], aBl + boff + kb);
        LDMX4(blf[2][0], blf[2][1], blf[3][0], blf[3][1], aBl + boff + kb + 16*ST*2);
        #pragma unroll
        for (int mi = 0; mi < MI; mi++) {
            uint32_t ao = aoff + kb + (uint32_t)(mi*16*ST*2);
            uint32_t ah0,ah1,ah2,ah3, al0,al1,al2,al3;
            LDMX4(ah0,ah1,ah2,ah3, aAh + ao);
            LDMX4(al0,al1,al2,al3, aAl + ao);
            #pragma unroll
            for (int ni = 0; ni < 4; ni++) {
                MMA_BF16(acc[mi][ni], ah0,ah1,ah2,ah3, bhf[ni][0], bhf[ni][1]);
                MMA_BF16(acc[mi][ni], ah0,ah1,ah2,ah3, blf[ni][0], blf[ni][1]);
                MMA_BF16(acc[mi][ni], al0,al1,al2,al3, bhf[ni][0], bhf[ni][1]);
            }
        }
    }
}

// =====================================================================
// prep kernels
// =====================================================================
__global__ __launch_bounds__(256) void k_prep_x(const float* __restrict__ X)
{
    int idx = (blockIdx.x*256 + threadIdx.x)*4;
    float4 v = *(const float4*)&X[idx];
    uint32_t h0, l0, h1, l1;
    split2(v.x, v.y, h0, l0);
    split2(v.z, v.w, h1, l1);
    *(uint2*)&g_xh[idx] = make_uint2(h0, h1);
    *(uint2*)&g_xl[idx] = make_uint2(l0, l1);
}

__global__ void k_prep_w(
    const float* __restrict__ w0, const float* __restrict__ w1,
    const float* __restrict__ w2, const float* __restrict__ w3,
    const float* __restrict__ w4, const float* __restrict__ w5,
    const float* __restrict__ w6)
{
    const float* W;
    switch (blockIdx.z) {
        case 0: W = w0; break; case 1: W = w1; break; case 2: W = w2; break;
        case 3: W = w3; break; case 4: W = w4; break; case 5: W = w5; break;
        default: W = w6; break;
    }
    __shared__ float t[32][33];
    int tx = threadIdx.x, ty = threadIdx.y;   // (32, 8)
    int k0 = blockIdx.y*32, n0 = blockIdx.x*32;
    #pragma unroll
    for (int i = 0; i < 4; i++)
        t[ty + i*8][tx] = W[(size_t)(k0 + ty + i*8)*DIMM + n0 + tx];
    __syncthreads();
    size_t zoff = (size_t)blockIdx.z * DIMM * DIMM;
    #pragma unroll
    for (int i = 0; i < 4; i++) {
        float v = t[tx][ty + i*8];
        __nv_bfloat16 h, l; split_bf16(v, h, l);
        size_t o = zoff + (size_t)(n0 + ty + i*8)*DIMM + k0 + tx;
        g_wth[o] = h; g_wtl[o] = l;
    }
}

// =====================================================================
// k_proj_mma: 6 projections -> bf16 splits (v_c transposed)
// =====================================================================
__global__ __launch_bounds__(256,2) void k_proj_mma()
{
    int z = blockIdx.z;
    __nv_bfloat16 *Oh = 0, *Ol = 0;
    float sc = 1.f;
    switch (z) {
        case 0: Oh = g_quh; Ol = g_qul; sc = SCALE; break;
        case 1: Oh = g_kuh; Ol = g_kul; break;
        case 2: Oh = g_vuh; Ol = g_vul; break;
        case 3: Oh = g_qch; Ol = g_qcl; sc = SCALE; break;
        case 4: Oh = g_kch; Ol = g_kcl; break;
        default: break;  // z==5 -> transposed g_vch/g_vcl
    }
    const __nv_bfloat16* Wth = g_wth + (size_t)z*DIMM*DIMM;
    const __nv_bfloat16* Wtl = g_wtl + (size_t)z*DIMM*DIMM;
    __shared__ __align__(16) uint16_t sAh[128*ST], sAl[128*ST], sBh[128*ST], sBl[128*ST];
    uint32_t aAh = smem_u32(sAh), aAl = smem_u32(sAl);
    uint32_t aBh = smem_u32(sBh), aBl = smem_u32(sBl);
    int tid = threadIdx.x, lane = tid & 31, wid = tid >> 5;
    int wm = wid >> 2, wn = wid & 3;
    int m0 = blockIdx.y*128, n0 = blockIdx.x*128;
    float acc[4][4][4] = {};
    for (int k0 = 0; k0 < DIMM; k0 += 32) {
        ld_tile(sAh, g_xh, m0, k0, DIMM);
        ld_tile(sAl, g_xl, m0, k0, DIMM);
        ld_tile(sBh, Wth,  n0, k0, DIMM);
        ld_tile(sBl, Wtl,  n0, k0, DIMM);
        __syncthreads();
        mma_chunk_ldm<4>(aAh, aAl, aBh, aBl, acc, wm, wn, lane);
        __syncthreads();
    }
    int g = lane >> 2, q = lane & 3;
    #pragma unroll
    for (int mi = 0; mi < 4; mi++) {
        #pragma unroll
        for (int ni = 0; ni < 4; ni++) {
            int col = n0 + wn*32 + ni*8 + q*2;
            int h = col >> 6, dd = col & 63;
            #pragma unroll
            for (int rr = 0; rr < 2; rr++) {
                int m = m0 + wm*64 + mi*16 + g + rr*8;
                int b = m >> 10, tok = m & 1023;
                float v0 = acc[mi][ni][rr*2+0], v1 = acc[mi][ni][rr*2+1];
                if (z == 5) {
                    size_t tb = ((size_t)(b*HEADS + h)*DH + dd)*NTOK + tok;
                    __nv_bfloat16 h0, l0, h1, l1;
                    split_bf16(v0, h0, l0); split_bf16(v1, h1, l1);
                    g_vch[tb] = h0;        g_vcl[tb] = l0;
                    g_vch[tb + NTOK] = h1; g_vcl[tb + NTOK] = l1;
                } else {
                    size_t oidx = ((size_t)(b*HEADS + h)*NTOK + tok)*DH + dd;
                    uint32_t hp, lp;
                    split2(v0*sc, v1*sc, hp, lp);
                    *(uint32_t*)&Oh[oidx] = hp;
                    *(uint32_t*)&Ol[oidx] = lp;
                }
            }
        }
    }
}

// =====================================================================
// k_t1sig_mma: term1 / sig via split mma, K=64
// =====================================================================
__global__ __launch_bounds__(256,2) void k_t1sig_mma()
{
    int which = blockIdx.z >> 4;
    int bh    = blockIdx.z & 15;
    int bx = blockIdx.x, by = blockIdx.y;
    if (which == 0) { if (bx > by) return; }
    else            { if (bx < by) return; }
    size_t voff = (size_t)bh*NTOK*DH;
    const __nv_bfloat16* Ah_g = (which == 0 ? g_qch : g_quh) + voff;
    const __nv_bfloat16* Al_g = (which == 0 ? g_qcl : g_qul) + voff;
    const __nv_bfloat16* Bh_g = (which == 0 ? g_vuh : g_kuh) + voff;
    const __nv_bfloat16* Bl_g = (which == 0 ? g_vul : g_kul) + voff;
    __nv_bfloat16* Oh = (which == 0 ? g_t1h : g_sgh) + (size_t)bh*NTOK*NTOK;
    __nv_bfloat16* Ol = (which == 0 ? g_t1l : g_sgl) + (size_t)bh*NTOK*NTOK;

    __shared__ __align__(16) uint16_t sAh[128*ST], sAl[128*ST], sBh[128*ST], sBl[128*ST];
    uint32_t aAh = smem_u32(sAh), aAl = smem_u32(sAl);
    uint32_t aBh = smem_u32(sBh), aBl = smem_u32(sBl);
    int tid = threadIdx.x, lane = tid & 31, wid = tid >> 5;
    int wm = wid >> 2, wn = wid & 3;
    int i0 = by*128, j0b = bx*128;
    float acc[4][4][4] = {};
    for (int k0 = 0; k0 < DH; k0 += 32) {
        ld_tile(sAh, Ah_g, i0,  k0, DH);
        ld_tile(sAl, Al_g, i0,  k0, DH);
        ld_tile(sBh, Bh_g, j0b, k0, DH);
        ld_tile(sBl, Bl_g, j0b, k0, DH);
        __syncthreads();
        mma_chunk_ldm<4>(aAh, aAl, aBh, aBl, acc, wm, wn, lane);
        __syncthreads();
    }
    int g = lane >> 2, q = lane & 3;
    #pragma unroll
    for (int mi = 0; mi < 4; mi++) {
        #pragma unroll
        for (int ni = 0; ni < 4; ni++) {
            int j = j0b + wn*32 + ni*8 + q*2;
            #pragma unroll
            for (int rr = 0; rr < 2; rr++) {
                int i = i0 + wm*64 + mi*16 + g + rr*8;
                float s0 = acc[mi][ni][rr*2+0], s1 = acc[mi][ni][rr*2+1];
                float o0, o1;
                if (which == 0) {
                    o0 = (j   <= i) ? s0 : 0.f;
                    o1 = (j+1 <= i) ? s1 : 0.f;
                } else {
                    o0 = (j   > i) ? 1.f/(1.f + __expf(-s0)) : 0.f;
                    o1 = (j+1 > i) ? 1.f/(1.f + __expf(-s1)) : 0.f;
                }
                uint32_t hp, lp;
                split2(o0, o1, hp, lp);
                size_t idx = (size_t)i*NTOK + j;
                *(uint32_t*)&Oh[idx] = hp;
                *(uint32_t*)&Ol[idx] = lp;
            }
        }
    }
}

// =====================================================================
// k_su_mma: fused scores
// =====================================================================
__global__ __launch_bounds__(256,2) void k_su_mma()
{
    int bx = blockIdx.x, by = blockIdx.y, bh = blockIdx.z;
    if (bx > by) return;
    const __nv_bfloat16* T1h = g_t1h + (size_t)bh*NTOK*NTOK;
    const __nv_bfloat16* T1l = g_t1l + (size_t)bh*NTOK*NTOK;
    const __nv_bfloat16* SGh = g_sgh + (size_t)bh*NTOK*NTOK;
    const __nv_bfloat16* SGl = g_sgl + (size_t)bh*NTOK*NTOK;
    const __nv_bfloat16* Qh = g_qch + (size_t)bh*NTOK*DH;
    const __nv_bfloat16* Ql = g_qcl + (size_t)bh*NTOK*DH;
    const __nv_bfloat16* Kh = g_kch + (size_t)bh*NTOK*DH;
    const __nv_bfloat16* Kl = g_kcl + (size_t)bh*NTOK*DH;
    float* S = g_su + (size_t)bh*NTOK*NTOK;

    __shared__ __align__(16) uint16_t sAh[128*ST], sAl[128*ST], sBh[128*ST], sBl[128*ST];
    uint32_t aAh = smem_u32(sAh), aAl = smem_u32(sAl);
    uint32_t aBh = smem_u32(sBh), aBl = smem_u32(sBl);
    int tid = threadIdx.x, lane = tid & 31, wid = tid >> 5;
    int wm = wid >> 2, wn = wid & 3;
    int i0 = by*128, kx0 = bx*128;
    float acc[4][4][4] = {};

    int jend = (by+1)*128;
    for (int j0 = bx*128; j0 < jend; j0 += 32) {
        ld_tile(sAh, T1h, i0,  j0, NTOK);
        ld_tile(sAl, T1l, i0,  j0, NTOK);
        ld_tile(sBh, SGh, kx0, j0, NTOK);
        ld_tile(sBl, SGl, kx0, j0, NTOK);
        __syncthreads();
        mma_chunk_ldm<4>(aAh, aAl, aBh, aBl, acc, wm, wn, lane);
        __syncthreads();
    }
    #pragma unroll
    for (int mi = 0; mi < 4; mi++)
        #pragma unroll
        for (int ni = 0; ni < 4; ni++)
            #pragma unroll
            for (int e = 0; e < 4; e++) {
                float su = acc[mi][ni][e];
                acc[mi][ni][e] = -su / (1.f + __expf(-su));
            }
    for (int k0 = 0; k0 < DH; k0 += 32) {
        ld_tile(sAh, Qh, i0,  k0, DH);
        ld_tile(sAl, Ql, i0,  k0, DH);
        ld_tile(sBh, Kh, kx0, k0, DH);
        ld_tile(sBl, Kl, kx0, k0, DH);
        __syncthreads();
        mma_chunk_ldm<4>(aAh, aAl, aBh, aBl, acc, wm, wn, lane);
        __syncthreads();
    }
    int g = lane >> 2, q = lane & 3;
    #pragma unroll
    for (int mi = 0; mi < 4; mi++) {
        #pragma unroll
        for (int ni = 0; ni < 4; ni++) {
            int k = kx0 + wn*32 + ni*8 + q*2;
            #pragma unroll
            for (int rr = 0; rr < 2; rr++) {
                int i = i0 + wm*64 + mi*16 + g + rr*8;
                float v0 = (k   <= i) ? acc[mi][ni][rr*2+0] : -1e30f;
                float v1 = (k+1 <= i) ? acc[mi][ni][rr*2+1] : -1e30f;
                *(float2*)&S[(size_t)i*NTOK + k] = make_float2(v0, v1);
            }
        }
    }
}

// =====================================================================
// k_softmax: 4 consecutive elems/thread; fp32 in, packed bf16 splits out
// =====================================================================
__global__ __launch_bounds__(256) void k_softmax()
{
    int i  = blockIdx.x;
    int bh = blockIdx.y;
    size_t roff = (size_t)bh*NTOK*NTOK + (size_t)i*NTOK;
    const float* S = g_su + roff;
    __nv_bfloat16* Ph = g_ph + roff;
    __nv_bfloat16* Pl = g_pl + roff;
    int L = i + 1;
    int wlen = ((i >> 7) + 1) << 7;
    int tid = threadIdx.x;
    int k0 = tid*4;
    __shared__ float red[256];
    float4 v = *(const float4*)&S[k0];
    float x[4] = {v.x, v.y, v.z, v.w};
    float mx = -1e30f;
    #pragma unroll
    for (int l = 0; l < 4; l++) {
        if (k0 + l >= L) x[l] = -1e30f;
        mx = fmaxf(mx, x[l]);
    }
    red[tid] = mx; __syncthreads();
    for (int s = 128; s > 0; s >>= 1) {
        if (tid < s) red[tid] = fmaxf(red[tid], red[tid+s]);
        __syncthreads();
    }
    mx = red[0]; __syncthreads();
    float sum = 0.f;
    #pragma unroll
    for (int l = 0; l < 4; l++) {
        x[l] = (k0 + l < L) ? __expf(x[l] - mx) : 0.f;
        sum += x[l];
    }
    red[tid] = sum; __syncthreads();
    for (int s = 128; s > 0; s >>= 1) {
        if (tid < s) red[tid] += red[tid+s];
        __syncthreads();
    }
    float inv = 1.f / red[0];
    if (k0 < wlen) {
        uint32_t h0, l0, h1, l1;
        split2(x[0]*inv, x[1]*inv, h0, l0);
        split2(x[2]*inv, x[3]*inv, h1, l1);
        *(uint2*)&Ph[k0] = make_uint2(h0, h1);
        *(uint2*)&Pl[k0] = make_uint2(l0, l1);
    }
}

// =====================================================================
// k_av_mma: O = P @ V via split mma. Block 128x64, warps 4x2 (MI=2).
// =====================================================================
__global__ __launch_bounds__(256,2) void k_av_mma()
{
    int by = blockIdx.x, bh = blockIdx.y;
    int b = bh >> 3, h = bh & 7;
    const __nv_bfloat16* Ph = g_ph + (size_t)bh*NTOK*NTOK;
    const __nv_bfloat16* Pl = g_pl + (size_t)bh*NTOK*NTOK;
    const __nv_bfloat16* Vh = g_vch + (size_t)bh*DH*NTOK;
    const __nv_bfloat16* Vl = g_vcl + (size_t)bh*DH*NTOK;

    __shared__ __align__(16) uint16_t sAh[128*ST], sAl[128*ST], sBh[64*ST], sBl[64*ST];
    uint32_t aAh = smem_u32(sAh), aAl = smem_u32(sAl);
    uint32_t aBh = smem_u32(sBh), aBl = smem_u32(sBl);
    int tid = threadIdx.x, lane = tid & 31, wid = tid >> 5;
    int wm = wid >> 1, wn = wid & 1;   // 4 x 2
    int i0 = by*128;
    float acc[2][4][4] = {};
    int kend = (by+1)*128;
    for (int k0 = 0; k0 < kend; k0 += 32) {
        ld_tile(sAh, Ph, i0, k0, NTOK);
        ld_tile(sAl, Pl, i0, k0, NTOK);
        ld_tile64(sBh, Vh, 0, k0, NTOK);
        ld_tile64(sBl, Vl, 0, k0, NTOK);
        __syncthreads();
        mma_chunk_ldm<2>(aAh, aAl, aBh, aBl, acc, wm, wn, lane);
        __syncthreads();
    }
    int g = lane >> 2, q = lane & 3;
    #pragma unroll
    for (int mi = 0; mi < 2; mi++) {
        #pragma unroll
        for (int ni = 0; ni < 4; ni++) {
            int d = wn*32 + ni*8 + q*2;
            #pragma unroll
            for (int rr = 0; rr < 2; rr++) {
                int i = i0 + wm*32 + mi*16 + g + rr*8;
                size_t row = (size_t)(b*NTOK + i)*DIMM + h*DH + d;
                uint32_t hp, lp;
                split2(acc[mi][ni][rr*2+0], acc[mi][ni][rr*2+1], hp, lp);
                *(uint32_t*)&g_ohh[row] = hp;
                *(uint32_t*)&g_ohl[row] = lp;
            }
        }
    }
}

// =====================================================================
// k_outproj_mma: [2048,512] @ w_out via split mma
// =====================================================================
__global__ __launch_bounds__(256,2) void k_outproj_mma(float* __restrict__ Out)
{
    const __nv_bfloat16* Wth = g_wth + (size_t)6*DIMM*DIMM;
    const __nv_bfloat16* Wtl = g_wtl + (size_t)6*DIMM*DIMM;
    __shared__ __align__(16) uint16_t sAh[128*ST], sAl[128*ST], sBh[128*ST], sBl[128*ST];
    uint32_t aAh = smem_u32(sAh), aAl = smem_u32(sAl);
    uint32_t aBh = smem_u32(sBh), aBl = smem_u32(sBl);
    int tid = threadIdx.x, lane = tid & 31, wid = tid >> 5;
    int wm = wid >> 2, wn = wid & 3;
    int m0 = blockIdx.y*128, n0 = blockIdx.x*128;
    float acc[4][4][4] = {};
    for (int k0 = 0; k0 < DIMM; k0 += 32) {
        ld_tile(sAh, g_ohh, m0, k0, DIMM);
        ld_tile(sAl, g_ohl, m0, k0, DIMM);
        ld_tile(sBh, Wth,  n0, k0, DIMM);
        ld_tile(sBl, Wtl,  n0, k0, DIMM);
        __syncthreads();
        mma_chunk_ldm<4>(aAh, aAl, aBh, aBl, acc, wm, wn, lane);
        __syncthreads();
    }
    int g = lane >> 2, q = lane & 3;
    #pragma unroll
    for (int mi = 0; mi < 4; mi++) {
        #pragma unroll
        for (int ni = 0; ni < 4; ni++) {
            int nn = n0 + wn*32 + ni*8 + q*2;
            #pragma unroll
            for (int rr = 0; rr < 2; rr++) {
                int m = m0 + wm*64 + mi*16 + g + rr*8;
                *(float2*)&Out[(size_t)m*DIMM + nn] =
                    make_float2(acc[mi][ni][rr*2+0], acc[mi][ni][rr*2+1]);
            }
        }
    }
}

extern "C" void kernel_launch(void* const* d_in, const int* in_sizes, int n_in,
                              void* d_out, int out_size)
{
    const float* x   = (const float*)d_in[0];
    const float* wqu = (const float*)d_in[1];
    const float* wku = (const float*)d_in[2];
    const float* wvu = (const float*)d_in[3];
    const float* wqc = (const float*)d_in[4];
    const float* wkc = (const float*)d_in[5];
    const float* wvc = (const float*)d_in[6];
    const float* wout= (const float*)d_in[7];
    float* out = (float*)d_out;

    k_prep_x    <<<1024, 256>>>(x);
    k_prep_w    <<<dim3(16,16,7), dim3(32,8)>>>(wqu, wku, wvu, wqc, wkc, wvc, wout);
    k_proj_mma  <<<dim3(4, 16, 6), 256>>>();
    k_t1sig_mma <<<dim3(8, 8, 32), 256>>>();
    k_su_mma    <<<dim3(8, 8, 16), 256>>>();
    k_softmax   <<<dim3(1024,16),  256>>>();
    k_av_mma    <<<dim3(8, 16),    256>>>();
    k_outproj_mma<<<dim3(4, 16),   256>>>(out);
}

// round 9
// speedup vs baseline: 2.4050x; 1.1285x over previous
#include <cuda_runtime.h>
#include <cuda_bf16.h>
#include <math.h>
#include <stdint.h>

#define NTOK 1024
#define BATCH 2
#define HEADS 8
#define DH 64
#define BHN (BATCH*HEADS)   /* 16 */
#define DIMM 512
#define SCALE 0.125f
#define ST 40               /* smem row stride in bf16 elems (80B, 16B-aligned, conflict-free) */

#define BUF128   (128*ST*2)         /* 10240 B  */
#define STAGE128 (4*BUF128)         /* 40960 B  */
#define SMEM128  (2*STAGE128)       /* 81920 B  */
#define BUF64    (64*ST*2)          /* 5120 B   */
#define STAGE_AV (2*BUF128 + 2*BUF64)  /* 30720 */
#define SMEM_AV  (2*STAGE_AV)       /* 61440 B  */

// ---- scratch ----
__device__ float g_su[(size_t)BHN*NTOK*NTOK];   // pre-softmax scores

// bf16 hi/lo split operands
__device__ __nv_bfloat16 g_xh[2048*DIMM];
__device__ __nv_bfloat16 g_xl[2048*DIMM];
__device__ __nv_bfloat16 g_wth[7*DIMM*DIMM];   // transposed weights [z][n][k]
__device__ __nv_bfloat16 g_wtl[7*DIMM*DIMM];
__device__ __nv_bfloat16 g_t1h[(size_t)BHN*NTOK*NTOK];
__device__ __nv_bfloat16 g_t1l[(size_t)BHN*NTOK*NTOK];
__device__ __nv_bfloat16 g_sgh[(size_t)BHN*NTOK*NTOK];
__device__ __nv_bfloat16 g_sgl[(size_t)BHN*NTOK*NTOK];
__device__ __nv_bfloat16 g_ph[(size_t)BHN*NTOK*NTOK];   // probs split
__device__ __nv_bfloat16 g_pl[(size_t)BHN*NTOK*NTOK];
__device__ __nv_bfloat16 g_quh[BHN*NTOK*DH];   // SCALE * q_u
__device__ __nv_bfloat16 g_qul[BHN*NTOK*DH];
__device__ __nv_bfloat16 g_kuh[BHN*NTOK*DH];
__device__ __nv_bfloat16 g_kul[BHN*NTOK*DH];
__device__ __nv_bfloat16 g_vuh[BHN*NTOK*DH];
__device__ __nv_bfloat16 g_vul[BHN*NTOK*DH];
__device__ __nv_bfloat16 g_qch[BHN*NTOK*DH];   // SCALE * q_c
__device__ __nv_bfloat16 g_qcl[BHN*NTOK*DH];
__device__ __nv_bfloat16 g_kch[BHN*NTOK*DH];
__device__ __nv_bfloat16 g_kcl[BHN*NTOK*DH];
__device__ __nv_bfloat16 g_vch[BHN*DH*NTOK];   // v_c TRANSPOSED [bh][d][tok]
__device__ __nv_bfloat16 g_vcl[BHN*DH*NTOK];
__device__ __nv_bfloat16 g_ohh[2048*DIMM];     // attn@v_c, [m][h*64+d] split
__device__ __nv_bfloat16 g_ohl[2048*DIMM];

// =====================================================================
// helpers
// =====================================================================
#define MMA_BF16(c, a0,a1,a2,a3, b0,b1)                                  \
    asm volatile("mma.sync.aligned.m16n8k16.row.col.f32.bf16.bf16.f32 "  \
        "{%0,%1,%2,%3}, {%4,%5,%6,%7}, {%8,%9}, {%0,%1,%2,%3};"          \
        : "+f"((c)[0]), "+f"((c)[1]), "+f"((c)[2]), "+f"((c)[3])         \
        : "r"(a0), "r"(a1), "r"(a2), "r"(a3), "r"(b0), "r"(b1))

#define LDMX4(r0,r1,r2,r3, addr)                                         \
    asm volatile("ldmatrix.sync.aligned.m8n8.x4.shared.b16 {%0,%1,%2,%3}, [%4];" \
        : "=r"(r0),"=r"(r1),"=r"(r2),"=r"(r3) : "r"(addr))

#define CP_COMMIT() asm volatile("cp.async.commit_group;" ::: "memory")
#define CP_WAIT1()  asm volatile("cp.async.wait_group 1;" ::: "memory")
#define CP_WAIT0()  asm volatile("cp.async.wait_group 0;" ::: "memory")

__device__ __forceinline__ void cp16(uint32_t d, const void* s) {
    asm volatile("cp.async.cg.shared.global [%0], [%1], 16;" :: "r"(d), "l"(s));
}

__device__ __forceinline__ uint32_t smem_u32(const void* p) {
    uint32_t a;
    asm("{ .reg .u64 t; cvta.to.shared.u64 t, %1; cvt.u32.u64 %0, t; }"
        : "=r"(a) : "l"(p));
    return a;
}

// packed hi/lo split of a pair: hp/lp hold {lo16=v0, hi16=v1}
__device__ __forceinline__ void split2(float v0, float v1, uint32_t& hp, uint32_t& lp)
{
    asm("cvt.rn.bf16x2.f32 %0, %1, %2;" : "=r"(hp) : "f"(v1), "f"(v0));
    float h0 = __uint_as_float(hp << 16);
    float h1 = __uint_as_float(hp & 0xFFFF0000u);
    asm("cvt.rn.bf16x2.f32 %0, %1, %2;" : "=r"(lp) : "f"(v1 - h1), "f"(v0 - h0));
}

__device__ __forceinline__ void split_bf16(float v, __nv_bfloat16& h, __nv_bfloat16& l)
{
    h = __float2bfloat16(v);
    l = __float2bfloat16(v - __bfloat162float(h));
}

// async load 128 rows x 32 k bf16 tile into smem (row-major, stride ST)
__device__ __forceinline__ void ld_tile_cp(uint32_t dst, const __nv_bfloat16* g,
                                           int row0, int k0, int ldg, int tid)
{
    int r = tid >> 1, h = tid & 1;
    const __nv_bfloat16* s = g + (size_t)(row0 + r)*ldg + k0 + h*16;
    uint32_t d = dst + (uint32_t)((r*ST + h*16)*2);
    cp16(d, s); cp16(d + 16, s + 8);
}

// =====================================================================
// ldmatrix-based 32-k chunk of the split GEMM.
// =====================================================================
template<int MI>
__device__ __forceinline__ void mma_chunk_ldm(
    uint32_t aAh, uint32_t aAl, uint32_t aBh, uint32_t aBl,
    float (&acc)[MI][4][4], int wm, int wn, int lane)
{
    int lr = lane & 15;
    int lc = (lane >> 4) << 3;
    int bl_ = lane & 7;
    int bn = ((lane >> 4) & 1) << 3;
    int bk = ((lane >> 3) & 1) << 3;
    uint32_t aoff = (uint32_t)(((wm*(MI*16) + lr)*ST + lc) * 2);
    uint32_t boff = (uint32_t)(((wn*32 + bn + bl_)*ST + bk) * 2);
    #pragma unroll
    for (int ks = 0; ks < 2; ks++) {
        uint32_t kb = (uint32_t)(ks * 32);
        uint32_t bhf[4][2], blf[4][2];
        LDMX4(bhf[0][0], bhf[0][1], bhf[1][0], bhf[1][1], aBh + boff + kb);
        LDMX4(bhf[2][0], bhf[2][1], bhf[3][0], bhf[3][1], aBh + boff + kb + 16*ST*2);
        LDMX4(blf[0][0], blf[0][1], blf[1][0], blf[1][1], aBl + boff + kb);
        LDMX4(blf[2][0], blf[2][1], blf[3][0], blf[3][1], aBl + boff + kb + 16*ST*2);
        #pragma unroll
        for (int mi = 0; mi < MI; mi++) {
            uint32_t ao = aoff + kb + (uint32_t)(mi*16*ST*2);
            uint32_t ah0,ah1,ah2,ah3, al0,al1,al2,al3;
            LDMX4(ah0,ah1,ah2,ah3, aAh + ao);
            LDMX4(al0,al1,al2,al3, aAl + ao);
            #pragma unroll
            for (int ni = 0; ni < 4; ni++) {
                MMA_BF16(acc[mi][ni], ah0,ah1,ah2,ah3, bhf[ni][0], bhf[ni][1]);
                MMA_BF16(acc[mi][ni], ah0,ah1,ah2,ah3, blf[ni][0], blf[ni][1]);
                MMA_BF16(acc[mi][ni], al0,al1,al2,al3, bhf[ni][0], bhf[ni][1]);
            }
        }
    }
}

// =====================================================================
// prep kernels
// =====================================================================
__global__ __launch_bounds__(256) void k_prep_x(const float* __restrict__ X)
{
    int idx = (blockIdx.x*256 + threadIdx.x)*4;
    float4 v = *(const float4*)&X[idx];
    uint32_t h0, l0, h1, l1;
    split2(v.x, v.y, h0, l0);
    split2(v.z, v.w, h1, l1);
    *(uint2*)&g_xh[idx] = make_uint2(h0, h1);
    *(uint2*)&g_xl[idx] = make_uint2(l0, l1);
}

__global__ void k_prep_w(
    const float* __restrict__ w0, const float* __restrict__ w1,
    const float* __restrict__ w2, const float* __restrict__ w3,
    const float* __restrict__ w4, const float* __restrict__ w5,
    const float* __restrict__ w6)
{
    const float* W;
    switch (blockIdx.z) {
        case 0: W = w0; break; case 1: W = w1; break; case 2: W = w2; break;
        case 3: W = w3; break; case 4: W = w4; break; case 5: W = w5; break;
        default: W = w6; break;
    }
    __shared__ float t[32][33];
    int tx = threadIdx.x, ty = threadIdx.y;   // (32, 8)
    int k0 = blockIdx.y*32, n0 = blockIdx.x*32;
    #pragma unroll
    for (int i = 0; i < 4; i++)
        t[ty + i*8][tx] = W[(size_t)(k0 + ty + i*8)*DIMM + n0 + tx];
    __syncthreads();
    size_t zoff = (size_t)blockIdx.z * DIMM * DIMM;
    #pragma unroll
    for (int i = 0; i < 4; i++) {
        float v = t[tx][ty + i*8];
        __nv_bfloat16 h, l; split_bf16(v, h, l);
        size_t o = zoff + (size_t)(n0 + ty + i*8)*DIMM + k0 + tx;
        g_wth[o] = h; g_wtl[o] = l;
    }
}

// =====================================================================
// k_proj_mma: pipelined, 16 chunks
// =====================================================================
__global__ __launch_bounds__(256,2) void k_proj_mma()
{
    int z = blockIdx.z;
    __nv_bfloat16 *Oh = 0, *Ol = 0;
    float sc = 1.f;
    switch (z) {
        case 0: Oh = g_quh; Ol = g_qul; sc = SCALE; break;
        case 1: Oh = g_kuh; Ol = g_kul; break;
        case 2: Oh = g_vuh; Ol = g_vul; break;
        case 3: Oh = g_qch; Ol = g_qcl; sc = SCALE; break;
        case 4: Oh = g_kch; Ol = g_kcl; break;
        default: break;
    }
    const __nv_bfloat16* Wth = g_wth + (size_t)z*DIMM*DIMM;
    const __nv_bfloat16* Wtl = g_wtl + (size_t)z*DIMM*DIMM;
    extern __shared__ __align__(16) char dynsm[];
    uint32_t base = smem_u32(dynsm);
    int tid = threadIdx.x, lane = tid & 31, wid = tid >> 5;
    int wm = wid >> 2, wn = wid & 3;
    int m0 = blockIdx.y*128, n0 = blockIdx.x*128;
    float acc[4][4][4] = {};

    auto load_stage = [&](int s, int k0) {
        uint32_t sb = base + s*STAGE128;
        ld_tile_cp(sb,            g_xh, m0, k0, DIMM, tid);
        ld_tile_cp(sb +   BUF128, g_xl, m0, k0, DIMM, tid);
        ld_tile_cp(sb + 2*BUF128, Wth,  n0, k0, DIMM, tid);
        ld_tile_cp(sb + 3*BUF128, Wtl,  n0, k0, DIMM, tid);
    };
    load_stage(0, 0); CP_COMMIT();
    for (int c = 0; c < 16; c++) {
        int cur = c & 1;
        if (c + 1 < 16) { load_stage(cur^1, (c+1)*32); CP_COMMIT(); CP_WAIT1(); }
        else CP_WAIT0();
        __syncthreads();
        uint32_t sb = base + cur*STAGE128;
        mma_chunk_ldm<4>(sb, sb+BUF128, sb+2*BUF128, sb+3*BUF128, acc, wm, wn, lane);
        __syncthreads();
    }
    int g = lane >> 2, q = lane & 3;
    #pragma unroll
    for (int mi = 0; mi < 4; mi++) {
        #pragma unroll
        for (int ni = 0; ni < 4; ni++) {
            int col = n0 + wn*32 + ni*8 + q*2;
            int h = col >> 6, dd = col & 63;
            #pragma unroll
            for (int rr = 0; rr < 2; rr++) {
                int m = m0 + wm*64 + mi*16 + g + rr*8;
                int b = m >> 10, tok = m & 1023;
                float v0 = acc[mi][ni][rr*2+0], v1 = acc[mi][ni][rr*2+1];
                if (z == 5) {
                    size_t tb = ((size_t)(b*HEADS + h)*DH + dd)*NTOK + tok;
                    __nv_bfloat16 h0, l0, h1, l1;
                    split_bf16(v0, h0, l0); split_bf16(v1, h1, l1);
                    g_vch[tb] = h0;        g_vcl[tb] = l0;
                    g_vch[tb + NTOK] = h1; g_vcl[tb + NTOK] = l1;
                } else {
                    size_t oidx = ((size_t)(b*HEADS + h)*NTOK + tok)*DH + dd;
                    uint32_t hp, lp;
                    split2(v0*sc, v1*sc, hp, lp);
                    *(uint32_t*)&Oh[oidx] = hp;
                    *(uint32_t*)&Ol[oidx] = lp;
                }
            }
        }
    }
}

// =====================================================================
// k_t1sig_mma: pipelined, 2 chunks
// =====================================================================
__global__ __launch_bounds__(256,2) void k_t1sig_mma()
{
    int which = blockIdx.z >> 4;
    int bh    = blockIdx.z & 15;
    int bx = blockIdx.x, by = blockIdx.y;
    if (which == 0) { if (bx > by) return; }
    else            { if (bx < by) return; }
    size_t voff = (size_t)bh*NTOK*DH;
    const __nv_bfloat16* Ah_g = (which == 0 ? g_qch : g_quh) + voff;
    const __nv_bfloat16* Al_g = (which == 0 ? g_qcl : g_qul) + voff;
    const __nv_bfloat16* Bh_g = (which == 0 ? g_vuh : g_kuh) + voff;
    const __nv_bfloat16* Bl_g = (which == 0 ? g_vul : g_kul) + voff;
    __nv_bfloat16* Oh = (which == 0 ? g_t1h : g_sgh) + (size_t)bh*NTOK*NTOK;
    __nv_bfloat16* Ol = (which == 0 ? g_t1l : g_sgl) + (size_t)bh*NTOK*NTOK;

    extern __shared__ __align__(16) char dynsm[];
    uint32_t base = smem_u32(dynsm);
    int tid = threadIdx.x, lane = tid & 31, wid = tid >> 5;
    int wm = wid >> 2, wn = wid & 3;
    int i0 = by*128, j0b = bx*128;
    float acc[4][4][4] = {};

    auto load_stage = [&](int s, int k0) {
        uint32_t sb = base + s*STAGE128;
        ld_tile_cp(sb,            Ah_g, i0,  k0, DH, tid);
        ld_tile_cp(sb +   BUF128, Al_g, i0,  k0, DH, tid);
        ld_tile_cp(sb + 2*BUF128, Bh_g, j0b, k0, DH, tid);
        ld_tile_cp(sb + 3*BUF128, Bl_g, j0b, k0, DH, tid);
    };
    load_stage(0, 0); CP_COMMIT();
    for (int c = 0; c < 2; c++) {
        int cur = c & 1;
        if (c + 1 < 2) { load_stage(cur^1, 32); CP_COMMIT(); CP_WAIT1(); }
        else CP_WAIT0();
        __syncthreads();
        uint32_t sb = base + cur*STAGE128;
        mma_chunk_ldm<4>(sb, sb+BUF128, sb+2*BUF128, sb+3*BUF128, acc, wm, wn, lane);
        __syncthreads();
    }
    int g = lane >> 2, q = lane & 3;
    #pragma unroll
    for (int mi = 0; mi < 4; mi++) {
        #pragma unroll
        for (int ni = 0; ni < 4; ni++) {
            int j = j0b + wn*32 + ni*8 + q*2;
            #pragma unroll
            for (int rr = 0; rr < 2; rr++) {
                int i = i0 + wm*64 + mi*16 + g + rr*8;
                float s0 = acc[mi][ni][rr*2+0], s1 = acc[mi][ni][rr*2+1];
                float o0, o1;
                if (which == 0) {
                    o0 = (j   <= i) ? s0 : 0.f;
                    o1 = (j+1 <= i) ? s1 : 0.f;
                } else {
                    o0 = (j   > i) ? 1.f/(1.f + __expf(-s0)) : 0.f;
                    o1 = (j+1 > i) ? 1.f/(1.f + __expf(-s1)) : 0.f;
                }
                uint32_t hp, lp;
                split2(o0, o1, hp, lp);
                size_t idx = (size_t)i*NTOK + j;
                *(uint32_t*)&Oh[idx] = hp;
                *(uint32_t*)&Ol[idx] = lp;
            }
        }
    }
}

// =====================================================================
// k_su_mma: unified pipelined loop over phase1 (S_u) + phase2 (QK)
// =====================================================================
__global__ __launch_bounds__(256,2) void k_su_mma()
{
    int bx = blockIdx.x, by = blockIdx.y, bh = blockIdx.z;
    if (bx > by) return;
    const __nv_bfloat16* T1h = g_t1h + (size_t)bh*NTOK*NTOK;
    const __nv_bfloat16* T1l = g_t1l + (size_t)bh*NTOK*NTOK;
    const __nv_bfloat16* SGh = g_sgh + (size_t)bh*NTOK*NTOK;
    const __nv_bfloat16* SGl = g_sgl + (size_t)bh*NTOK*NTOK;
    const __nv_bfloat16* Qh = g_qch + (size_t)bh*NTOK*DH;
    const __nv_bfloat16* Ql = g_qcl + (size_t)bh*NTOK*DH;
    const __nv_bfloat16* Kh = g_kch + (size_t)bh*NTOK*DH;
    const __nv_bfloat16* Kl = g_kcl + (size_t)bh*NTOK*DH;
    float* S = g_su + (size_t)bh*NTOK*NTOK;

    extern __shared__ __align__(16) char dynsm[];
    uint32_t base = smem_u32(dynsm);
    int tid = threadIdx.x, lane = tid & 31, wid = tid >> 5;
    int wm = wid >> 2, wn = wid & 3;
    int i0 = by*128, kx0 = bx*128;
    float acc[4][4][4] = {};

    int n1 = (by - bx + 1) * 4;      // phase-1 chunks
    int ntot = n1 + 2;

    auto load_stage = [&](int s, int c) {
        uint32_t sb = base + s*STAGE128;
        if (c < n1) {
            int j0 = bx*128 + c*32;
            ld_tile_cp(sb,            T1h, i0,  j0, NTOK, tid);
            ld_tile_cp(sb +   BUF128, T1l, i0,  j0, NTOK, tid);
            ld_tile_cp(sb + 2*BUF128, SGh, kx0, j0, NTOK, tid);
            ld_tile_cp(sb + 3*BUF128, SGl, kx0, j0, NTOK, tid);
        } else {
            int k0 = (c - n1)*32;
            ld_tile_cp(sb,            Qh, i0,  k0, DH, tid);
            ld_tile_cp(sb +   BUF128, Ql, i0,  k0, DH, tid);
            ld_tile_cp(sb + 2*BUF128, Kh, kx0, k0, DH, tid);
            ld_tile_cp(sb + 3*BUF128, Kl, kx0, k0, DH, tid);
        }
    };
    load_stage(0, 0); CP_COMMIT();
    for (int c = 0; c < ntot; c++) {
        int cur = c & 1;
        if (c + 1 < ntot) { load_stage(cur^1, c+1); CP_COMMIT(); CP_WAIT1(); }
        else CP_WAIT0();
        __syncthreads();
        if (c == n1) {   // phase boundary: acc = -silu(acc), registers only
            #pragma unroll
            for (int mi = 0; mi < 4; mi++)
                #pragma unroll
                for (int ni = 0; ni < 4; ni++)
                    #pragma unroll
                    for (int e = 0; e < 4; e++) {
                        float su = acc[mi][ni][e];
                        acc[mi][ni][e] = -su / (1.f + __expf(-su));
                    }
        }
        uint32_t sb = base + cur*STAGE128;
        mma_chunk_ldm<4>(sb, sb+BUF128, sb+2*BUF128, sb+3*BUF128, acc, wm, wn, lane);
        __syncthreads();
    }
    int g = lane >> 2, q = lane & 3;
    #pragma unroll
    for (int mi = 0; mi < 4; mi++) {
        #pragma unroll
        for (int ni = 0; ni < 4; ni++) {
            int k = kx0 + wn*32 + ni*8 + q*2;
            #pragma unroll
            for (int rr = 0; rr < 2; rr++) {
                int i = i0 + wm*64 + mi*16 + g + rr*8;
                float v0 = (k   <= i) ? acc[mi][ni][rr*2+0] : -1e30f;
                float v1 = (k+1 <= i) ? acc[mi][ni][rr*2+1] : -1e30f;
                *(float2*)&S[(size_t)i*NTOK + k] = make_float2(v0, v1);
            }
        }
    }
}

// =====================================================================
// k_softmax
// =====================================================================
__global__ __launch_bounds__(256) void k_softmax()
{
    int i  = blockIdx.x;
    int bh = blockIdx.y;
    size_t roff = (size_t)bh*NTOK*NTOK + (size_t)i*NTOK;
    const float* S = g_su + roff;
    __nv_bfloat16* Ph = g_ph + roff;
    __nv_bfloat16* Pl = g_pl + roff;
    int L = i + 1;
    int wlen = ((i >> 7) + 1) << 7;
    int tid = threadIdx.x;
    int k0 = tid*4;
    __shared__ float red[256];
    float4 v = *(const float4*)&S[k0];
    float x[4] = {v.x, v.y, v.z, v.w};
    float mx = -1e30f;
    #pragma unroll
    for (int l = 0; l < 4; l++) {
        if (k0 + l >= L) x[l] = -1e30f;
        mx = fmaxf(mx, x[l]);
    }
    red[tid] = mx; __syncthreads();
    for (int s = 128; s > 0; s >>= 1) {
        if (tid < s) red[tid] = fmaxf(red[tid], red[tid+s]);
        __syncthreads();
    }
    mx = red[0]; __syncthreads();
    float sum = 0.f;
    #pragma unroll
    for (int l = 0; l < 4; l++) {
        x[l] = (k0 + l < L) ? __expf(x[l] - mx) : 0.f;
        sum += x[l];
    }
    red[tid] = sum; __syncthreads();
    for (int s = 128; s > 0; s >>= 1) {
        if (tid < s) red[tid] += red[tid+s];
        __syncthreads();
    }
    float inv = 1.f / red[0];
    if (k0 < wlen) {
        uint32_t h0, l0, h1, l1;
        split2(x[0]*inv, x[1]*inv, h0, l0);
        split2(x[2]*inv, x[3]*inv, h1, l1);
        *(uint2*)&Ph[k0] = make_uint2(h0, h1);
        *(uint2*)&Pl[k0] = make_uint2(l0, l1);
    }
}

// =====================================================================
// k_av_mma: O = P @ V, pipelined. Block 128x64, warps 4x2 (MI=2).
// =====================================================================
__global__ __launch_bounds__(256,2) void k_av_mma()
{
    int by = blockIdx.x, bh = blockIdx.y;
    int b = bh >> 3, h = bh & 7;
    const __nv_bfloat16* Ph = g_ph + (size_t)bh*NTOK*NTOK;
    const __nv_bfloat16* Pl = g_pl + (size_t)bh*NTOK*NTOK;
    const __nv_bfloat16* Vh = g_vch + (size_t)bh*DH*NTOK;
    const __nv_bfloat16* Vl = g_vcl + (size_t)bh*DH*NTOK;

    extern __shared__ __align__(16) char dynsm[];
    uint32_t base = smem_u32(dynsm);
    int tid = threadIdx.x, lane = tid & 31, wid = tid >> 5;
    int wm = wid >> 1, wn = wid & 1;
    int i0 = by*128;
    float acc[2][4][4] = {};
    int nch = (by + 1) * 4;

    auto load_stage = [&](int s, int c) {
        int k0 = c*32;
        uint32_t sb = base + s*STAGE_AV;
        ld_tile_cp(sb,          Ph, i0, k0, NTOK, tid);
        ld_tile_cp(sb + BUF128, Pl, i0, k0, NTOK, tid);
        if (tid < 128) {
            ld_tile_cp(sb + 2*BUF128,         Vh, 0, k0, NTOK, tid);
            ld_tile_cp(sb + 2*BUF128 + BUF64, Vl, 0, k0, NTOK, tid);
        }
    };
    load_stage(0, 0); CP_COMMIT();
    for (int c = 0; c < nch; c++) {
        int cur = c & 1;
        if (c + 1 < nch) { load_stage(cur^1, c+1); CP_COMMIT(); CP_WAIT1(); }
        else CP_WAIT0();
        __syncthreads();
        uint32_t sb = base + cur*STAGE_AV;
        mma_chunk_ldm<2>(sb, sb+BUF128, sb+2*BUF128, sb+2*BUF128+BUF64,
                         acc, wm, wn, lane);
        __syncthreads();
    }
    int g = lane >> 2, q = lane & 3;
    #pragma unroll
    for (int mi = 0; mi < 2; mi++) {
        #pragma unroll
        for (int ni = 0; ni < 4; ni++) {
            int d = wn*32 + ni*8 + q*2;
            #pragma unroll
            for (int rr = 0; rr < 2; rr++) {
                int i = i0 + wm*32 + mi*16 + g + rr*8;
                size_t row = (size_t)(b*NTOK + i)*DIMM + h*DH + d;
                uint32_t hp, lp;
                split2(acc[mi][ni][rr*2+0], acc[mi][ni][rr*2+1], hp, lp);
                *(uint32_t*)&g_ohh[row] = hp;
                *(uint32_t*)&g_ohl[row] = lp;
            }
        }
    }
}

// =====================================================================
// k_outproj_mma: pipelined, 16 chunks
// =====================================================================
__global__ __launch_bounds__(256,2) void k_outproj_mma(float* __restrict__ Out)
{
    const __nv_bfloat16* Wth = g_wth + (size_t)6*DIMM*DIMM;
    const __nv_bfloat16* Wtl = g_wtl + (size_t)6*DIMM*DIMM;
    extern __shared__ __align__(16) char dynsm[];
    uint32_t base = smem_u32(dynsm);
    int tid = threadIdx.x, lane = tid & 31, wid = tid >> 5;
    int wm = wid >> 2, wn = wid & 3;
    int m0 = blockIdx.y*128, n0 = blockIdx.x*128;
    float acc[4][4][4] = {};

    auto load_stage = [&](int s, int k0) {
        uint32_t sb = base + s*STAGE128;
        ld_tile_cp(sb,            g_ohh, m0, k0, DIMM, tid);
        ld_tile_cp(sb +   BUF128, g_ohl, m0, k0, DIMM, tid);
        ld_tile_cp(sb + 2*BUF128, Wth,   n0, k0, DIMM, tid);
        ld_tile_cp(sb + 3*BUF128, Wtl,   n0, k0, DIMM, tid);
    };
    load_stage(0, 0); CP_COMMIT();
    for (int c = 0; c < 16; c++) {
        int cur = c & 1;
        if (c + 1 < 16) { load_stage(cur^1, (c+1)*32); CP_COMMIT(); CP_WAIT1(); }
        else CP_WAIT0();
        __syncthreads();
        uint32_t sb = base + cur*STAGE128;
        mma_chunk_ldm<4>(sb, sb+BUF128, sb+2*BUF128, sb+3*BUF128, acc, wm, wn, lane);
        __syncthreads();
    }
    int g = lane >> 2, q = lane & 3;
    #pragma unroll
    for (int mi = 0; mi < 4; mi++) {
        #pragma unroll
        for (int ni = 0; ni < 4; ni++) {
            int nn = n0 + wn*32 + ni*8 + q*2;
            #pragma unroll
            for (int rr = 0; rr < 2; rr++) {
                int m = m0 + wm*64 + mi*16 + g + rr*8;
                *(float2*)&Out[(size_t)m*DIMM + nn] =
                    make_float2(acc[mi][ni][rr*2+0], acc[mi][ni][rr*2+1]);
            }
        }
    }
}

extern "C" void kernel_launch(void* const* d_in, const int* in_sizes, int n_in,
                              void* d_out, int out_size)
{
    const float* x   = (const float*)d_in[0];
    const float* wqu = (const float*)d_in[1];
    const float* wku = (const float*)d_in[2];
    const float* wvu = (const float*)d_in[3];
    const float* wqc = (const float*)d_in[4];
    const float* wkc = (const float*)d_in[5];
    const float* wvc = (const float*)d_in[6];
    const float* wout= (const float*)d_in[7];
    float* out = (float*)d_out;

    static int attr_done = 0;
    if (!attr_done) {
        cudaFuncSetAttribute(k_proj_mma,    cudaFuncAttributeMaxDynamicSharedMemorySize, SMEM128);
        cudaFuncSetAttribute(k_t1sig_mma,   cudaFuncAttributeMaxDynamicSharedMemorySize, SMEM128);
        cudaFuncSetAttribute(k_su_mma,      cudaFuncAttributeMaxDynamicSharedMemorySize, SMEM128);
        cudaFuncSetAttribute(k_av_mma,      cudaFuncAttributeMaxDynamicSharedMemorySize, SMEM_AV);
        cudaFuncSetAttribute(k_outproj_mma, cudaFuncAttributeMaxDynamicSharedMemorySize, SMEM128);
        attr_done = 1;
    }

    k_prep_x    <<<1024, 256>>>(x);
    k_prep_w    <<<dim3(16,16,7), dim3(32,8)>>>(wqu, wku, wvu, wqc, wkc, wvc, wout);
    k_proj_mma  <<<dim3(4, 16, 6), 256, SMEM128>>>();
    k_t1sig_mma <<<dim3(8, 8, 32), 256, SMEM128>>>();
    k_su_mma    <<<dim3(8, 8, 16), 256, SMEM128>>>();
    k_softmax   <<<dim3(1024,16),  256>>>();
    k_av_mma    <<<dim3(8, 16),    256, SMEM_AV>>>();
    k_outproj_mma<<<dim3(4, 16),   256, SMEM128>>>(out);
}

// round 10
// speedup vs baseline: 2.7306x; 1.1354x over previous
#include <cuda_runtime.h>
#include <cuda_bf16.h>
#include <cuda_fp16.h>
#include <math.h>
#include <stdint.h>

#define NTOK 1024
#define BATCH 2
#define HEADS 8
#define DH 64
#define BHN (BATCH*HEADS)   /* 16 */
#define DIMM 512
#define SCALE 0.125f
#define ST 40               /* smem row stride in 16-bit elems (80B, 16B-aligned, conflict-free) */

#define BUF128   (128*ST*2)         /* 10240 B  */
#define STAGE128 (4*BUF128)         /* 40960 B  */
#define SMEM128  (2*STAGE128)       /* 81920 B  */
#define BUF64    (64*ST*2)          /* 5120 B   */
#define STAGE_AV (BUF128 + BUF64)   /* 15360 B  */
#define SMEM_AV  (2*STAGE_AV)       /* 30720 B  */

// ---- scratch ----
__device__ float g_su[(size_t)BHN*NTOK*NTOK];   // pre-softmax scores

// bf16 hi/lo split operands (high-sensitivity GEMMs)
__device__ __nv_bfloat16 g_xh[2048*DIMM];
__device__ __nv_bfloat16 g_xl[2048*DIMM];
__device__ __nv_bfloat16 g_wth[7*DIMM*DIMM];   // transposed weights [z][n][k]
__device__ __nv_bfloat16 g_wtl[7*DIMM*DIMM];
__device__ __nv_bfloat16 g_quh[BHN*NTOK*DH];   // SCALE * q_u
__device__ __nv_bfloat16 g_qul[BHN*NTOK*DH];
__device__ __nv_bfloat16 g_kuh[BHN*NTOK*DH];
__device__ __nv_bfloat16 g_kul[BHN*NTOK*DH];
__device__ __nv_bfloat16 g_vuh[BHN*NTOK*DH];
__device__ __nv_bfloat16 g_vul[BHN*NTOK*DH];
__device__ __nv_bfloat16 g_qch[BHN*NTOK*DH];   // SCALE * q_c
__device__ __nv_bfloat16 g_qcl[BHN*NTOK*DH];
__device__ __nv_bfloat16 g_kch[BHN*NTOK*DH];
__device__ __nv_bfloat16 g_kcl[BHN*NTOK*DH];
__device__ __nv_bfloat16 g_ohh[2048*DIMM];     // attn@v_c, [m][h*64+d] split
__device__ __nv_bfloat16 g_ohl[2048*DIMM];

// fp16 operands (precision-budgeted GEMMs)
__device__ __half g_t1h[(size_t)BHN*NTOK*NTOK];  // term1 fp16 hi
__device__ __half g_t1l[(size_t)BHN*NTOK*NTOK];  // term1 fp16 lo
__device__ __half g_sg [(size_t)BHN*NTOK*NTOK];  // sig, single fp16
__device__ __half g_p  [(size_t)BHN*NTOK*NTOK];  // probs, single fp16
__device__ __half g_vct[BHN*DH*NTOK];            // v_c TRANSPOSED [bh][d][tok], fp16

// =====================================================================
// helpers
// =====================================================================
#define MMA_BF16(c, a0,a1,a2,a3, b0,b1)                                  \
    asm volatile("mma.sync.aligned.m16n8k16.row.col.f32.bf16.bf16.f32 "  \
        "{%0,%1,%2,%3}, {%4,%5,%6,%7}, {%8,%9}, {%0,%1,%2,%3};"          \
        : "+f"((c)[0]), "+f"((c)[1]), "+f"((c)[2]), "+f"((c)[3])         \
        : "r"(a0), "r"(a1), "r"(a2), "r"(a3), "r"(b0), "r"(b1))

#define MMA_F16(c, a0,a1,a2,a3, b0,b1)                                   \
    asm volatile("mma.sync.aligned.m16n8k16.row.col.f32.f16.f16.f32 "    \
        "{%0,%1,%2,%3}, {%4,%5,%6,%7}, {%8,%9}, {%0,%1,%2,%3};"          \
        : "+f"((c)[0]), "+f"((c)[1]), "+f"((c)[2]), "+f"((c)[3])         \
        : "r"(a0), "r"(a1), "r"(a2), "r"(a3), "r"(b0), "r"(b1))

#define LDMX4(r0,r1,r2,r3, addr)                                         \
    asm volatile("ldmatrix.sync.aligned.m8n8.x4.shared.b16 {%0,%1,%2,%3}, [%4];" \
        : "=r"(r0),"=r"(r1),"=r"(r2),"=r"(r3) : "r"(addr))

#define CP_COMMIT() asm volatile("cp.async.commit_group;" ::: "memory")
#define CP_WAIT1()  asm volatile("cp.async.wait_group 1;" ::: "memory")
#define CP_WAIT0()  asm volatile("cp.async.wait_group 0;" ::: "memory")

__device__ __forceinline__ void cp16(uint32_t d, const void* s) {
    asm volatile("cp.async.cg.shared.global [%0], [%1], 16;" :: "r"(d), "l"(s));
}

__device__ __forceinline__ uint32_t smem_u32(const void* p) {
    uint32_t a;
    asm("{ .reg .u64 t; cvta.to.shared.u64 t, %1; cvt.u32.u64 %0, t; }"
        : "=r"(a) : "l"(p));
    return a;
}

// packed bf16 hi/lo split of a pair: hp/lp hold {lo16=v0, hi16=v1}
__device__ __forceinline__ void split2(float v0, float v1, uint32_t& hp, uint32_t& lp)
{
    asm("cvt.rn.bf16x2.f32 %0, %1, %2;" : "=r"(hp) : "f"(v1), "f"(v0));
    float h0 = __uint_as_float(hp << 16);
    float h1 = __uint_as_float(hp & 0xFFFF0000u);
    asm("cvt.rn.bf16x2.f32 %0, %1, %2;" : "=r"(lp) : "f"(v1 - h1), "f"(v0 - h0));
}

// packed fp16 hi/lo split of a pair
__device__ __forceinline__ void split2h(float v0, float v1, uint32_t& hp, uint32_t& lp)
{
    asm("cvt.rn.f16x2.f32 %0, %1, %2;" : "=r"(hp) : "f"(v1), "f"(v0));
    __half2 h2 = *reinterpret_cast<__half2*>(&hp);
    float h0 = __low2float(h2), h1 = __high2float(h2);
    asm("cvt.rn.f16x2.f32 %0, %1, %2;" : "=r"(lp) : "f"(v1 - h1), "f"(v0 - h0));
}

__device__ __forceinline__ uint32_t pack2h(float v0, float v1)
{
    uint32_t r;
    asm("cvt.rn.f16x2.f32 %0, %1, %2;" : "=r"(r) : "f"(v1), "f"(v0));
    return r;
}

__device__ __forceinline__ void split_bf16(float v, __nv_bfloat16& h, __nv_bfloat16& l)
{
    h = __float2bfloat16(v);
    l = __float2bfloat16(v - __bfloat162float(h));
}

// async load 128 rows x 32 col 16-bit tile into smem (row-major, stride ST)
__device__ __forceinline__ void ld_tile_cp(uint32_t dst, const uint16_t* g,
                                           int row0, int k0, int ldg, int tid)
{
    int r = tid >> 1, h = tid & 1;
    const uint16_t* s = g + (size_t)(row0 + r)*ldg + k0 + h*16;
    uint32_t d = dst + (uint32_t)((r*ST + h*16)*2);
    cp16(d, s); cp16(d + 16, s + 8);
}

// =====================================================================
// mma chunk variants (ldmatrix-based, 32-k chunk)
// =====================================================================
// 3-product bf16 split x split
template<int MI>
__device__ __forceinline__ void mma_chunk_ldm(
    uint32_t aAh, uint32_t aAl, uint32_t aBh, uint32_t aBl,
    float (&acc)[MI][4][4], int wm, int wn, int lane)
{
    int lr = lane & 15;
    int lc = (lane >> 4) << 3;
    int bl_ = lane & 7;
    int bn = ((lane >> 4) & 1) << 3;
    int bk = ((lane >> 3) & 1) << 3;
    uint32_t aoff = (uint32_t)(((wm*(MI*16) + lr)*ST + lc) * 2);
    uint32_t boff = (uint32_t)(((wn*32 + bn + bl_)*ST + bk) * 2);
    #pragma unroll
    for (int ks = 0; ks < 2; ks++) {
        uint32_t kb = (uint32_t)(ks * 32);
        uint32_t bhf[4][2], blf[4][2];
        LDMX4(bhf[0][0], bhf[0][1], bhf[1][0], bhf[1][1], aBh + boff + kb);
        LDMX4(bhf[2][0], bhf[2][1], bhf[3][0], bhf[3][1], aBh + boff + kb + 16*ST*2);
        LDMX4(blf[0][0], blf[0][1], blf[1][0], blf[1][1], aBl + boff + kb);
        LDMX4(blf[2][0], blf[2][1], blf[3][0], blf[3][1], aBl + boff + kb + 16*ST*2);
        #pragma unroll
        for (int mi = 0; mi < MI; mi++) {
            uint32_t ao = aoff + kb + (uint32_t)(mi*16*ST*2);
            uint32_t ah0,ah1,ah2,ah3, al0,al1,al2,al3;
            LDMX4(ah0,ah1,ah2,ah3, aAh + ao);
            LDMX4(al0,al1,al2,al3, aAl + ao);
            #pragma unroll
            for (int ni = 0; ni < 4; ni++) {
                MMA_BF16(acc[mi][ni], ah0,ah1,ah2,ah3, bhf[ni][0], bhf[ni][1]);
                MMA_BF16(acc[mi][ni], ah0,ah1,ah2,ah3, blf[ni][0], blf[ni][1]);
                MMA_BF16(acc[mi][ni], al0,al1,al2,al3, bhf[ni][0], bhf[ni][1]);
            }
        }
    }
}

// 2-product fp16: A split (hi/lo) x B single
template<int MI>
__device__ __forceinline__ void mma_chunk_2p(
    uint32_t aAh, uint32_t aAl, uint32_t aB,
    float (&acc)[MI][4][4], int wm, int wn, int lane)
{
    int lr = lane & 15;
    int lc = (lane >> 4) << 3;
    int bl_ = lane & 7;
    int bn = ((lane >> 4) & 1) << 3;
    int bk = ((lane >> 3) & 1) << 3;
    uint32_t aoff = (uint32_t)(((wm*(MI*16) + lr)*ST + lc) * 2);
    uint32_t boff = (uint32_t)(((wn*32 + bn + bl_)*ST + bk) * 2);
    #pragma unroll
    for (int ks = 0; ks < 2; ks++) {
        uint32_t kb = (uint32_t)(ks * 32);
        uint32_t bf[4][2];
        LDMX4(bf[0][0], bf[0][1], bf[1][0], bf[1][1], aB + boff + kb);
        LDMX4(bf[2][0], bf[2][1], bf[3][0], bf[3][1], aB + boff + kb + 16*ST*2);
        #pragma unroll
        for (int mi = 0; mi < MI; mi++) {
            uint32_t ao = aoff + kb + (uint32_t)(mi*16*ST*2);
            uint32_t ah0,ah1,ah2,ah3, al0,al1,al2,al3;
            LDMX4(ah0,ah1,ah2,ah3, aAh + ao);
            LDMX4(al0,al1,al2,al3, aAl + ao);
            #pragma unroll
            for (int ni = 0; ni < 4; ni++) {
                MMA_F16(acc[mi][ni], ah0,ah1,ah2,ah3, bf[ni][0], bf[ni][1]);
                MMA_F16(acc[mi][ni], al0,al1,al2,al3, bf[ni][0], bf[ni][1]);
            }
        }
    }
}

// 1-product fp16: A single x B single
template<int MI>
__device__ __forceinline__ void mma_chunk_1p(
    uint32_t aA, uint32_t aB,
    float (&acc)[MI][4][4], int wm, int wn, int lane)
{
    int lr = lane & 15;
    int lc = (lane >> 4) << 3;
    int bl_ = lane & 7;
    int bn = ((lane >> 4) & 1) << 3;
    int bk = ((lane >> 3) & 1) << 3;
    uint32_t aoff = (uint32_t)(((wm*(MI*16) + lr)*ST + lc) * 2);
    uint32_t boff = (uint32_t)(((wn*32 + bn + bl_)*ST + bk) * 2);
    #pragma unroll
    for (int ks = 0; ks < 2; ks++) {
        uint32_t kb = (uint32_t)(ks * 32);
        uint32_t bf[4][2];
        LDMX4(bf[0][0], bf[0][1], bf[1][0], bf[1][1], aB + boff + kb);
        LDMX4(bf[2][0], bf[2][1], bf[3][0], bf[3][1], aB + boff + kb + 16*ST*2);
        #pragma unroll
        for (int mi = 0; mi < MI; mi++) {
            uint32_t ao = aoff + kb + (uint32_t)(mi*16*ST*2);
            uint32_t a0,a1,a2,a3;
            LDMX4(a0,a1,a2,a3, aA + ao);
            #pragma unroll
            for (int ni = 0; ni < 4; ni++)
                MMA_F16(acc[mi][ni], a0,a1,a2,a3, bf[ni][0], bf[ni][1]);
        }
    }
}

// =====================================================================
// prep kernels
// =====================================================================
__global__ __launch_bounds__(256) void k_prep_x(const float* __restrict__ X)
{
    int idx = (blockIdx.x*256 + threadIdx.x)*4;
    float4 v = *(const float4*)&X[idx];
    uint32_t h0, l0, h1, l1;
    split2(v.x, v.y, h0, l0);
    split2(v.z, v.w, h1, l1);
    *(uint2*)&g_xh[idx] = make_uint2(h0, h1);
    *(uint2*)&g_xl[idx] = make_uint2(l0, l1);
}

__global__ void k_prep_w(
    const float* __restrict__ w0, const float* __restrict__ w1,
    const float* __restrict__ w2, const float* __restrict__ w3,
    const float* __restrict__ w4, const float* __restrict__ w5,
    const float* __restrict__ w6)
{
    const float* W;
    switch (blockIdx.z) {
        case 0: W = w0; break; case 1: W = w1; break; case 2: W = w2; break;
        case 3: W = w3; break; case 4: W = w4; break; case 5: W = w5; break;
        default: W = w6; break;
    }
    __shared__ float t[32][33];
    int tx = threadIdx.x, ty = threadIdx.y;   // (32, 8)
    int k0 = blockIdx.y*32, n0 = blockIdx.x*32;
    #pragma unroll
    for (int i = 0; i < 4; i++)
        t[ty + i*8][tx] = W[(size_t)(k0 + ty + i*8)*DIMM + n0 + tx];
    __syncthreads();
    size_t zoff = (size_t)blockIdx.z * DIMM * DIMM;
    #pragma unroll
    for (int i = 0; i < 4; i++) {
        float v = t[tx][ty + i*8];
        __nv_bfloat16 h, l; split_bf16(v, h, l);
        size_t o = zoff + (size_t)(n0 + ty + i*8)*DIMM + k0 + tx;
        g_wth[o] = h; g_wtl[o] = l;
    }
}

// =====================================================================
// k_proj_mma: pipelined, 16 chunks; z==5 -> transposed fp16 v_c
// =====================================================================
__global__ __launch_bounds__(256,2) void k_proj_mma()
{
    int z = blockIdx.z;
    __nv_bfloat16 *Oh = 0, *Ol = 0;
    float sc = 1.f;
    switch (z) {
        case 0: Oh = g_quh; Ol = g_qul; sc = SCALE; break;
        case 1: Oh = g_kuh; Ol = g_kul; break;
        case 2: Oh = g_vuh; Ol = g_vul; break;
        case 3: Oh = g_qch; Ol = g_qcl; sc = SCALE; break;
        case 4: Oh = g_kch; Ol = g_kcl; break;
        default: break;
    }
    const __nv_bfloat16* Wth = g_wth + (size_t)z*DIMM*DIMM;
    const __nv_bfloat16* Wtl = g_wtl + (size_t)z*DIMM*DIMM;
    extern __shared__ __align__(16) char dynsm[];
    uint32_t base = smem_u32(dynsm);
    int tid = threadIdx.x, lane = tid & 31, wid = tid >> 5;
    int wm = wid >> 2, wn = wid & 3;
    int m0 = blockIdx.y*128, n0 = blockIdx.x*128;
    float acc[4][4][4] = {};

    auto load_stage = [&](int s, int k0) {
        uint32_t sb = base + s*STAGE128;
        ld_tile_cp(sb,            (const uint16_t*)g_xh, m0, k0, DIMM, tid);
        ld_tile_cp(sb +   BUF128, (const uint16_t*)g_xl, m0, k0, DIMM, tid);
        ld_tile_cp(sb + 2*BUF128, (const uint16_t*)Wth,  n0, k0, DIMM, tid);
        ld_tile_cp(sb + 3*BUF128, (const uint16_t*)Wtl,  n0, k0, DIMM, tid);
    };
    load_stage(0, 0); CP_COMMIT();
    for (int c = 0; c < 16; c++) {
        int cur = c & 1;
        if (c + 1 < 16) { load_stage(cur^1, (c+1)*32); CP_COMMIT(); CP_WAIT1(); }
        else CP_WAIT0();
        __syncthreads();
        uint32_t sb = base + cur*STAGE128;
        mma_chunk_ldm<4>(sb, sb+BUF128, sb+2*BUF128, sb+3*BUF128, acc, wm, wn, lane);
        __syncthreads();
    }
    int g = lane >> 2, q = lane & 3;
    #pragma unroll
    for (int mi = 0; mi < 4; mi++) {
        #pragma unroll
        for (int ni = 0; ni < 4; ni++) {
            int col = n0 + wn*32 + ni*8 + q*2;
            int h = col >> 6, dd = col & 63;
            #pragma unroll
            for (int rr = 0; rr < 2; rr++) {
                int m = m0 + wm*64 + mi*16 + g + rr*8;
                int b = m >> 10, tok = m & 1023;
                float v0 = acc[mi][ni][rr*2+0], v1 = acc[mi][ni][rr*2+1];
                if (z == 5) {
                    size_t tb = ((size_t)(b*HEADS + h)*DH + dd)*NTOK + tok;
                    g_vct[tb]        = __float2half(v0);
                    g_vct[tb + NTOK] = __float2half(v1);
                } else {
                    size_t oidx = ((size_t)(b*HEADS + h)*NTOK + tok)*DH + dd;
                    uint32_t hp, lp;
                    split2(v0*sc, v1*sc, hp, lp);
                    *(uint32_t*)&Oh[oidx] = hp;
                    *(uint32_t*)&Ol[oidx] = lp;
                }
            }
        }
    }
}

// =====================================================================
// k_t1sig_mma: bf16-split compute; epilogue -> fp16 split (t1) / single (sig)
// =====================================================================
__global__ __launch_bounds__(256,2) void k_t1sig_mma()
{
    int which = blockIdx.z >> 4;
    int bh    = blockIdx.z & 15;
    int bx = blockIdx.x, by = blockIdx.y;
    if (which == 0) { if (bx > by) return; }
    else            { if (bx < by) return; }
    size_t voff = (size_t)bh*NTOK*DH;
    const __nv_bfloat16* Ah_g = (which == 0 ? g_qch : g_quh) + voff;
    const __nv_bfloat16* Al_g = (which == 0 ? g_qcl : g_qul) + voff;
    const __nv_bfloat16* Bh_g = (which == 0 ? g_vuh : g_kuh) + voff;
    const __nv_bfloat16* Bl_g = (which == 0 ? g_vul : g_kul) + voff;
    __half* Oh = (which == 0 ? g_t1h : g_sg) + (size_t)bh*NTOK*NTOK;
    __half* Ol = g_t1l + (size_t)bh*NTOK*NTOK;   // used only for which==0

    extern __shared__ __align__(16) char dynsm[];
    uint32_t base = smem_u32(dynsm);
    int tid = threadIdx.x, lane = tid & 31, wid = tid >> 5;
    int wm = wid >> 2, wn = wid & 3;
    int i0 = by*128, j0b = bx*128;
    float acc[4][4][4] = {};

    auto load_stage = [&](int s, int k0) {
        uint32_t sb = base + s*STAGE128;
        ld_tile_cp(sb,            (const uint16_t*)Ah_g, i0,  k0, DH, tid);
        ld_tile_cp(sb +   BUF128, (const uint16_t*)Al_g, i0,  k0, DH, tid);
        ld_tile_cp(sb + 2*BUF128, (const uint16_t*)Bh_g, j0b, k0, DH, tid);
        ld_tile_cp(sb + 3*BUF128, (const uint16_t*)Bl_g, j0b, k0, DH, tid);
    };
    load_stage(0, 0); CP_COMMIT();
    for (int c = 0; c < 2; c++) {
        int cur = c & 1;
        if (c + 1 < 2) { load_stage(cur^1, 32); CP_COMMIT(); CP_WAIT1(); }
        else CP_WAIT0();
        __syncthreads();
        uint32_t sb = base + cur*STAGE128;
        mma_chunk_ldm<4>(sb, sb+BUF128, sb+2*BUF128, sb+3*BUF128, acc, wm, wn, lane);
        __syncthreads();
    }
    int g = lane >> 2, q = lane & 3;
    #pragma unroll
    for (int mi = 0; mi < 4; mi++) {
        #pragma unroll
        for (int ni = 0; ni < 4; ni++) {
            int j = j0b + wn*32 + ni*8 + q*2;
            #pragma unroll
            for (int rr = 0; rr < 2; rr++) {
                int i = i0 + wm*64 + mi*16 + g + rr*8;
                float s0 = acc[mi][ni][rr*2+0], s1 = acc[mi][ni][rr*2+1];
                size_t idx = (size_t)i*NTOK + j;
                if (which == 0) {
                    float o0 = (j   <= i) ? s0 : 0.f;
                    float o1 = (j+1 <= i) ? s1 : 0.f;
                    uint32_t hp, lp;
                    split2h(o0, o1, hp, lp);
                    *(uint32_t*)&Oh[idx] = hp;
                    *(uint32_t*)&Ol[idx] = lp;
                } else {
                    float o0 = (j   > i) ? 1.f/(1.f + __expf(-s0)) : 0.f;
                    float o1 = (j+1 > i) ? 1.f/(1.f + __expf(-s1)) : 0.f;
                    *(uint32_t*)&Oh[idx] = pack2h(o0, o1);
                }
            }
        }
    }
}

// =====================================================================
// k_su_mma: phase1 = fp16 2-product (t1 split x sig single);
//           phase2 = bf16 3-product (q_c x k_c)
// =====================================================================
__global__ __launch_bounds__(256,2) void k_su_mma()
{
    int bx = blockIdx.x, by = blockIdx.y, bh = blockIdx.z;
    if (bx > by) return;
    const __half* T1h = g_t1h + (size_t)bh*NTOK*NTOK;
    const __half* T1l = g_t1l + (size_t)bh*NTOK*NTOK;
    const __half* SG  = g_sg  + (size_t)bh*NTOK*NTOK;
    const __nv_bfloat16* Qh = g_qch + (size_t)bh*NTOK*DH;
    const __nv_bfloat16* Ql = g_qcl + (size_t)bh*NTOK*DH;
    const __nv_bfloat16* Kh = g_kch + (size_t)bh*NTOK*DH;
    const __nv_bfloat16* Kl = g_kcl + (size_t)bh*NTOK*DH;
    float* S = g_su + (size_t)bh*NTOK*NTOK;

    extern __shared__ __align__(16) char dynsm[];
    uint32_t base = smem_u32(dynsm);
    int tid = threadIdx.x, lane = tid & 31, wid = tid >> 5;
    int wm = wid >> 2, wn = wid & 3;
    int i0 = by*128, kx0 = bx*128;
    float acc[4][4][4] = {};

    int n1 = (by - bx + 1) * 4;      // phase-1 chunks
    int ntot = n1 + 2;

    auto load_stage = [&](int s, int c) {
        uint32_t sb = base + s*STAGE128;
        if (c < n1) {
            int j0 = bx*128 + c*32;
            ld_tile_cp(sb,            (const uint16_t*)T1h, i0,  j0, NTOK, tid);
            ld_tile_cp(sb +   BUF128, (const uint16_t*)T1l, i0,  j0, NTOK, tid);
            ld_tile_cp(sb + 2*BUF128, (const uint16_t*)SG,  kx0, j0, NTOK, tid);
        } else {
            int k0 = (c - n1)*32;
            ld_tile_cp(sb,            (const uint16_t*)Qh, i0,  k0, DH, tid);
            ld_tile_cp(sb +   BUF128, (const uint16_t*)Ql, i0,  k0, DH, tid);
            ld_tile_cp(sb + 2*BUF128, (const uint16_t*)Kh, kx0, k0, DH, tid);
            ld_tile_cp(sb + 3*BUF128, (const uint16_t*)Kl, kx0, k0, DH, tid);
        }
    };
    load_stage(0, 0); CP_COMMIT();
    for (int c = 0; c < ntot; c++) {
        int cur = c & 1;
        if (c + 1 < ntot) { load_stage(cur^1, c+1); CP_COMMIT(); CP_WAIT1(); }
        else CP_WAIT0();
        __syncthreads();
        if (c == n1) {   // phase boundary: acc = -silu(acc), registers only
            #pragma unroll
            for (int mi = 0; mi < 4; mi++)
                #pragma unroll
                for (int ni = 0; ni < 4; ni++)
                    #pragma unroll
                    for (int e = 0; e < 4; e++) {
                        float su = acc[mi][ni][e];
                        acc[mi][ni][e] = -su / (1.f + __expf(-su));
                    }
        }
        uint32_t sb = base + cur*STAGE128;
        if (c < n1)
            mma_chunk_2p<4>(sb, sb+BUF128, sb+2*BUF128, acc, wm, wn, lane);
        else
            mma_chunk_ldm<4>(sb, sb+BUF128, sb+2*BUF128, sb+3*BUF128, acc, wm, wn, lane);
        __syncthreads();
    }
    int g = lane >> 2, q = lane & 3;
    #pragma unroll
    for (int mi = 0; mi < 4; mi++) {
        #pragma unroll
        for (int ni = 0; ni < 4; ni++) {
            int k = kx0 + wn*32 + ni*8 + q*2;
            #pragma unroll
            for (int rr = 0; rr < 2; rr++) {
                int i = i0 + wm*64 + mi*16 + g + rr*8;
                float v0 = (k   <= i) ? acc[mi][ni][rr*2+0] : -1e30f;
                float v1 = (k+1 <= i) ? acc[mi][ni][rr*2+1] : -1e30f;
                *(float2*)&S[(size_t)i*NTOK + k] = make_float2(v0, v1);
            }
        }
    }
}

// =====================================================================
// k_softmax: fp32 in, single fp16 probs out
// =====================================================================
__global__ __launch_bounds__(256) void k_softmax()
{
    int i  = blockIdx.x;
    int bh = blockIdx.y;
    size_t roff = (size_t)bh*NTOK*NTOK + (size_t)i*NTOK;
    const float* S = g_su + roff;
    __half* P = g_p + roff;
    int L = i + 1;
    int wlen = ((i >> 7) + 1) << 7;
    int tid = threadIdx.x;
    int k0 = tid*4;
    __shared__ float red[256];
    float4 v = *(const float4*)&S[k0];
    float x[4] = {v.x, v.y, v.z, v.w};
    float mx = -1e30f;
    #pragma unroll
    for (int l = 0; l < 4; l++) {
        if (k0 + l >= L) x[l] = -1e30f;
        mx = fmaxf(mx, x[l]);
    }
    red[tid] = mx; __syncthreads();
    for (int s = 128; s > 0; s >>= 1) {
        if (tid < s) red[tid] = fmaxf(red[tid], red[tid+s]);
        __syncthreads();
    }
    mx = red[0]; __syncthreads();
    float sum = 0.f;
    #pragma unroll
    for (int l = 0; l < 4; l++) {
        x[l] = (k0 + l < L) ? __expf(x[l] - mx) : 0.f;
        sum += x[l];
    }
    red[tid] = sum; __syncthreads();
    for (int s = 128; s > 0; s >>= 1) {
        if (tid < s) red[tid] += red[tid+s];
        __syncthreads();
    }
    float inv = 1.f / red[0];
    if (k0 < wlen) {
        *(uint2*)&P[k0] = make_uint2(pack2h(x[0]*inv, x[1]*inv),
                                     pack2h(x[2]*inv, x[3]*inv));
    }
}

// =====================================================================
// k_av_mma: O = P @ V, fp16 single-product pipelined. 128x64, warps 4x2.
// =====================================================================
__global__ __launch_bounds__(256,2) void k_av_mma()
{
    int by = blockIdx.x, bh = blockIdx.y;
    int b = bh >> 3, h = bh & 7;
    const __half* P  = g_p   + (size_t)bh*NTOK*NTOK;
    const __half* Vt = g_vct + (size_t)bh*DH*NTOK;

    extern __shared__ __align__(16) char dynsm[];
    uint32_t base = smem_u32(dynsm);
    int tid = threadIdx.x, lane = tid & 31, wid = tid >> 5;
    int wm = wid >> 1, wn = wid & 1;
    int i0 = by*128;
    float acc[2][4][4] = {};
    int nch = (by + 1) * 4;

    auto load_stage = [&](int s, int c) {
        int k0 = c*32;
        uint32_t sb = base + s*STAGE_AV;
        ld_tile_cp(sb, (const uint16_t*)P, i0, k0, NTOK, tid);
        if (tid < 128)
            ld_tile_cp(sb + BUF128, (const uint16_t*)Vt, 0, k0, NTOK, tid);
    };
    load_stage(0, 0); CP_COMMIT();
    for (int c = 0; c < nch; c++) {
        int cur = c & 1;
        if (c + 1 < nch) { load_stage(cur^1, c+1); CP_COMMIT(); CP_WAIT1(); }
        else CP_WAIT0();
        __syncthreads();
        uint32_t sb = base + cur*STAGE_AV;
        mma_chunk_1p<2>(sb, sb+BUF128, acc, wm, wn, lane);
        __syncthreads();
    }
    int g = lane >> 2, q = lane & 3;
    #pragma unroll
    for (int mi = 0; mi < 2; mi++) {
        #pragma unroll
        for (int ni = 0; ni < 4; ni++) {
            int d = wn*32 + ni*8 + q*2;
            #pragma unroll
            for (int rr = 0; rr < 2; rr++) {
                int i = i0 + wm*32 + mi*16 + g + rr*8;
                size_t row = (size_t)(b*NTOK + i)*DIMM + h*DH + d;
                uint32_t hp, lp;
                split2(acc[mi][ni][rr*2+0], acc[mi][ni][rr*2+1], hp, lp);
                *(uint32_t*)&g_ohh[row] = hp;
                *(uint32_t*)&g_ohl[row] = lp;
            }
        }
    }
}

// =====================================================================
// k_outproj_mma: pipelined, 16 chunks (bf16 3-product)
// =====================================================================
__global__ __launch_bounds__(256,2) void k_outproj_mma(float* __restrict__ Out)
{
    const __nv_bfloat16* Wth = g_wth + (size_t)6*DIMM*DIMM;
    const __nv_bfloat16* Wtl = g_wtl + (size_t)6*DIMM*DIMM;
    extern __shared__ __align__(16) char dynsm[];
    uint32_t base = smem_u32(dynsm);
    int tid = threadIdx.x, lane = tid & 31, wid = tid >> 5;
    int wm = wid >> 2, wn = wid & 3;
    int m0 = blockIdx.y*128, n0 = blockIdx.x*128;
    float acc[4][4][4] = {};

    auto load_stage = [&](int s, int k0) {
        uint32_t sb = base + s*STAGE128;
        ld_tile_cp(sb,            (const uint16_t*)g_ohh, m0, k0, DIMM, tid);
        ld_tile_cp(sb +   BUF128, (const uint16_t*)g_ohl, m0, k0, DIMM, tid);
        ld_tile_cp(sb + 2*BUF128, (const uint16_t*)Wth,   n0, k0, DIMM, tid);
        ld_tile_cp(sb + 3*BUF128, (const uint16_t*)Wtl,   n0, k0, DIMM, tid);
    };
    load_stage(0, 0); CP_COMMIT();
    for (int c = 0; c < 16; c++) {
        int cur = c & 1;
        if (c + 1 < 16) { load_stage(cur^1, (c+1)*32); CP_COMMIT(); CP_WAIT1(); }
        else CP_WAIT0();
        __syncthreads();
        uint32_t sb = base + cur*STAGE128;
        mma_chunk_ldm<4>(sb, sb+BUF128, sb+2*BUF128, sb+3*BUF128, acc, wm, wn, lane);
        __syncthreads();
    }
    int g = lane >> 2, q = lane & 3;
    #pragma unroll
    for (int mi = 0; mi < 4; mi++) {
        #pragma unroll
        for (int ni = 0; ni < 4; ni++) {
            int nn = n0 + wn*32 + ni*8 + q*2;
            #pragma unroll
            for (int rr = 0; rr < 2; rr++) {
                int m = m0 + wm*64 + mi*16 + g + rr*8;
                *(float2*)&Out[(size_t)m*DIMM + nn] =
                    make_float2(acc[mi][ni][rr*2+0], acc[mi][ni][rr*2+1]);
            }
        }
    }
}

extern "C" void kernel_launch(void* const* d_in, const int* in_sizes, int n_in,
                              void* d_out, int out_size)
{
    const float* x   = (const float*)d_in[0];
    const float* wqu = (const float*)d_in[1];
    const float* wku = (const float*)d_in[2];
    const float* wvu = (const float*)d_in[3];
    const float* wqc = (const float*)d_in[4];
    const float* wkc = (const float*)d_in[5];
    const float* wvc = (const float*)d_in[6];
    const float* wout= (const float*)d_in[7];
    float* out = (float*)d_out;

    static int attr_done = 0;
    if (!attr_done) {
        cudaFuncSetAttribute(k_proj_mma,    cudaFuncAttributeMaxDynamicSharedMemorySize, SMEM128);
        cudaFuncSetAttribute(k_t1sig_mma,   cudaFuncAttributeMaxDynamicSharedMemorySize, SMEM128);
        cudaFuncSetAttribute(k_su_mma,      cudaFuncAttributeMaxDynamicSharedMemorySize, SMEM128);
        cudaFuncSetAttribute(k_av_mma,      cudaFuncAttributeMaxDynamicSharedMemorySize, SMEM_AV);
        cudaFuncSetAttribute(k_outproj_mma, cudaFuncAttributeMaxDynamicSharedMemorySize, SMEM128);
        attr_done = 1;
    }

    k_prep_x    <<<1024, 256>>>(x);
    k_prep_w    <<<dim3(16,16,7), dim3(32,8)>>>(wqu, wku, wvu, wqc, wkc, wvc, wout);
    k_proj_mma  <<<dim3(4, 16, 6), 256, SMEM128>>>();
    k_t1sig_mma <<<dim3(8, 8, 32), 256, SMEM128>>>();
    k_su_mma    <<<dim3(8, 8, 16), 256, SMEM128>>>();
    k_softmax   <<<dim3(1024,16),  256>>>();
    k_av_mma    <<<dim3(8, 16),    256, SMEM_AV>>>();
    k_outproj_mma<<<dim3(4, 16),   256, SMEM128>>>(out);
}

// round 13
// speedup vs baseline: 2.7693x; 1.0142x over previous
#include <cuda_runtime.h>
#include <cuda_bf16.h>
#include <cuda_fp16.h>
#include <math.h>
#include <stdint.h>

#define NTOK 1024
#define BATCH 2
#define HEADS 8
#define DH 64
#define BHN (BATCH*HEADS)   /* 16 */
#define DIMM 512
#define SCALE 0.125f
#define ST 40               /* smem row stride in 16-bit elems (80B, 16B-aligned, conflict-free) */

#define BUF128   (128*ST*2)         /* 10240 B  */
#define STAGE128 (4*BUF128)         /* 40960 B  */
#define SMEM128  (2*STAGE128)       /* 81920 B  */
#define BUF64    (64*ST*2)          /* 5120 B   */
#define STAGE_AV (BUF128 + BUF64)   /* 15360 B  */
#define SMEM_AV  (2*STAGE_AV)       /* 30720 B  */

// ---- scratch ----
__device__ float g_su[(size_t)BHN*NTOK*NTOK];   // pre-softmax scores

// bf16 hi/lo split operands (projection GEMMs)
__device__ __nv_bfloat16 g_xh[2048*DIMM];
__device__ __nv_bfloat16 g_xl[2048*DIMM];
__device__ __nv_bfloat16 g_wth[7*DIMM*DIMM];   // transposed weights [z][n][k]
__device__ __nv_bfloat16 g_wtl[7*DIMM*DIMM];
__device__ __nv_bfloat16 g_ohh[2048*DIMM];     // attn@v_c, [m][h*64+d] split
__device__ __nv_bfloat16 g_ohl[2048*DIMM];

// fp16 operands (attention-side)
__device__ __half g_quh[BHN*NTOK*DH];            // SCALE*q_u fp16 split
__device__ __half g_qul[BHN*NTOK*DH];
__device__ __half g_ku [BHN*NTOK*DH];            // k_u single fp16
__device__ __half g_vu [BHN*NTOK*DH];            // v_u single fp16
__device__ __half g_qch[BHN*NTOK*DH];            // SCALE*q_c fp16 split
__device__ __half g_qcl[BHN*NTOK*DH];
__device__ __half g_kch[BHN*NTOK*DH];            // k_c fp16 split
__device__ __half g_kcl[BHN*NTOK*DH];
__device__ __half g_t1h[(size_t)BHN*NTOK*NTOK];  // term1 fp16 split
__device__ __half g_t1l[(size_t)BHN*NTOK*NTOK];
__device__ __half g_sg [(size_t)BHN*NTOK*NTOK];  // sig single fp16
__device__ __half g_p  [(size_t)BHN*NTOK*NTOK];  // probs single fp16
__device__ __half g_vct[BHN*DH*NTOK];            // v_c transposed [bh][d][tok] fp16

// k_su heavy-first tile map: (bx,by) sorted by descending by-bx
__device__ __constant__ uint8_t su_map[36][2] = {
    {0,7},
    {0,6},{1,7},
    {0,5},{1,6},{2,7},
    {0,4},{1,5},{2,6},{3,7},
    {0,3},{1,4},{2,5},{3,6},{4,7},
    {0,2},{1,3},{2,4},{3,5},{4,6},{5,7},
    {0,1},{1,2},{2,3},{3,4},{4,5},{5,6},{6,7},
    {0,0},{1,1},{2,2},{3,3},{4,4},{5,5},{6,6},{7,7}
};

// =====================================================================
// helpers
// =====================================================================
#define MMA_BF16(c, a0,a1,a2,a3, b0,b1)                                  \
    asm volatile("mma.sync.aligned.m16n8k16.row.col.f32.bf16.bf16.f32 "  \
        "{%0,%1,%2,%3}, {%4,%5,%6,%7}, {%8,%9}, {%0,%1,%2,%3};"          \
        : "+f"((c)[0]), "+f"((c)[1]), "+f"((c)[2]), "+f"((c)[3])         \
        : "r"(a0), "r"(a1), "r"(a2), "r"(a3), "r"(b0), "r"(b1))

#define MMA_F16(c, a0,a1,a2,a3, b0,b1)                                   \
    asm volatile("mma.sync.aligned.m16n8k16.row.col.f32.f16.f16.f32 "    \
        "{%0,%1,%2,%3}, {%4,%5,%6,%7}, {%8,%9}, {%0,%1,%2,%3};"          \
        : "+f"((c)[0]), "+f"((c)[1]), "+f"((c)[2]), "+f"((c)[3])         \
        : "r"(a0), "r"(a1), "r"(a2), "r"(a3), "r"(b0), "r"(b1))

#define LDMX4(r0,r1,r2,r3, addr)                                         \
    asm volatile("ldmatrix.sync.aligned.m8n8.x4.shared.b16 {%0,%1,%2,%3}, [%4];" \
        : "=r"(r0),"=r"(r1),"=r"(r2),"=r"(r3) : "r"(addr))

#define CP_COMMIT() asm volatile("cp.async.commit_group;" ::: "memory")
#define CP_WAIT0()  asm volatile("cp.async.wait_group 0;" ::: "memory")

__device__ __forceinline__ void cp16(uint32_t d, const void* s) {
    asm volatile("cp.async.cg.shared.global [%0], [%1], 16;" :: "r"(d), "l"(s));
}

__device__ __forceinline__ uint32_t smem_u32(const void* p) {
    uint32_t a;
    asm("{ .reg .u64 t; cvta.to.shared.u64 t, %1; cvt.u32.u64 %0, t; }"
        : "=r"(a) : "l"(p));
    return a;
}

// packed bf16 hi/lo split of a pair: hp/lp hold {lo16=v0, hi16=v1}
__device__ __forceinline__ void split2(float v0, float v1, uint32_t& hp, uint32_t& lp)
{
    asm("cvt.rn.bf16x2.f32 %0, %1, %2;" : "=r"(hp) : "f"(v1), "f"(v0));
    float h0 = __uint_as_float(hp << 16);
    float h1 = __uint_as_float(hp & 0xFFFF0000u);
    asm("cvt.rn.bf16x2.f32 %0, %1, %2;" : "=r"(lp) : "f"(v1 - h1), "f"(v0 - h0));
}

// packed fp16 hi/lo split of a pair
__device__ __forceinline__ void split2h(float v0, float v1, uint32_t& hp, uint32_t& lp)
{
    asm("cvt.rn.f16x2.f32 %0, %1, %2;" : "=r"(hp) : "f"(v1), "f"(v0));
    __half2 h2 = *reinterpret_cast<__half2*>(&hp);
    float h0 = __low2float(h2), h1 = __high2float(h2);
    asm("cvt.rn.f16x2.f32 %0, %1, %2;" : "=r"(lp) : "f"(v1 - h1), "f"(v0 - h0));
}

__device__ __forceinline__ uint32_t pack2h(float v0, float v1)
{
    uint32_t r;
    asm("cvt.rn.f16x2.f32 %0, %1, %2;" : "=r"(r) : "f"(v1), "f"(v0));
    return r;
}

__device__ __forceinline__ void split_bf16(float v, __nv_bfloat16& h, __nv_bfloat16& l)
{
    h = __float2bfloat16(v);
    l = __float2bfloat16(v - __bfloat162float(h));
}

// async load 128 rows x 32 col 16-bit tile into smem (row-major, stride ST)
__device__ __forceinline__ void ld_tile_cp(uint32_t dst, const uint16_t* g,
                                           int row0, int k0, int ldg, int tid)
{
    int r = tid >> 1, h = tid & 1;
    const uint16_t* s = g + (size_t)(row0 + r)*ldg + k0 + h*16;
    uint32_t d = dst + (uint32_t)((r*ST + h*16)*2);
    cp16(d, s); cp16(d + 16, s + 8);
}

// =====================================================================
// mma chunk variants (ldmatrix-based, 32-k chunk)
// =====================================================================
// 3-product bf16 split x split
template<int MI>
__device__ __forceinline__ void mma_chunk_3b(
    uint32_t aAh, uint32_t aAl, uint32_t aBh, uint32_t aBl,
    float (&acc)[MI][4][4], int wm, int wn, int lane)
{
    int lr = lane & 15;
    int lc = (lane >> 4) << 3;
    int bl_ = lane & 7;
    int bn = ((lane >> 4) & 1) << 3;
    int bk = ((lane >> 3) & 1) << 3;
    uint32_t aoff = (uint32_t)(((wm*(MI*16) + lr)*ST + lc) * 2);
    uint32_t boff = (uint32_t)(((wn*32 + bn + bl_)*ST + bk) * 2);
    #pragma unroll
    for (int ks = 0; ks < 2; ks++) {
        uint32_t kb = (uint32_t)(ks * 32);
        uint32_t bhf[4][2], blf[4][2];
        LDMX4(bhf[0][0], bhf[0][1], bhf[1][0], bhf[1][1], aBh + boff + kb);
        LDMX4(bhf[2][0], bhf[2][1], bhf[3][0], bhf[3][1], aBh + boff + kb + 16*ST*2);
        LDMX4(blf[0][0], blf[0][1], blf[1][0], blf[1][1], aBl + boff + kb);
        LDMX4(blf[2][0], blf[2][1], blf[3][0], blf[3][1], aBl + boff + kb + 16*ST*2);
        #pragma unroll
        for (int mi = 0; mi < MI; mi++) {
            uint32_t ao = aoff + kb + (uint32_t)(mi*16*ST*2);
            uint32_t ah0,ah1,ah2,ah3, al0,al1,al2,al3;
            LDMX4(ah0,ah1,ah2,ah3, aAh + ao);
            LDMX4(al0,al1,al2,al3, aAl + ao);
            #pragma unroll
            for (int ni = 0; ni < 4; ni++) {
                MMA_BF16(acc[mi][ni], ah0,ah1,ah2,ah3, bhf[ni][0], bhf[ni][1]);
                MMA_BF16(acc[mi][ni], ah0,ah1,ah2,ah3, blf[ni][0], blf[ni][1]);
                MMA_BF16(acc[mi][ni], al0,al1,al2,al3, bhf[ni][0], bhf[ni][1]);
            }
        }
    }
}

// 3-product fp16 split x split
template<int MI>
__device__ __forceinline__ void mma_chunk_3h(
    uint32_t aAh, uint32_t aAl, uint32_t aBh, uint32_t aBl,
    float (&acc)[MI][4][4], int wm, int wn, int lane)
{
    int lr = lane & 15;
    int lc = (lane >> 4) << 3;
    int bl_ = lane & 7;
    int bn = ((lane >> 4) & 1) << 3;
    int bk = ((lane >> 3) & 1) << 3;
    uint32_t aoff = (uint32_t)(((wm*(MI*16) + lr)*ST + lc) * 2);
    uint32_t boff = (uint32_t)(((wn*32 + bn + bl_)*ST + bk) * 2);
    #pragma unroll
    for (int ks = 0; ks < 2; ks++) {
        uint32_t kb = (uint32_t)(ks * 32);
        uint32_t bhf[4][2], blf[4][2];
        LDMX4(bhf[0][0], bhf[0][1], bhf[1][0], bhf[1][1], aBh + boff + kb);
        LDMX4(bhf[2][0], bhf[2][1], bhf[3][0], bhf[3][1], aBh + boff + kb + 16*ST*2);
        LDMX4(blf[0][0], blf[0][1], blf[1][0], blf[1][1], aBl + boff + kb);
        LDMX4(blf[2][0], blf[2][1], blf[3][0], blf[3][1], aBl + boff + kb + 16*ST*2);
        #pragma unroll
        for (int mi = 0; mi < MI; mi++) {
            uint32_t ao = aoff + kb + (uint32_t)(mi*16*ST*2);
            uint32_t ah0,ah1,ah2,ah3, al0,al1,al2,al3;
            LDMX4(ah0,ah1,ah2,ah3, aAh + ao);
            LDMX4(al0,al1,al2,al3, aAl + ao);
            #pragma unroll
            for (int ni = 0; ni < 4; ni++) {
                MMA_F16(acc[mi][ni], ah0,ah1,ah2,ah3, bhf[ni][0], bhf[ni][1]);
                MMA_F16(acc[mi][ni], ah0,ah1,ah2,ah3, blf[ni][0], blf[ni][1]);
                MMA_F16(acc[mi][ni], al0,al1,al2,al3, bhf[ni][0], bhf[ni][1]);
            }
        }
    }
}

// 2-product fp16: A split (hi/lo) x B single
template<int MI>
__device__ __forceinline__ void mma_chunk_2p(
    uint32_t aAh, uint32_t aAl, uint32_t aB,
    float (&acc)[MI][4][4], int wm, int wn, int lane)
{
    int lr = lane & 15;
    int lc = (lane >> 4) << 3;
    int bl_ = lane & 7;
    int bn = ((lane >> 4) & 1) << 3;
    int bk = ((lane >> 3) & 1) << 3;
    uint32_t aoff = (uint32_t)(((wm*(MI*16) + lr)*ST + lc) * 2);
    uint32_t boff = (uint32_t)(((wn*32 + bn + bl_)*ST + bk) * 2);
    #pragma unroll
    for (int ks = 0; ks < 2; ks++) {
        uint32_t kb = (uint32_t)(ks * 32);
        uint32_t bf[4][2];
        LDMX4(bf[0][0], bf[0][1], bf[1][0], bf[1][1], aB + boff + kb);
        LDMX4(bf[2][0], bf[2][1], bf[3][0], bf[3][1], aB + boff + kb + 16*ST*2);
        #pragma unroll
        for (int mi = 0; mi < MI; mi++) {
            uint32_t ao = aoff + kb + (uint32_t)(mi*16*ST*2);
            uint32_t ah0,ah1,ah2,ah3, al0,al1,al2,al3;
            LDMX4(ah0,ah1,ah2,ah3, aAh + ao);
            LDMX4(al0,al1,al2,al3, aAl + ao);
            #pragma unroll
            for (int ni = 0; ni < 4; ni++) {
                MMA_F16(acc[mi][ni], ah0,ah1,ah2,ah3, bf[ni][0], bf[ni][1]);
                MMA_F16(acc[mi][ni], al0,al1,al2,al3, bf[ni][0], bf[ni][1]);
            }
        }
    }
}

// 1-product fp16
template<int MI>
__device__ __forceinline__ void mma_chunk_1p(
    uint32_t aA, uint32_t aB,
    float (&acc)[MI][4][4], int wm, int wn, int lane)
{
    int lr = lane & 15;
    int lc = (lane >> 4) << 3;
    int bl_ = lane & 7;
    int bn = ((lane >> 4) & 1) << 3;
    int bk = ((lane >> 3) & 1) << 3;
    uint32_t aoff = (uint32_t)(((wm*(MI*16) + lr)*ST + lc) * 2);
    uint32_t boff = (uint32_t)(((wn*32 + bn + bl_)*ST + bk) * 2);
    #pragma unroll
    for (int ks = 0; ks < 2; ks++) {
        uint32_t kb = (uint32_t)(ks * 32);
        uint32_t bf[4][2];
        LDMX4(bf[0][0], bf[0][1], bf[1][0], bf[1][1], aB + boff + kb);
        LDMX4(bf[2][0], bf[2][1], bf[3][0], bf[3][1], aB + boff + kb + 16*ST*2);
        #pragma unroll
        for (int mi = 0; mi < MI; mi++) {
            uint32_t ao = aoff + kb + (uint32_t)(mi*16*ST*2);
            uint32_t a0,a1,a2,a3;
            LDMX4(a0,a1,a2,a3, aA + ao);
            #pragma unroll
            for (int ni = 0; ni < 4; ni++)
                MMA_F16(acc[mi][ni], a0,a1,a2,a3, bf[ni][0], bf[ni][1]);
        }
    }
}

// =====================================================================
// prep kernels
// =====================================================================
__global__ __launch_bounds__(256) void k_prep_x(const float* __restrict__ X)
{
    int idx = (blockIdx.x*256 + threadIdx.x)*4;
    float4 v = *(const float4*)&X[idx];
    uint32_t h0, l0, h1, l1;
    split2(v.x, v.y, h0, l0);
    split2(v.z, v.w, h1, l1);
    *(uint2*)&g_xh[idx] = make_uint2(h0, h1);
    *(uint2*)&g_xl[idx] = make_uint2(l0, l1);
}

__global__ void k_prep_w(
    const float* __restrict__ w0, const float* __restrict__ w1,
    const float* __restrict__ w2, const float* __restrict__ w3,
    const float* __restrict__ w4, const float* __restrict__ w5,
    const float* __restrict__ w6)
{
    const float* W;
    switch (blockIdx.z) {
        case 0: W = w0; break; case 1: W = w1; break; case 2: W = w2; break;
        case 3: W = w3; break; case 4: W = w4; break; case 5: W = w5; break;
        default: W = w6; break;
    }
    __shared__ float t[32][33];
    int tx = threadIdx.x, ty = threadIdx.y;   // (32, 8)
    int k0 = blockIdx.y*32, n0 = blockIdx.x*32;
    #pragma unroll
    for (int i = 0; i < 4; i++)
        t[ty + i*8][tx] = W[(size_t)(k0 + ty + i*8)*DIMM + n0 + tx];
    __syncthreads();
    size_t zoff = (size_t)blockIdx.z * DIMM * DIMM;
    #pragma unroll
    for (int i = 0; i < 4; i++) {
        float v = t[tx][ty + i*8];
        __nv_bfloat16 h, l; split_bf16(v, h, l);
        size_t o = zoff + (size_t)(n0 + ty + i*8)*DIMM + k0 + tx;
        g_wth[o] = h; g_wtl[o] = l;
    }
}

// =====================================================================
// k_proj_mma: 6 projections -> fp16 outputs per role
// =====================================================================
__global__ __launch_bounds__(256,2) void k_proj_mma()
{
    int z = blockIdx.z;
    __half *Oh = 0, *Ol = 0;
    float sc = 1.f;
    int mode;   // 0=split, 1=single, 2=vct
    switch (z) {
        case 0: Oh = g_quh; Ol = g_qul; sc = SCALE; mode = 0; break;
        case 1: Oh = g_ku;  mode = 1; break;
        case 2: Oh = g_vu;  mode = 1; break;
        case 3: Oh = g_qch; Ol = g_qcl; sc = SCALE; mode = 0; break;
        case 4: Oh = g_kch; Ol = g_kcl; mode = 0; break;
        default: mode = 2; break;
    }
    const __nv_bfloat16* Wth = g_wth + (size_t)z*DIMM*DIMM;
    const __nv_bfloat16* Wtl = g_wtl + (size_t)z*DIMM*DIMM;
    extern __shared__ __align__(16) char dynsm[];
    uint32_t base = smem_u32(dynsm);
    int tid = threadIdx.x, lane = tid & 31, wid = tid >> 5;
    int wm = wid >> 2, wn = wid & 3;
    int m0 = blockIdx.y*128, n0 = blockIdx.x*128;
    float acc[4][4][4] = {};

    auto load_stage = [&](int s, int k0) {
        uint32_t sb = base + s*STAGE128;
        ld_tile_cp(sb,            (const uint16_t*)g_xh, m0, k0, DIMM, tid);
        ld_tile_cp(sb +   BUF128, (const uint16_t*)g_xl, m0, k0, DIMM, tid);
        ld_tile_cp(sb + 2*BUF128, (const uint16_t*)Wth,  n0, k0, DIMM, tid);
        ld_tile_cp(sb + 3*BUF128, (const uint16_t*)Wtl,  n0, k0, DIMM, tid);
    };
    load_stage(0, 0); CP_COMMIT();
    for (int c = 0; c < 16; c++) {
        CP_WAIT0();
        __syncthreads();
        if (c + 1 < 16) { load_stage((c+1)&1, (c+1)*32); CP_COMMIT(); }
        uint32_t sb = base + (c&1)*STAGE128;
        mma_chunk_3b<4>(sb, sb+BUF128, sb+2*BUF128, sb+3*BUF128, acc, wm, wn, lane);
    }
    int g = lane >> 2, q = lane & 3;
    #pragma unroll
    for (int mi = 0; mi < 4; mi++) {
        #pragma unroll
        for (int ni = 0; ni < 4; ni++) {
            int col = n0 + wn*32 + ni*8 + q*2;
            int h = col >> 6, dd = col & 63;
            #pragma unroll
            for (int rr = 0; rr < 2; rr++) {
                int m = m0 + wm*64 + mi*16 + g + rr*8;
                int b = m >> 10, tok = m & 1023;
                float v0 = acc[mi][ni][rr*2+0], v1 = acc[mi][ni][rr*2+1];
                if (mode == 2) {
                    size_t tb = ((size_t)(b*HEADS + h)*DH + dd)*NTOK + tok;
                    g_vct[tb]        = __float2half(v0);
                    g_vct[tb + NTOK] = __float2half(v1);
                } else {
                    size_t oidx = ((size_t)(b*HEADS + h)*NTOK + tok)*DH + dd;
                    if (mode == 1) {
                        *(uint32_t*)&Oh[oidx] = pack2h(v0, v1);
                    } else {
                        uint32_t hp, lp;
                        split2h(v0*sc, v1*sc, hp, lp);
                        *(uint32_t*)&Oh[oidx] = hp;
                        *(uint32_t*)&Ol[oidx] = lp;
                    }
                }
            }
        }
    }
}

// =====================================================================
// k_t1sig_mma: fp16 2-product. which=0: t1 = (SCALE q_c split) @ v_u^T;
//              which=1: sig from (SCALE q_u split) @ k_u^T
// =====================================================================
__global__ __launch_bounds__(256,2) void k_t1sig_mma()
{
    int which = blockIdx.z >> 4;
    int bh    = blockIdx.z & 15;
    int bx = blockIdx.x, by = blockIdx.y;
    if (which == 0) { if (bx > by) return; }
    else            { if (bx < by) return; }
    size_t voff = (size_t)bh*NTOK*DH;
    const __half* Ah_g = (which == 0 ? g_qch : g_quh) + voff;
    const __half* Al_g = (which == 0 ? g_qcl : g_qul) + voff;
    const __half* B_g  = (which == 0 ? g_vu  : g_ku ) + voff;
    __half* Oh = (which == 0 ? g_t1h : g_sg) + (size_t)bh*NTOK*NTOK;
    __half* Ol = g_t1l + (size_t)bh*NTOK*NTOK;   // only for which==0

    extern __shared__ __align__(16) char dynsm[];
    uint32_t base = smem_u32(dynsm);
    int tid = threadIdx.x, lane = tid & 31, wid = tid >> 5;
    int wm = wid >> 2, wn = wid & 3;
    int i0 = by*128, j0b = bx*128;
    float acc[4][4][4] = {};

    auto load_stage = [&](int s, int k0) {
        uint32_t sb = base + s*STAGE128;
        ld_tile_cp(sb,            (const uint16_t*)Ah_g, i0,  k0, DH, tid);
        ld_tile_cp(sb +   BUF128, (const uint16_t*)Al_g, i0,  k0, DH, tid);
        ld_tile_cp(sb + 2*BUF128, (const uint16_t*)B_g,  j0b, k0, DH, tid);
    };
    load_stage(0, 0); CP_COMMIT();
    for (int c = 0; c < 2; c++) {
        CP_WAIT0();
        __syncthreads();
        if (c + 1 < 2) { load_stage((c+1)&1, 32); CP_COMMIT(); }
        uint32_t sb = base + (c&1)*STAGE128;
        mma_chunk_2p<4>(sb, sb+BUF128, sb+2*BUF128, acc, wm, wn, lane);
    }
    int g = lane >> 2, q = lane & 3;
    #pragma unroll
    for (int mi = 0; mi < 4; mi++) {
        #pragma unroll
        for (int ni = 0; ni < 4; ni++) {
            int j = j0b + wn*32 + ni*8 + q*2;
            #pragma unroll
            for (int rr = 0; rr < 2; rr++) {
                int i = i0 + wm*64 + mi*16 + g + rr*8;
                float s0 = acc[mi][ni][rr*2+0], s1 = acc[mi][ni][rr*2+1];
                size_t idx = (size_t)i*NTOK + j;
                if (which == 0) {
                    float o0 = (j   <= i) ? s0 : 0.f;
                    float o1 = (j+1 <= i) ? s1 : 0.f;
                    uint32_t hp, lp;
                    split2h(o0, o1, hp, lp);
                    *(uint32_t*)&Oh[idx] = hp;
                    *(uint32_t*)&Ol[idx] = lp;
                } else {
                    float o0 = (j   > i) ? 1.f/(1.f + __expf(-s0)) : 0.f;
                    float o1 = (j+1 > i) ? 1.f/(1.f + __expf(-s1)) : 0.f;
                    *(uint32_t*)&Oh[idx] = pack2h(o0, o1);
                }
            }
        }
    }
}

// =====================================================================
// k_su_mma: phase1 fp16 2p (t1 split x sig); phase2 fp16 3p (q_c x k_c).
// Heavy-first triangular grid via su_map.
// =====================================================================
__global__ __launch_bounds__(256,2) void k_su_mma()
{
    int bx = su_map[blockIdx.x][0], by = su_map[blockIdx.x][1];
    int bh = blockIdx.y;
    const __half* T1h = g_t1h + (size_t)bh*NTOK*NTOK;
    const __half* T1l = g_t1l + (size_t)bh*NTOK*NTOK;
    const __half* SG  = g_sg  + (size_t)bh*NTOK*NTOK;
    const __half* Qh = g_qch + (size_t)bh*NTOK*DH;
    const __half* Ql = g_qcl + (size_t)bh*NTOK*DH;
    const __half* Kh = g_kch + (size_t)bh*NTOK*DH;
    const __half* Kl = g_kcl + (size_t)bh*NTOK*DH;
    float* S = g_su + (size_t)bh*NTOK*NTOK;

    extern __shared__ __align__(16) char dynsm[];
    uint32_t base = smem_u32(dynsm);
    int tid = threadIdx.x, lane = tid & 31, wid = tid >> 5;
    int wm = wid >> 2, wn = wid & 3;
    int i0 = by*128, kx0 = bx*128;
    float acc[4][4][4] = {};

    int n1 = (by - bx + 1) * 4;
    int ntot = n1 + 2;

    auto load_stage = [&](int s, int c) {
        uint32_t sb = base + s*STAGE128;
        if (c < n1) {
            int j0 = bx*128 + c*32;
            ld_tile_cp(sb,            (const uint16_t*)T1h, i0,  j0, NTOK, tid);
            ld_tile_cp(sb +   BUF128, (const uint16_t*)T1l, i0,  j0, NTOK, tid);
            ld_tile_cp(sb + 2*BUF128, (const uint16_t*)SG,  kx0, j0, NTOK, tid);
        } else {
            int k0 = (c - n1)*32;
            ld_tile_cp(sb,            (const uint16_t*)Qh, i0,  k0, DH, tid);
            ld_tile_cp(sb +   BUF128, (const uint16_t*)Ql, i0,  k0, DH, tid);
            ld_tile_cp(sb + 2*BUF128, (const uint16_t*)Kh, kx0, k0, DH, tid);
            ld_tile_cp(sb + 3*BUF128, (const uint16_t*)Kl, kx0, k0, DH, tid);
        }
    };
    load_stage(0, 0); CP_COMMIT();
    for (int c = 0; c < ntot; c++) {
        CP_WAIT0();
        __syncthreads();
        if (c + 1 < ntot) { load_stage((c+1)&1, c+1); CP_COMMIT(); }
        if (c == n1) {   // acc = -silu(acc) in registers
            #pragma unroll
            for (int mi = 0; mi < 4; mi++)
                #pragma unroll
                for (int ni = 0; ni < 4; ni++)
                    #pragma unroll
                    for (int e = 0; e < 4; e++) {
                        float su = acc[mi][ni][e];
                        acc[mi][ni][e] = -su / (1.f + __expf(-su));
                    }
        }
        uint32_t sb = base + (c&1)*STAGE128;
        if (c < n1)
            mma_chunk_2p<4>(sb, sb+BUF128, sb+2*BUF128, acc, wm, wn, lane);
        else
            mma_chunk_3h<4>(sb, sb+BUF128, sb+2*BUF128, sb+3*BUF128, acc, wm, wn, lane);
    }
    int g = lane >> 2, q = lane & 3;
    #pragma unroll
    for (int mi = 0; mi < 4; mi++) {
        #pragma unroll
        for (int ni = 0; ni < 4; ni++) {
            int k = kx0 + wn*32 + ni*8 + q*2;
            #pragma unroll
            for (int rr = 0; rr < 2; rr++) {
                int i = i0 + wm*64 + mi*16 + g + rr*8;
                float v0 = (k   <= i) ? acc[mi][ni][rr*2+0] : -1e30f;
                float v1 = (k+1 <= i) ? acc[mi][ni][rr*2+1] : -1e30f;
                *(float2*)&S[(size_t)i*NTOK + k] = make_float2(v0, v1);
            }
        }
    }
}

// =====================================================================
// k_softmax: fp32 in, single fp16 probs out
// =====================================================================
__global__ __launch_bounds__(256) void k_softmax()
{
    int i  = blockIdx.x;
    int bh = blockIdx.y;
    size_t roff = (size_t)bh*NTOK*NTOK + (size_t)i*NTOK;
    const float* S = g_su + roff;
    __half* P = g_p + roff;
    int L = i + 1;
    int wlen = ((i >> 7) + 1) << 7;
    int tid = threadIdx.x;
    int k0 = tid*4;
    __shared__ float red[256];
    float4 v = *(const float4*)&S[k0];
    float x[4] = {v.x, v.y, v.z, v.w};
    float mx = -1e30f;
    #pragma unroll
    for (int l = 0; l < 4; l++) {
        if (k0 + l >= L) x[l] = -1e30f;
        mx = fmaxf(mx, x[l]);
    }
    red[tid] = mx; __syncthreads();
    for (int s = 128; s > 0; s >>= 1) {
        if (tid < s) red[tid] = fmaxf(red[tid], red[tid+s]);
        __syncthreads();
    }
    mx = red[0]; __syncthreads();
    float sum = 0.f;
    #pragma unroll
    for (int l = 0; l < 4; l++) {
        x[l] = (k0 + l < L) ? __expf(x[l] - mx) : 0.f;
        sum += x[l];
    }
    red[tid] = sum; __syncthreads();
    for (int s = 128; s > 0; s >>= 1) {
        if (tid < s) red[tid] += red[tid+s];
        __syncthreads();
    }
    float inv = 1.f / red[0];
    if (k0 < wlen) {
        *(uint2*)&P[k0] = make_uint2(pack2h(x[0]*inv, x[1]*inv),
                                     pack2h(x[2]*inv, x[3]*inv));
    }
}

// =====================================================================
// k_av_mma: O = P @ V, fp16 1-product. 128x64, warps 4x2 (MI=2).
// =====================================================================
__global__ __launch_bounds__(256,2) void k_av_mma()
{
    int by = blockIdx.x, bh = blockIdx.y;
    int b = bh >> 3, h = bh & 7;
    const __half* P  = g_p   + (size_t)bh*NTOK*NTOK;
    const __half* Vt = g_vct + (size_t)bh*DH*NTOK;

    extern __shared__ __align__(16) char dynsm[];
    uint32_t base = smem_u32(dynsm);
    int tid = threadIdx.x, lane = tid & 31, wid = tid >> 5;
    int wm = wid >> 1, wn = wid & 1;
    int i0 = by*128;
    float acc[2][4][4] = {};
    int nch = (by + 1) * 4;

    auto load_stage = [&](int s, int c) {
        int k0 = c*32;
        uint32_t sb = base + s*STAGE_AV;
        ld_tile_cp(sb, (const uint16_t*)P, i0, k0, NTOK, tid);
        if (tid < 128)
            ld_tile_cp(sb + BUF128, (const uint16_t*)Vt, 0, k0, NTOK, tid);
    };
    load_stage(0, 0); CP_COMMIT();
    for (int c = 0; c < nch; c++) {
        CP_WAIT0();
        __syncthreads();
        if (c + 1 < nch) { load_stage((c+1)&1, c+1); CP_COMMIT(); }
        uint32_t sb = base + (c&1)*STAGE_AV;
        mma_chunk_1p<2>(sb, sb+BUF128, acc, wm, wn, lane);
    }
    int g = lane >> 2, q = lane & 3;
    #pragma unroll
    for (int mi = 0; mi < 2; mi++) {
        #pragma unroll
        for (int ni = 0; ni < 4; ni++) {
            int d = wn*32 + ni*8 + q*2;
            #pragma unroll
            for (int rr = 0; rr < 2; rr++) {
                int i = i0 + wm*32 + mi*16 + g + rr*8;
                size_t row = (size_t)(b*NTOK + i)*DIMM + h*DH + d;
                uint32_t hp, lp;
                split2(acc[mi][ni][rr*2+0], acc[mi][ni][rr*2+1], hp, lp);
                *(uint32_t*)&g_ohh[row] = hp;
                *(uint32_t*)&g_ohl[row] = lp;
            }
        }
    }
}

// =====================================================================
// k_outproj_mma: bf16 3-product, 16 chunks
// =====================================================================
__global__ __launch_bounds__(256,2) void k_outproj_mma(float* __restrict__ Out)
{
    const __nv_bfloat16* Wth = g_wth + (size_t)6*DIMM*DIMM;
    const __nv_bfloat16* Wtl = g_wtl + (size_t)6*DIMM*DIMM;
    extern __shared__ __align__(16) char dynsm[];
    uint32_t base = smem_u32(dynsm);
    int tid = threadIdx.x, lane = tid & 31, wid = tid >> 5;
    int wm = wid >> 2, wn = wid & 3;
    int m0 = blockIdx.y*128, n0 = blockIdx.x*128;
    float acc[4][4][4] = {};

    auto load_stage = [&](int s, int k0) {
        uint32_t sb = base + s*STAGE128;
        ld_tile_cp(sb,            (const uint16_t*)g_ohh, m0, k0, DIMM, tid);
        ld_tile_cp(sb +   BUF128, (const uint16_t*)g_ohl, m0, k0, DIMM, tid);
        ld_tile_cp(sb + 2*BUF128, (const uint16_t*)Wth,   n0, k0, DIMM, tid);
        ld_tile_cp(sb + 3*BUF128, (const uint16_t*)Wtl,   n0, k0, DIMM, tid);
    };
    load_stage(0, 0); CP_COMMIT();
    for (int c = 0; c < 16; c++) {
        CP_WAIT0();
        __syncthreads();
        if (c + 1 < 16) { load_stage((c+1)&1, (c+1)*32); CP_COMMIT(); }
        uint32_t sb = base + (c&1)*STAGE128;
        mma_chunk_3b<4>(sb, sb+BUF128, sb+2*BUF128, sb+3*BUF128, acc, wm, wn, lane);
    }
    int g = lane >> 2, q = lane & 3;
    #pragma unroll
    for (int mi = 0; mi < 4; mi++) {
        #pragma unroll
        for (int ni = 0; ni < 4; ni++) {
            int nn = n0 + wn*32 + ni*8 + q*2;
            #pragma unroll
            for (int rr = 0; rr < 2; rr++) {
                int m = m0 + wm*64 + mi*16 + g + rr*8;
                *(float2*)&Out[(size_t)m*DIMM + nn] =
                    make_float2(acc[mi][ni][rr*2+0], acc[mi][ni][rr*2+1]);
            }
        }
    }
}

extern "C" void kernel_launch(void* const* d_in, const int* in_sizes, int n_in,
                              void* d_out, int out_size)
{
    const float* x   = (const float*)d_in[0];
    const float* wqu = (const float*)d_in[1];
    const float* wku = (const float*)d_in[2];
    const float* wvu = (const float*)d_in[3];
    const float* wqc = (const float*)d_in[4];
    const float* wkc = (const float*)d_in[5];
    const float* wvc = (const float*)d_in[6];
    const float* wout= (const float*)d_in[7];
    float* out = (float*)d_out;

    static int attr_done = 0;
    if (!attr_done) {
        cudaFuncSetAttribute(k_proj_mma,    cudaFuncAttributeMaxDynamicSharedMemorySize, SMEM128);
        cudaFuncSetAttribute(k_t1sig_mma,   cudaFuncAttributeMaxDynamicSharedMemorySize, SMEM128);
        cudaFuncSetAttribute(k_su_mma,      cudaFuncAttributeMaxDynamicSharedMemorySize, SMEM128);
        cudaFuncSetAttribute(k_av_mma,      cudaFuncAttributeMaxDynamicSharedMemorySize, SMEM_AV);
        cudaFuncSetAttribute(k_outproj_mma, cudaFuncAttributeMaxDynamicSharedMemorySize, SMEM128);
        attr_done = 1;
    }

    k_prep_x    <<<1024, 256>>>(x);
    k_prep_w    <<<dim3(16,16,7), dim3(32,8)>>>(wqu, wku, wvu, wqc, wkc, wvc, wout);
    k_proj_mma  <<<dim3(4, 16, 6), 256, SMEM128>>>();
    k_t1sig_mma <<<dim3(8, 8, 32), 256, SMEM128>>>();
    k_su_mma    <<<dim3(36, 16),   256, SMEM128>>>();
    k_softmax   <<<dim3(1024,16),  256>>>();
    k_av_mma    <<<dim3(8, 16),    256, SMEM_AV>>>();
    k_outproj_mma<<<dim3(4, 16),   256, SMEM128>>>(out);
}

// round 16
// speedup vs baseline: 3.0890x; 1.1155x over previous
#include <cuda_runtime.h>
#include <cuda_bf16.h>
#include <cuda_fp16.h>
#include <math.h>
#include <stdint.h>

#define NTOK 1024
#define BATCH 2
#define HEADS 8
#define DH 64
#define BHN (BATCH*HEADS)   /* 16 */
#define DIMM 512
#define SCALE 0.125f
#define ST 40               /* smem row stride in 16-bit elems (80B, 16B-aligned, conflict-free) */

#define BUF128   (128*ST*2)         /* 10240 B  */
#define STAGE3   (3*BUF128)         /* 30720 B  */
#define SMEM3    (2*STAGE3)         /* 61440 B  */
#define BUF64    (64*ST*2)          /* 5120 B   */
#define STAGE_AV (BUF128 + BUF64)   /* 15360 B  */
#define SMEM_AV  (2*STAGE_AV)       /* 30720 B  */

// ---- scratch ----
__device__ float g_su[(size_t)BHN*NTOK*NTOK];   // pre-softmax scores

// fp16 operands
__device__ __half g_xh[2048*DIMM];               // x fp16 split
__device__ __half g_xl[2048*DIMM];
__device__ __half g_wt[7*DIMM*DIMM];             // transposed weights, single fp16
__device__ __half g_quh[BHN*NTOK*DH];            // SCALE*q_u fp16 split
__device__ __half g_qul[BHN*NTOK*DH];
__device__ __half g_ku [BHN*NTOK*DH];            // k_u single
__device__ __half g_vu [BHN*NTOK*DH];            // v_u single
__device__ __half g_qch[BHN*NTOK*DH];            // SCALE*q_c fp16 split
__device__ __half g_qcl[BHN*NTOK*DH];
__device__ __half g_kc [BHN*NTOK*DH];            // k_c single
__device__ __half g_t1h[(size_t)BHN*NTOK*NTOK];  // term1 fp16 split
__device__ __half g_t1l[(size_t)BHN*NTOK*NTOK];
__device__ __half g_sg [(size_t)BHN*NTOK*NTOK];  // sig single
__device__ __half g_p  [(size_t)BHN*NTOK*NTOK];  // probs single
__device__ __half g_vct[BHN*DH*NTOK];            // v_c transposed [bh][d][tok]
__device__ __half g_ohh[2048*DIMM];              // attn@v_c fp16 split, [m][h*64+d]
__device__ __half g_ohl[2048*DIMM];

// triangular tile map: (a,b) sorted by descending b-a
__device__ __constant__ uint8_t su_map[36][2] = {
    {0,7},
    {0,6},{1,7},
    {0,5},{1,6},{2,7},
    {0,4},{1,5},{2,6},{3,7},
    {0,3},{1,4},{2,5},{3,6},{4,7},
    {0,2},{1,3},{2,4},{3,5},{4,6},{5,7},
    {0,1},{1,2},{2,3},{3,4},{4,5},{5,6},{6,7},
    {0,0},{1,1},{2,2},{3,3},{4,4},{5,5},{6,6},{7,7}
};

// =====================================================================
// helpers
// =====================================================================
#define MMA_F16(c, a0,a1,a2,a3, b0,b1)                                   \
    asm volatile("mma.sync.aligned.m16n8k16.row.col.f32.f16.f16.f32 "    \
        "{%0,%1,%2,%3}, {%4,%5,%6,%7}, {%8,%9}, {%0,%1,%2,%3};"          \
        : "+f"((c)[0]), "+f"((c)[1]), "+f"((c)[2]), "+f"((c)[3])         \
        : "r"(a0), "r"(a1), "r"(a2), "r"(a3), "r"(b0), "r"(b1))

#define LDMX4(r0,r1,r2,r3, addr)                                         \
    asm volatile("ldmatrix.sync.aligned.m8n8.x4.shared.b16 {%0,%1,%2,%3}, [%4];" \
        : "=r"(r0),"=r"(r1),"=r"(r2),"=r"(r3) : "r"(addr))

#define CP_COMMIT() asm volatile("cp.async.commit_group;" ::: "memory")
#define CP_WAIT0()  asm volatile("cp.async.wait_group 0;" ::: "memory")

__device__ __forceinline__ void cp16(uint32_t d, const void* s) {
    asm volatile("cp.async.cg.shared.global [%0], [%1], 16;" :: "r"(d), "l"(s));
}

__device__ __forceinline__ uint32_t smem_u32(const void* p) {
    uint32_t a;
    asm("{ .reg .u64 t; cvta.to.shared.u64 t, %1; cvt.u32.u64 %0, t; }"
        : "=r"(a) : "l"(p));
    return a;
}

// packed fp16 hi/lo split of a pair
__device__ __forceinline__ void split2h(float v0, float v1, uint32_t& hp, uint32_t& lp)
{
    asm("cvt.rn.f16x2.f32 %0, %1, %2;" : "=r"(hp) : "f"(v1), "f"(v0));
    __half2 h2 = *reinterpret_cast<__half2*>(&hp);
    float h0 = __low2float(h2), h1 = __high2float(h2);
    asm("cvt.rn.f16x2.f32 %0, %1, %2;" : "=r"(lp) : "f"(v1 - h1), "f"(v0 - h0));
}

__device__ __forceinline__ uint32_t pack2h(float v0, float v1)
{
    uint32_t r;
    asm("cvt.rn.f16x2.f32 %0, %1, %2;" : "=r"(r) : "f"(v1), "f"(v0));
    return r;
}

// async load 128 rows x 32 col 16-bit tile into smem (row-major, stride ST)
__device__ __forceinline__ void ld_tile_cp(uint32_t dst, const uint16_t* g,
                                           int row0, int k0, int ldg, int tid)
{
    int r = tid >> 1, h = tid & 1;
    const uint16_t* s = g + (size_t)(row0 + r)*ldg + k0 + h*16;
    uint32_t d = dst + (uint32_t)((r*ST + h*16)*2);
    cp16(d, s); cp16(d + 16, s + 8);
}

// =====================================================================
// mma chunk variants (ldmatrix-based, 32-k chunk)
// =====================================================================
// 2-product fp16: A split (hi/lo) x B single
template<int MI>
__device__ __forceinline__ void mma_chunk_2p(
    uint32_t aAh, uint32_t aAl, uint32_t aB,
    float (&acc)[MI][4][4], int wm, int wn, int lane)
{
    int lr = lane & 15;
    int lc = (lane >> 4) << 3;
    int bl_ = lane & 7;
    int bn = ((lane >> 4) & 1) << 3;
    int bk = ((lane >> 3) & 1) << 3;
    uint32_t aoff = (uint32_t)(((wm*(MI*16) + lr)*ST + lc) * 2);
    uint32_t boff = (uint32_t)(((wn*32 + bn + bl_)*ST + bk) * 2);
    #pragma unroll
    for (int ks = 0; ks < 2; ks++) {
        uint32_t kb = (uint32_t)(ks * 32);
        uint32_t bf[4][2];
        LDMX4(bf[0][0], bf[0][1], bf[1][0], bf[1][1], aB + boff + kb);
        LDMX4(bf[2][0], bf[2][1], bf[3][0], bf[3][1], aB + boff + kb + 16*ST*2);
        #pragma unroll
        for (int mi = 0; mi < MI; mi++) {
            uint32_t ao = aoff + kb + (uint32_t)(mi*16*ST*2);
            uint32_t ah0,ah1,ah2,ah3, al0,al1,al2,al3;
            LDMX4(ah0,ah1,ah2,ah3, aAh + ao);
            LDMX4(al0,al1,al2,al3, aAl + ao);
            #pragma unroll
            for (int ni = 0; ni < 4; ni++) {
                MMA_F16(acc[mi][ni], ah0,ah1,ah2,ah3, bf[ni][0], bf[ni][1]);
                MMA_F16(acc[mi][ni], al0,al1,al2,al3, bf[ni][0], bf[ni][1]);
            }
        }
    }
}

// 1-product fp16
template<int MI>
__device__ __forceinline__ void mma_chunk_1p(
    uint32_t aA, uint32_t aB,
    float (&acc)[MI][4][4], int wm, int wn, int lane)
{
    int lr = lane & 15;
    int lc = (lane >> 4) << 3;
    int bl_ = lane & 7;
    int bn = ((lane >> 4) & 1) << 3;
    int bk = ((lane >> 3) & 1) << 3;
    uint32_t aoff = (uint32_t)(((wm*(MI*16) + lr)*ST + lc) * 2);
    uint32_t boff = (uint32_t)(((wn*32 + bn + bl_)*ST + bk) * 2);
    #pragma unroll
    for (int ks = 0; ks < 2; ks++) {
        uint32_t kb = (uint32_t)(ks * 32);
        uint32_t bf[4][2];
        LDMX4(bf[0][0], bf[0][1], bf[1][0], bf[1][1], aB + boff + kb);
        LDMX4(bf[2][0], bf[2][1], bf[3][0], bf[3][1], aB + boff + kb + 16*ST*2);
        #pragma unroll
        for (int mi = 0; mi < MI; mi++) {
            uint32_t ao = aoff + kb + (uint32_t)(mi*16*ST*2);
            uint32_t a0,a1,a2,a3;
            LDMX4(a0,a1,a2,a3, aA + ao);
            #pragma unroll
            for (int ni = 0; ni < 4; ni++)
                MMA_F16(acc[mi][ni], a0,a1,a2,a3, bf[ni][0], bf[ni][1]);
        }
    }
}

// =====================================================================
// prep kernels
// =====================================================================
__global__ __launch_bounds__(256) void k_prep_x(const float* __restrict__ X)
{
    int idx = (blockIdx.x*256 + threadIdx.x)*4;
    float4 v = *(const float4*)&X[idx];
    uint32_t h0, l0, h1, l1;
    split2h(v.x, v.y, h0, l0);
    split2h(v.z, v.w, h1, l1);
    *(uint2*)&g_xh[idx] = make_uint2(h0, h1);
    *(uint2*)&g_xl[idx] = make_uint2(l0, l1);
}

__global__ void k_prep_w(
    const float* __restrict__ w0, const float* __restrict__ w1,
    const float* __restrict__ w2, const float* __restrict__ w3,
    const float* __restrict__ w4, const float* __restrict__ w5,
    const float* __restrict__ w6)
{
    const float* W;
    switch (blockIdx.z) {
        case 0: W = w0; break; case 1: W = w1; break; case 2: W = w2; break;
        case 3: W = w3; break; case 4: W = w4; break; case 5: W = w5; break;
        default: W = w6; break;
    }
    __shared__ float t[32][33];
    int tx = threadIdx.x, ty = threadIdx.y;   // (32, 8)
    int k0 = blockIdx.y*32, n0 = blockIdx.x*32;
    #pragma unroll
    for (int i = 0; i < 4; i++)
        t[ty + i*8][tx] = W[(size_t)(k0 + ty + i*8)*DIMM + n0 + tx];
    __syncthreads();
    size_t zoff = (size_t)blockIdx.z * DIMM * DIMM;
    #pragma unroll
    for (int i = 0; i < 4; i++) {
        float v = t[tx][ty + i*8];
        g_wt[zoff + (size_t)(n0 + ty + i*8)*DIMM + k0 + tx] = __float2half(v);
    }
}

// =====================================================================
// k_proj_mma: 6 projections, fp16 2-product (x split x w single)
// =====================================================================
__global__ __launch_bounds__(256,2) void k_proj_mma()
{
    int z = blockIdx.z;
    __half *Oh = 0, *Ol = 0;
    float sc = 1.f;
    int mode;   // 0=split out, 1=single out, 2=vct
    switch (z) {
        case 0: Oh = g_quh; Ol = g_qul; sc = SCALE; mode = 0; break;
        case 1: Oh = g_ku;  mode = 1; break;
        case 2: Oh = g_vu;  mode = 1; break;
        case 3: Oh = g_qch; Ol = g_qcl; sc = SCALE; mode = 0; break;
        case 4: Oh = g_kc;  mode = 1; break;
        default: mode = 2; break;
    }
    const __half* Wt = g_wt + (size_t)z*DIMM*DIMM;
    extern __shared__ __align__(16) char dynsm[];
    uint32_t base = smem_u32(dynsm);
    int tid = threadIdx.x, lane = tid & 31, wid = tid >> 5;
    int wm = wid >> 2, wn = wid & 3;
    int m0 = blockIdx.y*128, n0 = blockIdx.x*128;
    float acc[4][4][4] = {};

    auto load_stage = [&](int s, int k0) {
        uint32_t sb = base + s*STAGE3;
        ld_tile_cp(sb,            (const uint16_t*)g_xh, m0, k0, DIMM, tid);
        ld_tile_cp(sb +   BUF128, (const uint16_t*)g_xl, m0, k0, DIMM, tid);
        ld_tile_cp(sb + 2*BUF128, (const uint16_t*)Wt,   n0, k0, DIMM, tid);
    };
    load_stage(0, 0); CP_COMMIT();
    for (int c = 0; c < 16; c++) {
        CP_WAIT0();
        __syncthreads();
        if (c + 1 < 16) { load_stage((c+1)&1, (c+1)*32); CP_COMMIT(); }
        uint32_t sb = base + (c&1)*STAGE3;
        mma_chunk_2p<4>(sb, sb+BUF128, sb+2*BUF128, acc, wm, wn, lane);
    }
    int g = lane >> 2, q = lane & 3;
    #pragma unroll
    for (int mi = 0; mi < 4; mi++) {
        #pragma unroll
        for (int ni = 0; ni < 4; ni++) {
            int col = n0 + wn*32 + ni*8 + q*2;
            int h = col >> 6, dd = col & 63;
            #pragma unroll
            for (int rr = 0; rr < 2; rr++) {
                int m = m0 + wm*64 + mi*16 + g + rr*8;
                int b = m >> 10, tok = m & 1023;
                float v0 = acc[mi][ni][rr*2+0], v1 = acc[mi][ni][rr*2+1];
                if (mode == 2) {
                    size_t tb = ((size_t)(b*HEADS + h)*DH + dd)*NTOK + tok;
                    g_vct[tb]        = __float2half(v0);
                    g_vct[tb + NTOK] = __float2half(v1);
                } else {
                    size_t oidx = ((size_t)(b*HEADS + h)*NTOK + tok)*DH + dd;
                    if (mode == 1) {
                        *(uint32_t*)&Oh[oidx] = pack2h(v0, v1);
                    } else {
                        uint32_t hp, lp;
                        split2h(v0*sc, v1*sc, hp, lp);
                        *(uint32_t*)&Oh[oidx] = hp;
                        *(uint32_t*)&Ol[oidx] = lp;
                    }
                }
            }
        }
    }
}

// =====================================================================
// k_t1sig_mma: fp16 2-product, triangular grid.
// y = which*16+bh. which=0: t1 (lower); which=1: sig (upper, mirrored map)
// =====================================================================
__global__ __launch_bounds__(256,2) void k_t1sig_mma()
{
    int which = blockIdx.y >> 4;
    int bh    = blockIdx.y & 15;
    int bx, by;
    if (which == 0) { bx = su_map[blockIdx.x][0]; by = su_map[blockIdx.x][1]; }
    else            { bx = su_map[blockIdx.x][1]; by = su_map[blockIdx.x][0]; }
    size_t voff = (size_t)bh*NTOK*DH;
    const __half* Ah_g = (which == 0 ? g_qch : g_quh) + voff;
    const __half* Al_g = (which == 0 ? g_qcl : g_qul) + voff;
    const __half* B_g  = (which == 0 ? g_vu  : g_ku ) + voff;
    __half* Oh = (which == 0 ? g_t1h : g_sg) + (size_t)bh*NTOK*NTOK;
    __half* Ol = g_t1l + (size_t)bh*NTOK*NTOK;   // only for which==0

    extern __shared__ __align__(16) char dynsm[];
    uint32_t base = smem_u32(dynsm);
    int tid = threadIdx.x, lane = tid & 31, wid = tid >> 5;
    int wm = wid >> 2, wn = wid & 3;
    int i0 = by*128, j0b = bx*128;
    float acc[4][4][4] = {};

    auto load_stage = [&](int s, int k0) {
        uint32_t sb = base + s*STAGE3;
        ld_tile_cp(sb,            (const uint16_t*)Ah_g, i0,  k0, DH, tid);
        ld_tile_cp(sb +   BUF128, (const uint16_t*)Al_g, i0,  k0, DH, tid);
        ld_tile_cp(sb + 2*BUF128, (const uint16_t*)B_g,  j0b, k0, DH, tid);
    };
    load_stage(0, 0); CP_COMMIT();
    for (int c = 0; c < 2; c++) {
        CP_WAIT0();
        __syncthreads();
        if (c + 1 < 2) { load_stage((c+1)&1, 32); CP_COMMIT(); }
        uint32_t sb = base + (c&1)*STAGE3;
        mma_chunk_2p<4>(sb, sb+BUF128, sb+2*BUF128, acc, wm, wn, lane);
    }
    int g = lane >> 2, q = lane & 3;
    #pragma unroll
    for (int mi = 0; mi < 4; mi++) {
        #pragma unroll
        for (int ni = 0; ni < 4; ni++) {
            int j = j0b + wn*32 + ni*8 + q*2;
            #pragma unroll
            for (int rr = 0; rr < 2; rr++) {
                int i = i0 + wm*64 + mi*16 + g + rr*8;
                float s0 = acc[mi][ni][rr*2+0], s1 = acc[mi][ni][rr*2+1];
                size_t idx = (size_t)i*NTOK + j;
                if (which == 0) {
                    float o0 = (j   <= i) ? s0 : 0.f;
                    float o1 = (j+1 <= i) ? s1 : 0.f;
                    uint32_t hp, lp;
                    split2h(o0, o1, hp, lp);
                    *(uint32_t*)&Oh[idx] = hp;
                    *(uint32_t*)&Ol[idx] = lp;
                } else {
                    float o0 = (j   > i) ? 1.f/(1.f + __expf(-s0)) : 0.f;
                    float o1 = (j+1 > i) ? 1.f/(1.f + __expf(-s1)) : 0.f;
                    *(uint32_t*)&Oh[idx] = pack2h(o0, o1);
                }
            }
        }
    }
}

// =====================================================================
// k_su_mma: phase1 (t1 split x sig) + phase2 (q_c split x k_c single),
// both 2-product fp16 with identical 3-tile stage shape. Heavy-first map.
// =====================================================================
__global__ __launch_bounds__(256,2) void k_su_mma()
{
    int bx = su_map[blockIdx.x][0], by = su_map[blockIdx.x][1];
    int bh = blockIdx.y;
    const __half* T1h = g_t1h + (size_t)bh*NTOK*NTOK;
    const __half* T1l = g_t1l + (size_t)bh*NTOK*NTOK;
    const __half* SG  = g_sg  + (size_t)bh*NTOK*NTOK;
    const __half* Qh = g_qch + (size_t)bh*NTOK*DH;
    const __half* Ql = g_qcl + (size_t)bh*NTOK*DH;
    const __half* Kc = g_kc  + (size_t)bh*NTOK*DH;
    float* S = g_su + (size_t)bh*NTOK*NTOK;

    extern __shared__ __align__(16) char dynsm[];
    uint32_t base = smem_u32(dynsm);
    int tid = threadIdx.x, lane = tid & 31, wid = tid >> 5;
    int wm = wid >> 2, wn = wid & 3;
    int i0 = by*128, kx0 = bx*128;
    float acc[4][4][4] = {};

    int n1 = (by - bx + 1) * 4;
    int ntot = n1 + 2;

    auto load_stage = [&](int s, int c) {
        uint32_t sb = base + s*STAGE3;
        if (c < n1) {
            int j0 = bx*128 + c*32;
            ld_tile_cp(sb,            (const uint16_t*)T1h, i0,  j0, NTOK, tid);
            ld_tile_cp(sb +   BUF128, (const uint16_t*)T1l, i0,  j0, NTOK, tid);
            ld_tile_cp(sb + 2*BUF128, (const uint16_t*)SG,  kx0, j0, NTOK, tid);
        } else {
            int k0 = (c - n1)*32;
            ld_tile_cp(sb,            (const uint16_t*)Qh, i0,  k0, DH, tid);
            ld_tile_cp(sb +   BUF128, (const uint16_t*)Ql, i0,  k0, DH, tid);
            ld_tile_cp(sb + 2*BUF128, (const uint16_t*)Kc, kx0, k0, DH, tid);
        }
    };
    load_stage(0, 0); CP_COMMIT();
    for (int c = 0; c < ntot; c++) {
        CP_WAIT0();
        __syncthreads();
        if (c + 1 < ntot) { load_stage((c+1)&1, c+1); CP_COMMIT(); }
        if (c == n1) {   // acc = -silu(acc), registers only
            #pragma unroll
            for (int mi = 0; mi < 4; mi++)
                #pragma unroll
                for (int ni = 0; ni < 4; ni++)
                    #pragma unroll
                    for (int e = 0; e < 4; e++) {
                        float su = acc[mi][ni][e];
                        acc[mi][ni][e] = -su / (1.f + __expf(-su));
                    }
        }
        uint32_t sb = base + (c&1)*STAGE3;
        mma_chunk_2p<4>(sb, sb+BUF128, sb+2*BUF128, acc, wm, wn, lane);
    }
    int g = lane >> 2, q = lane & 3;
    #pragma unroll
    for (int mi = 0; mi < 4; mi++) {
        #pragma unroll
        for (int ni = 0; ni < 4; ni++) {
            int k = kx0 + wn*32 + ni*8 + q*2;
            #pragma unroll
            for (int rr = 0; rr < 2; rr++) {
                int i = i0 + wm*64 + mi*16 + g + rr*8;
                float v0 = (k   <= i) ? acc[mi][ni][rr*2+0] : -1e30f;
                float v1 = (k+1 <= i) ? acc[mi][ni][rr*2+1] : -1e30f;
                *(float2*)&S[(size_t)i*NTOK + k] = make_float2(v0, v1);
            }
        }
    }
}

// =====================================================================
// k_softmax: fp32 in, single fp16 probs out
// =====================================================================
__global__ __launch_bounds__(256) void k_softmax()
{
    int i  = blockIdx.x;
    int bh = blockIdx.y;
    size_t roff = (size_t)bh*NTOK*NTOK + (size_t)i*NTOK;
    const float* S = g_su + roff;
    __half* P = g_p + roff;
    int L = i + 1;
    int wlen = ((i >> 7) + 1) << 7;
    int tid = threadIdx.x;
    int k0 = tid*4;
    __shared__ float red[256];
    float4 v = *(const float4*)&S[k0];
    float x[4] = {v.x, v.y, v.z, v.w};
    float mx = -1e30f;
    #pragma unroll
    for (int l = 0; l < 4; l++) {
        if (k0 + l >= L) x[l] = -1e30f;
        mx = fmaxf(mx, x[l]);
    }
    red[tid] = mx; __syncthreads();
    for (int s = 128; s > 0; s >>= 1) {
        if (tid < s) red[tid] = fmaxf(red[tid], red[tid+s]);
        __syncthreads();
    }
    mx = red[0]; __syncthreads();
    float sum = 0.f;
    #pragma unroll
    for (int l = 0; l < 4; l++) {
        x[l] = (k0 + l < L) ? __expf(x[l] - mx) : 0.f;
        sum += x[l];
    }
    red[tid] = sum; __syncthreads();
    for (int s = 128; s > 0; s >>= 1) {
        if (tid < s) red[tid] += red[tid+s];
        __syncthreads();
    }
    float inv = 1.f / red[0];
    if (k0 < wlen) {
        *(uint2*)&P[k0] = make_uint2(pack2h(x[0]*inv, x[1]*inv),
                                     pack2h(x[2]*inv, x[3]*inv));
    }
}

// =====================================================================
// k_av_mma: O = P @ V, fp16 1-product. Epilogue writes fp16 splits.
// =====================================================================
__global__ __launch_bounds__(256,2) void k_av_mma()
{
    int by = blockIdx.x, bh = blockIdx.y;
    int b = bh >> 3, h = bh & 7;
    const __half* P  = g_p   + (size_t)bh*NTOK*NTOK;
    const __half* Vt = g_vct + (size_t)bh*DH*NTOK;

    extern __shared__ __align__(16) char dynsm[];
    uint32_t base = smem_u32(dynsm);
    int tid = threadIdx.x, lane = tid & 31, wid = tid >> 5;
    int wm = wid >> 1, wn = wid & 1;
    int i0 = by*128;
    float acc[2][4][4] = {};
    int nch = (by + 1) * 4;

    auto load_stage = [&](int s, int c) {
        int k0 = c*32;
        uint32_t sb = base + s*STAGE_AV;
        ld_tile_cp(sb, (const uint16_t*)P, i0, k0, NTOK, tid);
        if (tid < 128)
            ld_tile_cp(sb + BUF128, (const uint16_t*)Vt, 0, k0, NTOK, tid);
    };
    load_stage(0, 0); CP_COMMIT();
    for (int c = 0; c < nch; c++) {
        CP_WAIT0();
        __syncthreads();
        if (c + 1 < nch) { load_stage((c+1)&1, c+1); CP_COMMIT(); }
        uint32_t sb = base + (c&1)*STAGE_AV;
        mma_chunk_1p<2>(sb, sb+BUF128, acc, wm, wn, lane);
    }
    int g = lane >> 2, q = lane & 3;
    #pragma unroll
    for (int mi = 0; mi < 2; mi++) {
        #pragma unroll
        for (int ni = 0; ni < 4; ni++) {
            int d = wn*32 + ni*8 + q*2;
            #pragma unroll
            for (int rr = 0; rr < 2; rr++) {
                int i = i0 + wm*32 + mi*16 + g + rr*8;
                size_t row = (size_t)(b*NTOK + i)*DIMM + h*DH + d;
                uint32_t hp, lp;
                split2h(acc[mi][ni][rr*2+0], acc[mi][ni][rr*2+1], hp, lp);
                *(uint32_t*)&g_ohh[row] = hp;
                *(uint32_t*)&g_ohl[row] = lp;
            }
        }
    }
}

// =====================================================================
// k_outproj_mma: fp16 2-product (oh split x w_out single), 16 chunks
// =====================================================================
__global__ __launch_bounds__(256,2) void k_outproj_mma(float* __restrict__ Out)
{
    const __half* Wt = g_wt + (size_t)6*DIMM*DIMM;
    extern __shared__ __align__(16) char dynsm[];
    uint32_t base = smem_u32(dynsm);
    int tid = threadIdx.x, lane = tid & 31, wid = tid >> 5;
    int wm = wid >> 2, wn = wid & 3;
    int m0 = blockIdx.y*128, n0 = blockIdx.x*128;
    float acc[4][4][4] = {};

    auto load_stage = [&](int s, int k0) {
        uint32_t sb = base + s*STAGE3;
        ld_tile_cp(sb,            (const uint16_t*)g_ohh, m0, k0, DIMM, tid);
        ld_tile_cp(sb +   BUF128, (const uint16_t*)g_ohl, m0, k0, DIMM, tid);
        ld_tile_cp(sb + 2*BUF128, (const uint16_t*)Wt,    n0, k0, DIMM, tid);
    };
    load_stage(0, 0); CP_COMMIT();
    for (int c = 0; c < 16; c++) {
        CP_WAIT0();
        __syncthreads();
        if (c + 1 < 16) { load_stage((c+1)&1, (c+1)*32); CP_COMMIT(); }
        uint32_t sb = base + (c&1)*STAGE3;
        mma_chunk_2p<4>(sb, sb+BUF128, sb+2*BUF128, acc, wm, wn, lane);
    }
    int g = lane >> 2, q = lane & 3;
    #pragma unroll
    for (int mi = 0; mi < 4; mi++) {
        #pragma unroll
        for (int ni = 0; ni < 4; ni++) {
            int nn = n0 + wn*32 + ni*8 + q*2;
            #pragma unroll
            for (int rr = 0; rr < 2; rr++) {
                int m = m0 + wm*64 + mi*16 + g + rr*8;
                *(float2*)&Out[(size_t)m*DIMM + nn] =
                    make_float2(acc[mi][ni][rr*2+0], acc[mi][ni][rr*2+1]);
            }
        }
    }
}

extern "C" void kernel_launch(void* const* d_in, const int* in_sizes, int n_in,
                              void* d_out, int out_size)
{
    const float* x   = (const float*)d_in[0];
    const float* wqu = (const float*)d_in[1];
    const float* wku = (const float*)d_in[2];
    const float* wvu = (const float*)d_in[3];
    const float* wqc = (const float*)d_in[4];
    const float* wkc = (const float*)d_in[5];
    const float* wvc = (const float*)d_in[6];
    const float* wout= (const float*)d_in[7];
    float* out = (float*)d_out;

    static int attr_done = 0;
    if (!attr_done) {
        cudaFuncSetAttribute(k_proj_mma,    cudaFuncAttributeMaxDynamicSharedMemorySize, SMEM3);
        cudaFuncSetAttribute(k_t1sig_mma,   cudaFuncAttributeMaxDynamicSharedMemorySize, SMEM3);
        cudaFuncSetAttribute(k_su_mma,      cudaFuncAttributeMaxDynamicSharedMemorySize, SMEM3);
        cudaFuncSetAttribute(k_av_mma,      cudaFuncAttributeMaxDynamicSharedMemorySize, SMEM_AV);
        cudaFuncSetAttribute(k_outproj_mma, cudaFuncAttributeMaxDynamicSharedMemorySize, SMEM3);
        attr_done = 1;
    }

    k_prep_x    <<<1024, 256>>>(x);
    k_prep_w    <<<dim3(16,16,7), dim3(32,8)>>>(wqu, wku, wvu, wqc, wkc, wvc, wout);
    k_proj_mma  <<<dim3(4, 16, 6), 256, SMEM3>>>();
    k_t1sig_mma <<<dim3(36, 32),   256, SMEM3>>>();
    k_su_mma    <<<dim3(36, 16),   256, SMEM3>>>();
    k_softmax   <<<dim3(1024,16),  256>>>();
    k_av_mma    <<<dim3(8, 16),    256, SMEM_AV>>>();
    k_outproj_mma<<<dim3(4, 16),   256, SMEM3>>>(out);
}

// round 17
// speedup vs baseline: 3.6540x; 1.1829x over previous
#include <cuda_runtime.h>
#include <cuda_bf16.h>
#include <cuda_fp16.h>
#include <math.h>
#include <stdint.h>

#define NTOK 1024
#define BATCH 2
#define HEADS 8
#define DH 64
#define BHN (BATCH*HEADS)   /* 16 */
#define DIMM 512
#define SCALE 0.125f
#define ST 40               /* smem row stride in 16-bit elems (80B, 16B-aligned, conflict-free) */

#define BUF128   (128*ST*2)         /* 10240 B  */
#define STAGE3   (3*BUF128)         /* 30720 B  */
#define SMEM3    (2*STAGE3)         /* 61440 B  */
#define BUF64    (64*ST*2)          /* 5120 B   */
#define STAGE_AV (BUF128 + BUF64)   /* 15360 B  */
#define SMEM_AV  (2*STAGE_AV)       /* 30720 B  */

// ---- scratch ----
__device__ float g_su[(size_t)BHN*NTOK*NTOK];   // pre-softmax scores

// fp16 operands
__device__ __half g_xh[2048*DIMM];               // x fp16 split
__device__ __half g_xl[2048*DIMM];
__device__ __half g_wt[7*DIMM*DIMM];             // transposed weights, single fp16
__device__ __half g_quh[BHN*NTOK*DH];            // SCALE*q_u fp16 split
__device__ __half g_qul[BHN*NTOK*DH];
__device__ __half g_ku [BHN*NTOK*DH];            // k_u single
__device__ __half g_vu [BHN*NTOK*DH];            // v_u single
__device__ __half g_qch[BHN*NTOK*DH];            // SCALE*q_c fp16 split
__device__ __half g_qcl[BHN*NTOK*DH];
__device__ __half g_kc [BHN*NTOK*DH];            // k_c single
__device__ __half g_t1 [(size_t)BHN*NTOK*NTOK];  // term1 single fp16
__device__ __half g_sg [(size_t)BHN*NTOK*NTOK];  // sig single
__device__ __half g_p  [(size_t)BHN*NTOK*NTOK];  // probs single
__device__ __half g_vct[BHN*DH*NTOK];            // v_c transposed [bh][d][tok]
__device__ __half g_ohh[2048*DIMM];              // attn@v_c fp16 split, [m][h*64+d]
__device__ __half g_ohl[2048*DIMM];

// triangular tile map: (a,b) sorted by descending b-a
__device__ __constant__ uint8_t su_map[36][2] = {
    {0,7},
    {0,6},{1,7},
    {0,5},{1,6},{2,7},
    {0,4},{1,5},{2,6},{3,7},
    {0,3},{1,4},{2,5},{3,6},{4,7},
    {0,2},{1,3},{2,4},{3,5},{4,6},{5,7},
    {0,1},{1,2},{2,3},{3,4},{4,5},{5,6},{6,7},
    {0,0},{1,1},{2,2},{3,3},{4,4},{5,5},{6,6},{7,7}
};

// =====================================================================
// helpers
// =====================================================================
#define MMA_F16(c, a0,a1,a2,a3, b0,b1)                                   \
    asm volatile("mma.sync.aligned.m16n8k16.row.col.f32.f16.f16.f32 "    \
        "{%0,%1,%2,%3}, {%4,%5,%6,%7}, {%8,%9}, {%0,%1,%2,%3};"          \
        : "+f"((c)[0]), "+f"((c)[1]), "+f"((c)[2]), "+f"((c)[3])         \
        : "r"(a0), "r"(a1), "r"(a2), "r"(a3), "r"(b0), "r"(b1))

#define LDMX4(r0,r1,r2,r3, addr)                                         \
    asm volatile("ldmatrix.sync.aligned.m8n8.x4.shared.b16 {%0,%1,%2,%3}, [%4];" \
        : "=r"(r0),"=r"(r1),"=r"(r2),"=r"(r3) : "r"(addr))

#define CP_COMMIT() asm volatile("cp.async.commit_group;" ::: "memory")
#define CP_WAIT0()  asm volatile("cp.async.wait_group 0;" ::: "memory")

__device__ __forceinline__ void cp16(uint32_t d, const void* s) {
    asm volatile("cp.async.cg.shared.global [%0], [%1], 16;" :: "r"(d), "l"(s));
}

__device__ __forceinline__ uint32_t smem_u32(const void* p) {
    uint32_t a;
    asm("{ .reg .u64 t; cvta.to.shared.u64 t, %1; cvt.u32.u64 %0, t; }"
        : "=r"(a) : "l"(p));
    return a;
}

// packed fp16 hi/lo split of a pair
__device__ __forceinline__ void split2h(float v0, float v1, uint32_t& hp, uint32_t& lp)
{
    asm("cvt.rn.f16x2.f32 %0, %1, %2;" : "=r"(hp) : "f"(v1), "f"(v0));
    __half2 h2 = *reinterpret_cast<__half2*>(&hp);
    float h0 = __low2float(h2), h1 = __high2float(h2);
    asm("cvt.rn.f16x2.f32 %0, %1, %2;" : "=r"(lp) : "f"(v1 - h1), "f"(v0 - h0));
}

__device__ __forceinline__ uint32_t pack2h(float v0, float v1)
{
    uint32_t r;
    asm("cvt.rn.f16x2.f32 %0, %1, %2;" : "=r"(r) : "f"(v1), "f"(v0));
    return r;
}

// async load 128 rows x 32 col 16-bit tile into smem (row-major, stride ST)
__device__ __forceinline__ void ld_tile_cp(uint32_t dst, const uint16_t* g,
                                           int row0, int k0, int ldg, int tid)
{
    int r = tid >> 1, h = tid & 1;
    const uint16_t* s = g + (size_t)(row0 + r)*ldg + k0 + h*16;
    uint32_t d = dst + (uint32_t)((r*ST + h*16)*2);
    cp16(d, s); cp16(d + 16, s + 8);
}

// =====================================================================
// mma chunk variants (ldmatrix-based, 32-k chunk)
// =====================================================================
// 2-product fp16: A split (hi/lo) x B single
template<int MI>
__device__ __forceinline__ void mma_chunk_2p(
    uint32_t aAh, uint32_t aAl, uint32_t aB,
    float (&acc)[MI][4][4], int wm, int wn, int lane)
{
    int lr = lane & 15;
    int lc = (lane >> 4) << 3;
    int bl_ = lane & 7;
    int bn = ((lane >> 4) & 1) << 3;
    int bk = ((lane >> 3) & 1) << 3;
    uint32_t aoff = (uint32_t)(((wm*(MI*16) + lr)*ST + lc) * 2);
    uint32_t boff = (uint32_t)(((wn*32 + bn + bl_)*ST + bk) * 2);
    #pragma unroll
    for (int ks = 0; ks < 2; ks++) {
        uint32_t kb = (uint32_t)(ks * 32);
        uint32_t bf[4][2];
        LDMX4(bf[0][0], bf[0][1], bf[1][0], bf[1][1], aB + boff + kb);
        LDMX4(bf[2][0], bf[2][1], bf[3][0], bf[3][1], aB + boff + kb + 16*ST*2);
        #pragma unroll
        for (int mi = 0; mi < MI; mi++) {
            uint32_t ao = aoff + kb + (uint32_t)(mi*16*ST*2);
            uint32_t ah0,ah1,ah2,ah3, al0,al1,al2,al3;
            LDMX4(ah0,ah1,ah2,ah3, aAh + ao);
            LDMX4(al0,al1,al2,al3, aAl + ao);
            #pragma unroll
            for (int ni = 0; ni < 4; ni++) {
                MMA_F16(acc[mi][ni], ah0,ah1,ah2,ah3, bf[ni][0], bf[ni][1]);
                MMA_F16(acc[mi][ni], al0,al1,al2,al3, bf[ni][0], bf[ni][1]);
            }
        }
    }
}

// 1-product fp16
template<int MI>
__device__ __forceinline__ void mma_chunk_1p(
    uint32_t aA, uint32_t aB,
    float (&acc)[MI][4][4], int wm, int wn, int lane)
{
    int lr = lane & 15;
    int lc = (lane >> 4) << 3;
    int bl_ = lane & 7;
    int bn = ((lane >> 4) & 1) << 3;
    int bk = ((lane >> 3) & 1) << 3;
    uint32_t aoff = (uint32_t)(((wm*(MI*16) + lr)*ST + lc) * 2);
    uint32_t boff = (uint32_t)(((wn*32 + bn + bl_)*ST + bk) * 2);
    #pragma unroll
    for (int ks = 0; ks < 2; ks++) {
        uint32_t kb = (uint32_t)(ks * 32);
        uint32_t bf[4][2];
        LDMX4(bf[0][0], bf[0][1], bf[1][0], bf[1][1], aB + boff + kb);
        LDMX4(bf[2][0], bf[2][1], bf[3][0], bf[3][1], aB + boff + kb + 16*ST*2);
        #pragma unroll
        for (int mi = 0; mi < MI; mi++) {
            uint32_t ao = aoff + kb + (uint32_t)(mi*16*ST*2);
            uint32_t a0,a1,a2,a3;
            LDMX4(a0,a1,a2,a3, aA + ao);
            #pragma unroll
            for (int ni = 0; ni < 4; ni++)
                MMA_F16(acc[mi][ni], a0,a1,a2,a3, bf[ni][0], bf[ni][1]);
        }
    }
}

// =====================================================================
// prep kernels
// =====================================================================
__global__ __launch_bounds__(256) void k_prep_x(const float* __restrict__ X)
{
    int idx = (blockIdx.x*256 + threadIdx.x)*4;
    float4 v = *(const float4*)&X[idx];
    uint32_t h0, l0, h1, l1;
    split2h(v.x, v.y, h0, l0);
    split2h(v.z, v.w, h1, l1);
    *(uint2*)&g_xh[idx] = make_uint2(h0, h1);
    *(uint2*)&g_xl[idx] = make_uint2(l0, l1);
}

__global__ void k_prep_w(
    const float* __restrict__ w0, const float* __restrict__ w1,
    const float* __restrict__ w2, const float* __restrict__ w3,
    const float* __restrict__ w4, const float* __restrict__ w5,
    const float* __restrict__ w6)
{
    const float* W;
    switch (blockIdx.z) {
        case 0: W = w0; break; case 1: W = w1; break; case 2: W = w2; break;
        case 3: W = w3; break; case 4: W = w4; break; case 5: W = w5; break;
        default: W = w6; break;
    }
    __shared__ float t[32][33];
    int tx = threadIdx.x, ty = threadIdx.y;   // (32, 8)
    int k0 = blockIdx.y*32, n0 = blockIdx.x*32;
    #pragma unroll
    for (int i = 0; i < 4; i++)
        t[ty + i*8][tx] = W[(size_t)(k0 + ty + i*8)*DIMM + n0 + tx];
    __syncthreads();
    size_t zoff = (size_t)blockIdx.z * DIMM * DIMM;
    #pragma unroll
    for (int i = 0; i < 4; i++) {
        float v = t[tx][ty + i*8];
        g_wt[zoff + (size_t)(n0 + ty + i*8)*DIMM + k0 + tx] = __float2half(v);
    }
}

// =====================================================================
// k_proj_mma: 6 projections, fp16 2-product (x split x w single)
// =====================================================================
__global__ __launch_bounds__(256,2) void k_proj_mma()
{
    int z = blockIdx.z;
    __half *Oh = 0, *Ol = 0;
    float sc = 1.f;
    int mode;   // 0=split out, 1=single out, 2=vct
    switch (z) {
        case 0: Oh = g_quh; Ol = g_qul; sc = SCALE; mode = 0; break;
        case 1: Oh = g_ku;  mode = 1; break;
        case 2: Oh = g_vu;  mode = 1; break;
        case 3: Oh = g_qch; Ol = g_qcl; sc = SCALE; mode = 0; break;
        case 4: Oh = g_kc;  mode = 1; break;
        default: mode = 2; break;
    }
    const __half* Wt = g_wt + (size_t)z*DIMM*DIMM;
    extern __shared__ __align__(16) char dynsm[];
    uint32_t base = smem_u32(dynsm);
    int tid = threadIdx.x, lane = tid & 31, wid = tid >> 5;
    int wm = wid >> 2, wn = wid & 3;
    int m0 = blockIdx.y*128, n0 = blockIdx.x*128;
    float acc[4][4][4] = {};

    auto load_stage = [&](int s, int k0) {
        uint32_t sb = base + s*STAGE3;
        ld_tile_cp(sb,            (const uint16_t*)g_xh, m0, k0, DIMM, tid);
        ld_tile_cp(sb +   BUF128, (const uint16_t*)g_xl, m0, k0, DIMM, tid);
        ld_tile_cp(sb + 2*BUF128, (const uint16_t*)Wt,   n0, k0, DIMM, tid);
    };
    load_stage(0, 0); CP_COMMIT();
    for (int c = 0; c < 16; c++) {
        CP_WAIT0();
        __syncthreads();
        if (c + 1 < 16) { load_stage((c+1)&1, (c+1)*32); CP_COMMIT(); }
        uint32_t sb = base + (c&1)*STAGE3;
        mma_chunk_2p<4>(sb, sb+BUF128, sb+2*BUF128, acc, wm, wn, lane);
    }
    int g = lane >> 2, q = lane & 3;
    #pragma unroll
    for (int mi = 0; mi < 4; mi++) {
        #pragma unroll
        for (int ni = 0; ni < 4; ni++) {
            int col = n0 + wn*32 + ni*8 + q*2;
            int h = col >> 6, dd = col & 63;
            #pragma unroll
            for (int rr = 0; rr < 2; rr++) {
                int m = m0 + wm*64 + mi*16 + g + rr*8;
                int b = m >> 10, tok = m & 1023;
                float v0 = acc[mi][ni][rr*2+0], v1 = acc[mi][ni][rr*2+1];
                if (mode == 2) {
                    size_t tb = ((size_t)(b*HEADS + h)*DH + dd)*NTOK + tok;
                    g_vct[tb]        = __float2half(v0);
                    g_vct[tb + NTOK] = __float2half(v1);
                } else {
                    size_t oidx = ((size_t)(b*HEADS + h)*NTOK + tok)*DH + dd;
                    if (mode == 1) {
                        *(uint32_t*)&Oh[oidx] = pack2h(v0, v1);
                    } else {
                        uint32_t hp, lp;
                        split2h(v0*sc, v1*sc, hp, lp);
                        *(uint32_t*)&Oh[oidx] = hp;
                        *(uint32_t*)&Ol[oidx] = lp;
                    }
                }
            }
        }
    }
}

// =====================================================================
// k_t1sig_mma: fp16 2-product, triangular grid.
// which=0: t1 (lower, single fp16 out); which=1: sig (upper, mirrored map)
// =====================================================================
__global__ __launch_bounds__(256,2) void k_t1sig_mma()
{
    int which = blockIdx.y >> 4;
    int bh    = blockIdx.y & 15;
    int bx, by;
    if (which == 0) { bx = su_map[blockIdx.x][0]; by = su_map[blockIdx.x][1]; }
    else            { bx = su_map[blockIdx.x][1]; by = su_map[blockIdx.x][0]; }
    size_t voff = (size_t)bh*NTOK*DH;
    const __half* Ah_g = (which == 0 ? g_qch : g_quh) + voff;
    const __half* Al_g = (which == 0 ? g_qcl : g_qul) + voff;
    const __half* B_g  = (which == 0 ? g_vu  : g_ku ) + voff;
    __half* Oh = (which == 0 ? g_t1 : g_sg) + (size_t)bh*NTOK*NTOK;

    extern __shared__ __align__(16) char dynsm[];
    uint32_t base = smem_u32(dynsm);
    int tid = threadIdx.x, lane = tid & 31, wid = tid >> 5;
    int wm = wid >> 2, wn = wid & 3;
    int i0 = by*128, j0b = bx*128;
    float acc[4][4][4] = {};

    auto load_stage = [&](int s, int k0) {
        uint32_t sb = base + s*STAGE3;
        ld_tile_cp(sb,            (const uint16_t*)Ah_g, i0,  k0, DH, tid);
        ld_tile_cp(sb +   BUF128, (const uint16_t*)Al_g, i0,  k0, DH, tid);
        ld_tile_cp(sb + 2*BUF128, (const uint16_t*)B_g,  j0b, k0, DH, tid);
    };
    load_stage(0, 0); CP_COMMIT();
    for (int c = 0; c < 2; c++) {
        CP_WAIT0();
        __syncthreads();
        if (c + 1 < 2) { load_stage((c+1)&1, 32); CP_COMMIT(); }
        uint32_t sb = base + (c&1)*STAGE3;
        mma_chunk_2p<4>(sb, sb+BUF128, sb+2*BUF128, acc, wm, wn, lane);
    }
    int g = lane >> 2, q = lane & 3;
    #pragma unroll
    for (int mi = 0; mi < 4; mi++) {
        #pragma unroll
        for (int ni = 0; ni < 4; ni++) {
            int j = j0b + wn*32 + ni*8 + q*2;
            #pragma unroll
            for (int rr = 0; rr < 2; rr++) {
                int i = i0 + wm*64 + mi*16 + g + rr*8;
                float s0 = acc[mi][ni][rr*2+0], s1 = acc[mi][ni][rr*2+1];
                size_t idx = (size_t)i*NTOK + j;
                if (which == 0) {
                    float o0 = (j   <= i) ? s0 : 0.f;
                    float o1 = (j+1 <= i) ? s1 : 0.f;
                    *(uint32_t*)&Oh[idx] = pack2h(o0, o1);
                } else {
                    float o0 = (j   > i) ? 1.f/(1.f + __expf(-s0)) : 0.f;
                    float o1 = (j+1 > i) ? 1.f/(1.f + __expf(-s1)) : 0.f;
                    *(uint32_t*)&Oh[idx] = pack2h(o0, o1);
                }
            }
        }
    }
}

// =====================================================================
// k_su_mma: phase1 (t1 single x sig single, 1-product) +
//           phase2 (q_c split x k_c single, 2-product). Heavy-first map.
// =====================================================================
__global__ __launch_bounds__(256,2) void k_su_mma()
{
    int bx = su_map[blockIdx.x][0], by = su_map[blockIdx.x][1];
    int bh = blockIdx.y;
    const __half* T1 = g_t1 + (size_t)bh*NTOK*NTOK;
    const __half* SG = g_sg + (size_t)bh*NTOK*NTOK;
    const __half* Qh = g_qch + (size_t)bh*NTOK*DH;
    const __half* Ql = g_qcl + (size_t)bh*NTOK*DH;
    const __half* Kc = g_kc  + (size_t)bh*NTOK*DH;
    float* S = g_su + (size_t)bh*NTOK*NTOK;

    extern __shared__ __align__(16) char dynsm[];
    uint32_t base = smem_u32(dynsm);
    int tid = threadIdx.x, lane = tid & 31, wid = tid >> 5;
    int wm = wid >> 2, wn = wid & 3;
    int i0 = by*128, kx0 = bx*128;
    float acc[4][4][4] = {};

    int n1 = (by - bx + 1) * 4;
    int ntot = n1 + 2;

    auto load_stage = [&](int s, int c) {
        uint32_t sb = base + s*STAGE3;
        if (c < n1) {
            int j0 = bx*128 + c*32;
            ld_tile_cp(sb,            (const uint16_t*)T1, i0,  j0, NTOK, tid);
            ld_tile_cp(sb +   BUF128, (const uint16_t*)SG, kx0, j0, NTOK, tid);
        } else {
            int k0 = (c - n1)*32;
            ld_tile_cp(sb,            (const uint16_t*)Qh, i0,  k0, DH, tid);
            ld_tile_cp(sb +   BUF128, (const uint16_t*)Ql, i0,  k0, DH, tid);
            ld_tile_cp(sb + 2*BUF128, (const uint16_t*)Kc, kx0, k0, DH, tid);
        }
    };
    load_stage(0, 0); CP_COMMIT();
    for (int c = 0; c < ntot; c++) {
        CP_WAIT0();
        __syncthreads();
        if (c + 1 < ntot) { load_stage((c+1)&1, c+1); CP_COMMIT(); }
        if (c == n1) {   // acc = -silu(acc), registers only
            #pragma unroll
            for (int mi = 0; mi < 4; mi++)
                #pragma unroll
                for (int ni = 0; ni < 4; ni++)
                    #pragma unroll
                    for (int e = 0; e < 4; e++) {
                        float su = acc[mi][ni][e];
                        acc[mi][ni][e] = -su / (1.f + __expf(-su));
                    }
        }
        uint32_t sb = base + (c&1)*STAGE3;
        if (c < n1)
            mma_chunk_1p<4>(sb, sb+BUF128, acc, wm, wn, lane);
        else
            mma_chunk_2p<4>(sb, sb+BUF128, sb+2*BUF128, acc, wm, wn, lane);
    }
    int g = lane >> 2, q = lane & 3;
    #pragma unroll
    for (int mi = 0; mi < 4; mi++) {
        #pragma unroll
        for (int ni = 0; ni < 4; ni++) {
            int k = kx0 + wn*32 + ni*8 + q*2;
            #pragma unroll
            for (int rr = 0; rr < 2; rr++) {
                int i = i0 + wm*64 + mi*16 + g + rr*8;
                float v0 = (k   <= i) ? acc[mi][ni][rr*2+0] : -1e30f;
                float v1 = (k+1 <= i) ? acc[mi][ni][rr*2+1] : -1e30f;
                *(float2*)&S[(size_t)i*NTOK + k] = make_float2(v0, v1);
            }
        }
    }
}

// =====================================================================
// k_softmax: fp32 in, single fp16 probs out
// =====================================================================
__global__ __launch_bounds__(256) void k_softmax()
{
    int i  = blockIdx.x;
    int bh = blockIdx.y;
    size_t roff = (size_t)bh*NTOK*NTOK + (size_t)i*NTOK;
    const float* S = g_su + roff;
    __half* P = g_p + roff;
    int L = i + 1;
    int wlen = ((i >> 7) + 1) << 7;
    int tid = threadIdx.x;
    int k0 = tid*4;
    __shared__ float red[256];
    float4 v = *(const float4*)&S[k0];
    float x[4] = {v.x, v.y, v.z, v.w};
    float mx = -1e30f;
    #pragma unroll
    for (int l = 0; l < 4; l++) {
        if (k0 + l >= L) x[l] = -1e30f;
        mx = fmaxf(mx, x[l]);
    }
    red[tid] = mx; __syncthreads();
    for (int s = 128; s > 0; s >>= 1) {
        if (tid < s) red[tid] = fmaxf(red[tid], red[tid+s]);
        __syncthreads();
    }
    mx = red[0]; __syncthreads();
    float sum = 0.f;
    #pragma unroll
    for (int l = 0; l < 4; l++) {
        x[l] = (k0 + l < L) ? __expf(x[l] - mx) : 0.f;
        sum += x[l];
    }
    red[tid] = sum; __syncthreads();
    for (int s = 128; s > 0; s >>= 1) {
        if (tid < s) red[tid] += red[tid+s];
        __syncthreads();
    }
    float inv = 1.f / red[0];
    if (k0 < wlen) {
        *(uint2*)&P[k0] = make_uint2(pack2h(x[0]*inv, x[1]*inv),
                                     pack2h(x[2]*inv, x[3]*inv));
    }
}

// =====================================================================
// k_av_mma: O = P @ V, fp16 1-product. Epilogue writes fp16 splits.
// =====================================================================
__global__ __launch_bounds__(256,2) void k_av_mma()
{
    int by = blockIdx.x, bh = blockIdx.y;
    int b = bh >> 3, h = bh & 7;
    const __half* P  = g_p   + (size_t)bh*NTOK*NTOK;
    const __half* Vt = g_vct + (size_t)bh*DH*NTOK;

    extern __shared__ __align__(16) char dynsm[];
    uint32_t base = smem_u32(dynsm);
    int tid = threadIdx.x, lane = tid & 31, wid = tid >> 5;
    int wm = wid >> 1, wn = wid & 1;
    int i0 = by*128;
    float acc[2][4][4] = {};
    int nch = (by + 1) * 4;

    auto load_stage = [&](int s, int c) {
        int k0 = c*32;
        uint32_t sb = base + s*STAGE_AV;
        ld_tile_cp(sb, (const uint16_t*)P, i0, k0, NTOK, tid);
        if (tid < 128)
            ld_tile_cp(sb + BUF128, (const uint16_t*)Vt, 0, k0, NTOK, tid);
    };
    load_stage(0, 0); CP_COMMIT();
    for (int c = 0; c < nch; c++) {
        CP_WAIT0();
        __syncthreads();
        if (c + 1 < nch) { load_stage((c+1)&1, c+1); CP_COMMIT(); }
        uint32_t sb = base + (c&1)*STAGE_AV;
        mma_chunk_1p<2>(sb, sb+BUF128, acc, wm, wn, lane);
    }
    int g = lane >> 2, q = lane & 3;
    #pragma unroll
    for (int mi = 0; mi < 2; mi++) {
        #pragma unroll
        for (int ni = 0; ni < 4; ni++) {
            int d = wn*32 + ni*8 + q*2;
            #pragma unroll
            for (int rr = 0; rr < 2; rr++) {
                int i = i0 + wm*32 + mi*16 + g + rr*8;
                size_t row = (size_t)(b*NTOK + i)*DIMM + h*DH + d;
                uint32_t hp, lp;
                split2h(acc[mi][ni][rr*2+0], acc[mi][ni][rr*2+1], hp, lp);
                *(uint32_t*)&g_ohh[row] = hp;
                *(uint32_t*)&g_ohl[row] = lp;
            }
        }
    }
}

// =====================================================================
// k_outproj_mma: fp16 2-product (oh split x w_out single), 16 chunks
// =====================================================================
__global__ __launch_bounds__(256,2) void k_outproj_mma(float* __restrict__ Out)
{
    const __half* Wt = g_wt + (size_t)6*DIMM*DIMM;
    extern __shared__ __align__(16) char dynsm[];
    uint32_t base = smem_u32(dynsm);
    int tid = threadIdx.x, lane = tid & 31, wid = tid >> 5;
    int wm = wid >> 2, wn = wid & 3;
    int m0 = blockIdx.y*128, n0 = blockIdx.x*128;
    float acc[4][4][4] = {};

    auto load_stage = [&](int s, int k0) {
        uint32_t sb = base + s*STAGE3;
        ld_tile_cp(sb,            (const uint16_t*)g_ohh, m0, k0, DIMM, tid);
        ld_tile_cp(sb +   BUF128, (const uint16_t*)g_ohl, m0, k0, DIMM, tid);
        ld_tile_cp(sb + 2*BUF128, (const uint16_t*)Wt,    n0, k0, DIMM, tid);
    };
    load_stage(0, 0); CP_COMMIT();
    for (int c = 0; c < 16; c++) {
        CP_WAIT0();
        __syncthreads();
        if (c + 1 < 16) { load_stage((c+1)&1, (c+1)*32); CP_COMMIT(); }
        uint32_t sb = base + (c&1)*STAGE3;
        mma_chunk_2p<4>(sb, sb+BUF128, sb+2*BUF128, acc, wm, wn, lane);
    }
    int g = lane >> 2, q = lane & 3;
    #pragma unroll
    for (int mi = 0; mi < 4; mi++) {
        #pragma unroll
        for (int ni = 0; ni < 4; ni++) {
            int nn = n0 + wn*32 + ni*8 + q*2;
            #pragma unroll
            for (int rr = 0; rr < 2; rr++) {
                int m = m0 + wm*64 + mi*16 + g + rr*8;
                *(float2*)&Out[(size_t)m*DIMM + nn] =
                    make_float2(acc[mi][ni][rr*2+0], acc[mi][ni][rr*2+1]);
            }
        }
    }
}

extern "C" void kernel_launch(void* const* d_in, const int* in_sizes, int n_in,
                              void* d_out, int out_size)
{
    const float* x   = (const float*)d_in[0];
    const float* wqu = (const float*)d_in[1];
    const float* wku = (const float*)d_in[2];
    const float* wvu = (const float*)d_in[3];
    const float* wqc = (const float*)d_in[4];
    const float* wkc = (const float*)d_in[5];
    const float* wvc = (const float*)d_in[6];
    const float* wout= (const float*)d_in[7];
    float* out = (float*)d_out;

    static int attr_done = 0;
    if (!attr_done) {
        cudaFuncSetAttribute(k_proj_mma,    cudaFuncAttributeMaxDynamicSharedMemorySize, SMEM3);
        cudaFuncSetAttribute(k_t1sig_mma,   cudaFuncAttributeMaxDynamicSharedMemorySize, SMEM3);
        cudaFuncSetAttribute(k_su_mma,      cudaFuncAttributeMaxDynamicSharedMemorySize, SMEM3);
        cudaFuncSetAttribute(k_av_mma,      cudaFuncAttributeMaxDynamicSharedMemorySize, SMEM_AV);
        cudaFuncSetAttribute(k_outproj_mma, cudaFuncAttributeMaxDynamicSharedMemorySize, SMEM3);
        attr_done = 1;
    }

    k_prep_x    <<<1024, 256>>>(x);
    k_prep_w    <<<dim3(16,16,7), dim3(32,8)>>>(wqu, wku, wvu, wqc, wkc, wvc, wout);
    k_proj_mma  <<<dim3(4, 16, 6), 256, SMEM3>>>();
    k_t1sig_mma <<<dim3(36, 32),   256, SMEM3>>>();
    k_su_mma    <<<dim3(36, 16),   256, SMEM3>>>();
    k_softmax   <<<dim3(1024,16),  256>>>();
    k_av_mma    <<<dim3(8, 16),    256, SMEM_AV>>>();
    k_outproj_mma<<<dim3(4, 16),   256, SMEM3>>>(out);
}